// round 1
// baseline (speedup 1.0000x reference)
#include <cuda_runtime.h>

#define Bq 2
#define Sq 2048
#define Rq 128
#define Eq 2048
#define Hq 16
#define Dq 128
#define Lq (Sq + Rq)   // 2176

// ---------------- scratch (device globals, no allocations) ----------------
__device__ float g_wq[3][(size_t)Eq * Eq];        // quantized q/k/v weights (fp32 dequant)
__device__ float g_xq[(size_t)Bq * Sq * Eq];      // quantized activations (fp32 dequant)
__device__ float g_qb[(size_t)Bq * Sq * Eq];      // Q
__device__ float g_kb[(size_t)Bq * Lq * Eq];      // K (self + reasoning concat)
__device__ float g_vb[(size_t)Bq * Lq * Eq];      // V
__device__ float g_ob[(size_t)Bq * Sq * Eq];      // attention output
__device__ float g_part[3 * 1024];                // weight-mean partials
__device__ float g_scale[3];                      // weight scales

// ---------------- weight mean(|w|) : stage 1 (deterministic) ----------------
__global__ void reduce_abs_kernel(const float* __restrict__ w0,
                                  const float* __restrict__ w1,
                                  const float* __restrict__ w2,
                                  float* __restrict__ part) {
    const float* w = (blockIdx.y == 0) ? w0 : ((blockIdx.y == 1) ? w1 : w2);
    int t = threadIdx.x;
    size_t base = (size_t)blockIdx.x * 4096;
    float s = 0.f;
#pragma unroll
    for (int i = 0; i < 16; i++) s += fabsf(w[base + t + i * 256]);
    __shared__ float red[256];
    red[t] = s;
    __syncthreads();
    for (int o = 128; o > 0; o >>= 1) {
        if (t < o) red[t] += red[t + o];
        __syncthreads();
    }
    if (t == 0) part[blockIdx.y * 1024 + blockIdx.x] = red[0];
}

// ---------------- weight mean : stage 2 ----------------
__global__ void finalize_scale_kernel(const float* __restrict__ part,
                                      float* __restrict__ scale) {
    int w = blockIdx.x;
    int t = threadIdx.x;
    float s = part[w * 1024 + t] + part[w * 1024 + t + 256] +
              part[w * 1024 + t + 512] + part[w * 1024 + t + 768];
    __shared__ float red[256];
    red[t] = s;
    __syncthreads();
    for (int o = 128; o > 0; o >>= 1) {
        if (t < o) red[t] += red[t + o];
        __syncthreads();
    }
    if (t == 0) {
        float mean = red[0] * (1.0f / ((float)Eq * (float)Eq));
        scale[w] = fmaxf(mean, 1e-5f);
    }
}

// ---------------- ternary weight quantization ----------------
__global__ void quant_weight_kernel(const float* __restrict__ w0,
                                    const float* __restrict__ w1,
                                    const float* __restrict__ w2,
                                    float* __restrict__ wq,
                                    const float* __restrict__ scale) {
    int wi = blockIdx.y;
    const float* w = (wi == 0) ? w0 : ((wi == 1) ? w1 : w2);
    float s = scale[wi];
    float inv = __frcp_rn(s);  // match fp32 divide closely; rounding boundaries are robust
    size_t i = (size_t)blockIdx.x * 1024 + (size_t)threadIdx.x * 4;
    float4 v = *(const float4*)&w[i];
    float4 o;
    o.x = fminf(fmaxf(rintf(v.x * inv), -1.f), 1.f) * s;
    o.y = fminf(fmaxf(rintf(v.y * inv), -1.f), 1.f) * s;
    o.z = fminf(fmaxf(rintf(v.z * inv), -1.f), 1.f) * s;
    o.w = fminf(fmaxf(rintf(v.w * inv), -1.f), 1.f) * s;
    *(float4*)&wq[(size_t)wi * Eq * Eq + i] = o;
}

// ---------------- per-token int8 absmax activation quantization ----------------
__global__ void quant_act_kernel(const float* __restrict__ x, float* __restrict__ xq) {
    int row = blockIdx.x;
    int t = threadIdx.x;
    const float* xr = x + (size_t)row * Eq;
    float mx = 0.f;
#pragma unroll
    for (int i = 0; i < 8; i++) mx = fmaxf(mx, fabsf(xr[t + i * 256]));
    __shared__ float red[256];
    red[t] = mx;
    __syncthreads();
    for (int o = 128; o > 0; o >>= 1) {
        if (t < o) red[t] = fmaxf(red[t], red[t + o]);
        __syncthreads();
    }
    float s = __fdiv_rn(127.0f, fmaxf(red[0], 1e-5f));
    float* xo = xq + (size_t)row * Eq;
#pragma unroll
    for (int i = 0; i < 8; i++) {
        int d = t + i * 256;
        float q = fminf(fmaxf(rintf(xr[d] * s), -128.f), 127.f);
        xo[d] = __fdiv_rn(q, s);
    }
}

// ---------------- SGEMM: C[m,n] = A[m,:] . B[n,:] (+bias), with batched row remap ----------------
// out row = (m / rbi) * rbo + roff + (m % rbi)
__global__ __launch_bounds__(256, 2) void sgemm128(
    const float* __restrict__ A, const float* __restrict__ B,
    float* __restrict__ C, const float* __restrict__ bias,
    int M, int N, int K, int rbi, int rbo, int roff) {
    __shared__ float As[2][8][128];
    __shared__ float Bs[2][8][128];
    int t = threadIdx.x;
    int bx = blockIdx.x, by = blockIdx.y;
    const float* Ab = A + (size_t)by * 128 * K;
    const float* Bb = B + (size_t)bx * 128 * K;
    int lr = t >> 1;
    int lk = (t & 1) * 4;

    // preload tile 0
    float4 av = *(const float4*)&Ab[(size_t)lr * K + lk];
    float4 bv = *(const float4*)&Bb[(size_t)lr * K + lk];
    As[0][lk + 0][lr] = av.x; As[0][lk + 1][lr] = av.y;
    As[0][lk + 2][lr] = av.z; As[0][lk + 3][lr] = av.w;
    Bs[0][lk + 0][lr] = bv.x; Bs[0][lk + 1][lr] = bv.y;
    Bs[0][lk + 2][lr] = bv.z; Bs[0][lk + 3][lr] = bv.w;
    __syncthreads();

    float acc[8][8];
#pragma unroll
    for (int i = 0; i < 8; i++)
#pragma unroll
        for (int j = 0; j < 8; j++) acc[i][j] = 0.f;

    int tr = (t >> 4) * 8;
    int tc = (t & 15) * 8;
    int nk = K / 8;

    for (int kt = 0; kt < nk; ++kt) {
        int buf = kt & 1;
        int nbuf = buf ^ 1;
        if (kt + 1 < nk) {
            int k0 = (kt + 1) * 8;
            av = *(const float4*)&Ab[(size_t)lr * K + k0 + lk];
            bv = *(const float4*)&Bb[(size_t)lr * K + k0 + lk];
        }
#pragma unroll
        for (int k = 0; k < 8; k++) {
            float a[8], b[8];
            *(float4*)&a[0] = *(const float4*)&As[buf][k][tr];
            *(float4*)&a[4] = *(const float4*)&As[buf][k][tr + 4];
            *(float4*)&b[0] = *(const float4*)&Bs[buf][k][tc];
            *(float4*)&b[4] = *(const float4*)&Bs[buf][k][tc + 4];
#pragma unroll
            for (int i = 0; i < 8; i++)
#pragma unroll
                for (int j = 0; j < 8; j++) acc[i][j] += a[i] * b[j];
        }
        if (kt + 1 < nk) {
            As[nbuf][lk + 0][lr] = av.x; As[nbuf][lk + 1][lr] = av.y;
            As[nbuf][lk + 2][lr] = av.z; As[nbuf][lk + 3][lr] = av.w;
            Bs[nbuf][lk + 0][lr] = bv.x; Bs[nbuf][lk + 1][lr] = bv.y;
            Bs[nbuf][lk + 2][lr] = bv.z; Bs[nbuf][lk + 3][lr] = bv.w;
        }
        __syncthreads();
    }

    float bvals[8];
#pragma unroll
    for (int j = 0; j < 8; j++) bvals[j] = bias ? bias[bx * 128 + tc + j] : 0.f;

#pragma unroll
    for (int i = 0; i < 8; i++) {
        int m = by * 128 + tr + i;
        int orow = (m / rbi) * rbo + roff + (m % rbi);
        float* cr = C + (size_t)orow * N + bx * 128 + tc;
        float4 v0, v1;
        v0.x = acc[i][0] + bvals[0]; v0.y = acc[i][1] + bvals[1];
        v0.z = acc[i][2] + bvals[2]; v0.w = acc[i][3] + bvals[3];
        v1.x = acc[i][4] + bvals[4]; v1.y = acc[i][5] + bvals[5];
        v1.z = acc[i][6] + bvals[6]; v1.w = acc[i][7] + bvals[7];
        *(float4*)&cr[0] = v0;
        *(float4*)&cr[4] = v1;
    }
}

// ---------------- flash attention (fp32, online softmax) ----------------
#define DST 132
#define SST 65
#define SMEM_ATTN (119808)

__global__ __launch_bounds__(256, 1) void attn_kernel(
    const float* __restrict__ Qp, const float* __restrict__ Kp,
    const float* __restrict__ Vp, float* __restrict__ Op) {
    extern __shared__ float sm[];
    float* Qs = sm;                   // 64*132
    float* Ks = Qs + 64 * DST;        // 64*132
    float* Vs = Ks + 64 * DST;        // 64*132
    float* Ss = Vs + 64 * DST;        // 64*65
    float* Sp = Ss + 64 * SST;        // 64*4 partial sums
    float* rm = Sp + 256;             // 64 row max
    float* ra = rm + 64;              // 64 row alpha
    float* rl = ra + 64;              // 64 row l

    int t = threadIdx.x;
    int qb = blockIdx.x * 64;
    int h = blockIdx.y;
    int b = blockIdx.z;

    const float* Qbase = Qp + ((size_t)(b * Sq + qb)) * Eq + h * Dq;
    for (int i = t; i < 64 * 32; i += 256) {
        int r = i >> 5, d4 = (i & 31) << 2;
        *(float4*)&Qs[r * DST + d4] = *(const float4*)&Qbase[(size_t)r * Eq + d4];
    }
    if (t < 64) { rm[t] = -1e30f; rl[t] = 0.f; }

    float acc[32];
#pragma unroll
    for (int i = 0; i < 32; i++) acc[i] = 0.f;

    const int orow = (t >> 5) * 8 + ((t & 31) >> 2);
    const int oc0 = (t & 3) * 32;
    const int str = t >> 4, stc = t & 15;
    const int er = t >> 2, ec0 = (t & 3) * 16;
    const float SCALE = 0.08838834764831845f;  // 1/sqrt(128)

    __syncthreads();

    for (int kt = 0; kt < Lq / 64; ++kt) {
        const float* Kbase = Kp + ((size_t)(b * Lq + kt * 64)) * Eq + h * Dq;
        const float* Vbase = Vp + ((size_t)(b * Lq + kt * 64)) * Eq + h * Dq;
        for (int i = t; i < 64 * 32; i += 256) {
            int r = i >> 5, d4 = (i & 31) << 2;
            *(float4*)&Ks[r * DST + d4] = *(const float4*)&Kbase[(size_t)r * Eq + d4];
            *(float4*)&Vs[r * DST + d4] = *(const float4*)&Vbase[(size_t)r * Eq + d4];
        }
        __syncthreads();

        // scores: 4x4 micro-tile per thread
        float sacc[4][4];
#pragma unroll
        for (int i = 0; i < 4; i++)
#pragma unroll
            for (int j = 0; j < 4; j++) sacc[i][j] = 0.f;

#pragma unroll 4
        for (int k4 = 0; k4 < Dq; k4 += 4) {
            float4 qv[4], kv[4];
#pragma unroll
            for (int i = 0; i < 4; i++)
                qv[i] = *(const float4*)&Qs[(str * 4 + i) * DST + k4];
#pragma unroll
            for (int j = 0; j < 4; j++)
                kv[j] = *(const float4*)&Ks[(stc * 4 + j) * DST + k4];
#pragma unroll
            for (int i = 0; i < 4; i++)
#pragma unroll
                for (int j = 0; j < 4; j++)
                    sacc[i][j] += qv[i].x * kv[j].x + qv[i].y * kv[j].y +
                                  qv[i].z * kv[j].z + qv[i].w * kv[j].w;
        }
#pragma unroll
        for (int i = 0; i < 4; i++)
#pragma unroll
            for (int j = 0; j < 4; j++)
                Ss[(str * 4 + i) * SST + stc * 4 + j] = sacc[i][j] * SCALE;
        __syncthreads();

        // row max + alpha
        if (t < 64) {
            float mo = rm[t], mn = mo;
#pragma unroll 8
            for (int j = 0; j < 64; j++) mn = fmaxf(mn, Ss[t * SST + j]);
            rm[t] = mn;
            ra[t] = __expf(mo - mn);
        }
        __syncthreads();

        // exponentiate + partial row sums
        {
            float m = rm[er];
            float ps = 0.f;
#pragma unroll
            for (int j = 0; j < 16; j++) {
                float e = __expf(Ss[er * SST + ec0 + j] - m);
                Ss[er * SST + ec0 + j] = e;
                ps += e;
            }
            Sp[er * 4 + (t & 3)] = ps;
        }
        __syncthreads();

        if (t < 64) {
            float s = Sp[t * 4] + Sp[t * 4 + 1] + Sp[t * 4 + 2] + Sp[t * 4 + 3];
            rl[t] = rl[t] * ra[t] + s;
        }

        // O = O*alpha + P @ V
        {
            float al = ra[orow];
#pragma unroll
            for (int i = 0; i < 32; i++) acc[i] *= al;
#pragma unroll 4
            for (int j = 0; j < 64; j++) {
                float p = Ss[orow * SST + j];
                const float* vr = &Vs[j * DST + oc0];
#pragma unroll
                for (int c4 = 0; c4 < 8; c4++) {
                    float4 v = *(const float4*)&vr[c4 * 4];
                    acc[c4 * 4 + 0] += p * v.x;
                    acc[c4 * 4 + 1] += p * v.y;
                    acc[c4 * 4 + 2] += p * v.z;
                    acc[c4 * 4 + 3] += p * v.w;
                }
            }
        }
        __syncthreads();
    }

    float invl = 1.0f / rl[orow];
    float* Ob = Op + ((size_t)(b * Sq + qb + orow)) * Eq + h * Dq + oc0;
#pragma unroll
    for (int c4 = 0; c4 < 8; c4++) {
        float4 v;
        v.x = acc[c4 * 4 + 0] * invl;
        v.y = acc[c4 * 4 + 1] * invl;
        v.z = acc[c4 * 4 + 2] * invl;
        v.w = acc[c4 * 4 + 3] * invl;
        *(float4*)&Ob[c4 * 4] = v;
    }
}

// ---------------- host launcher ----------------
extern "C" void kernel_launch(void* const* d_in, const int* in_sizes, int n_in,
                              void* d_out, int out_size) {
    const float* x  = (const float*)d_in[0];
    const float* rt = (const float*)d_in[1];
    const float* qw = (const float*)d_in[2];
    const float* kw = (const float*)d_in[3];
    const float* vw = (const float*)d_in[4];
    const float* ow = (const float*)d_in[5];
    const float* ob = (const float*)d_in[6];
    float* out = (float*)d_out;

    float *wq, *xq, *qb, *kb, *vb, *obuf, *part, *scale;
    cudaGetSymbolAddress((void**)&wq, g_wq);
    cudaGetSymbolAddress((void**)&xq, g_xq);
    cudaGetSymbolAddress((void**)&qb, g_qb);
    cudaGetSymbolAddress((void**)&kb, g_kb);
    cudaGetSymbolAddress((void**)&vb, g_vb);
    cudaGetSymbolAddress((void**)&obuf, g_ob);
    cudaGetSymbolAddress((void**)&part, g_part);
    cudaGetSymbolAddress((void**)&scale, g_scale);

    cudaFuncSetAttribute(attn_kernel, cudaFuncAttributeMaxDynamicSharedMemorySize,
                         SMEM_ATTN);

    // 1) weight scales (mean |w|), deterministic two-stage
    reduce_abs_kernel<<<dim3(1024, 3), 256>>>(qw, kw, vw, part);
    finalize_scale_kernel<<<3, 256>>>(part, scale);
    // 2) quantize weights + activations
    quant_weight_kernel<<<dim3(Eq * Eq / 1024, 3), 256>>>(qw, kw, vw, wq, scale);
    quant_act_kernel<<<Bq * Sq, 256>>>(x, xq);
    // 3) projections
    size_t EE = (size_t)Eq * Eq;
    sgemm128<<<dim3(Eq / 128, (Bq * Sq) / 128), 256>>>(xq, wq + 0 * EE, qb, nullptr,
                                                       Bq * Sq, Eq, Eq, Sq, Sq, 0);
    sgemm128<<<dim3(Eq / 128, (Bq * Sq) / 128), 256>>>(xq, wq + 1 * EE, kb, nullptr,
                                                       Bq * Sq, Eq, Eq, Sq, Lq, 0);
    sgemm128<<<dim3(Eq / 128, (Bq * Sq) / 128), 256>>>(xq, wq + 2 * EE, vb, nullptr,
                                                       Bq * Sq, Eq, Eq, Sq, Lq, 0);
    // reasoning tokens: unquantized projections, appended after the S self rows
    sgemm128<<<dim3(Eq / 128, (Bq * Rq) / 128), 256>>>(rt, kw, kb, nullptr,
                                                       Bq * Rq, Eq, Eq, Rq, Lq, Sq);
    sgemm128<<<dim3(Eq / 128, (Bq * Rq) / 128), 256>>>(rt, vw, vb, nullptr,
                                                       Bq * Rq, Eq, Eq, Rq, Lq, Sq);
    // 4) attention
    attn_kernel<<<dim3(Sq / 64, Hq, Bq), 256, SMEM_ATTN>>>(qb, kb, vb, obuf);
    // 5) output projection + bias
    sgemm128<<<dim3(Eq / 128, (Bq * Sq) / 128), 256>>>(obuf, ow, out, ob,
                                                       Bq * Sq, Eq, Eq, Bq * Sq,
                                                       Bq * Sq, 0);
}

// round 2
// speedup vs baseline: 1.1385x; 1.1385x over previous
#include <cuda_runtime.h>

#define Bq 2
#define Sq 2048
#define Rq 128
#define Eq 2048
#define Hq 16
#define Dq 128
#define Lq (Sq + Rq)   // 2176
#define Kp (Eq / 4)    // 512 packed int8 words per row

// ---------------- scratch (device globals, no allocations) ----------------
__device__ int   g_w8[3][(size_t)Eq * Kp];        // ternary weights, packed int8
__device__ int   g_x8[(size_t)Bq * Sq * Kp];      // quantized activations, packed int8
__device__ float g_rows[(size_t)Bq * Sq];         // per-row act scale s (=127/max)
__device__ float g_qb[(size_t)Bq * Sq * Eq];      // Q
__device__ float g_kb[(size_t)Bq * Lq * Eq];      // K (self + reasoning concat)
__device__ float g_vb[(size_t)Bq * Lq * Eq];      // V
__device__ float g_ob[(size_t)Bq * Sq * Eq];      // attention output
__device__ float g_part[3 * 1024];                // weight-mean partials
__device__ float g_scale[3];                      // weight scales

// ---------------- f32x2 packed-FMA helpers ----------------
typedef unsigned long long ull;
__device__ __forceinline__ ull pack2(float x, float y) {
    ull r; asm("mov.b64 %0, {%1, %2};" : "=l"(r) : "f"(x), "f"(y)); return r;
}
__device__ __forceinline__ float2 unpack2(ull v) {
    float2 f; asm("mov.b64 {%0, %1}, %2;" : "=f"(f.x), "=f"(f.y) : "l"(v)); return f;
}
__device__ __forceinline__ void ffma2(ull& d, ull a, ull b) {
    asm("fma.rn.f32x2 %0, %1, %2, %0;" : "+l"(d) : "l"(a), "l"(b));
}
__device__ __forceinline__ ull fmul2(ull a, ull b) {
    ull d; asm("mul.rn.f32x2 %0, %1, %2;" : "=l"(d) : "l"(a), "l"(b)); return d;
}

// ---------------- weight mean(|w|) : stage 1 (deterministic) ----------------
__global__ void reduce_abs_kernel(const float* __restrict__ w0,
                                  const float* __restrict__ w1,
                                  const float* __restrict__ w2,
                                  float* __restrict__ part) {
    const float* w = (blockIdx.y == 0) ? w0 : ((blockIdx.y == 1) ? w1 : w2);
    int t = threadIdx.x;
    size_t base = (size_t)blockIdx.x * 4096;
    float s = 0.f;
#pragma unroll
    for (int i = 0; i < 16; i++) s += fabsf(w[base + t + i * 256]);
    __shared__ float red[256];
    red[t] = s;
    __syncthreads();
    for (int o = 128; o > 0; o >>= 1) {
        if (t < o) red[t] += red[t + o];
        __syncthreads();
    }
    if (t == 0) part[blockIdx.y * 1024 + blockIdx.x] = red[0];
}

// ---------------- weight mean : stage 2 ----------------
__global__ void finalize_scale_kernel(const float* __restrict__ part,
                                      float* __restrict__ scale) {
    int w = blockIdx.x;
    int t = threadIdx.x;
    float s = part[w * 1024 + t] + part[w * 1024 + t + 256] +
              part[w * 1024 + t + 512] + part[w * 1024 + t + 768];
    __shared__ float red[256];
    red[t] = s;
    __syncthreads();
    for (int o = 128; o > 0; o >>= 1) {
        if (t < o) red[t] += red[t + o];
        __syncthreads();
    }
    if (t == 0) {
        float mean = red[0] * (1.0f / ((float)Eq * (float)Eq));
        scale[w] = fmaxf(mean, 1e-5f);
    }
}

// ---------------- ternary weight quantization -> packed int8 ----------------
__global__ void quant_weight_i8(const float* __restrict__ w0,
                                const float* __restrict__ w1,
                                const float* __restrict__ w2,
                                int* __restrict__ wq,
                                const float* __restrict__ scale) {
    int wi = blockIdx.y;
    const float* w = (wi == 0) ? w0 : ((wi == 1) ? w1 : w2);
    float inv = __frcp_rn(scale[wi]);
    // each thread: 4 words = 16 elems
    size_t e0 = ((size_t)blockIdx.x * 256 + threadIdx.x) * 16;
    int* wout = wq + (size_t)wi * Eq * Kp + e0 / 4;
#pragma unroll
    for (int wd = 0; wd < 4; wd++) {
        float4 v = *(const float4*)&w[e0 + wd * 4];
        int b0 = (int)(fminf(fmaxf(rintf(v.x * inv), -1.f), 1.f));
        int b1 = (int)(fminf(fmaxf(rintf(v.y * inv), -1.f), 1.f));
        int b2 = (int)(fminf(fmaxf(rintf(v.z * inv), -1.f), 1.f));
        int b3 = (int)(fminf(fmaxf(rintf(v.w * inv), -1.f), 1.f));
        wout[wd] = (b0 & 255) | ((b1 & 255) << 8) | ((b2 & 255) << 16) | ((b3 & 255) << 24);
    }
}

// ---------------- per-token int8 absmax quantization -> packed int8 ----------------
__global__ void quant_act_i8(const float* __restrict__ x, int* __restrict__ xq,
                             float* __restrict__ rows) {
    int row = blockIdx.x;
    int t = threadIdx.x;
    const float* xr = x + (size_t)row * Eq;
    float4 v0 = *(const float4*)&xr[t * 8];
    float4 v1 = *(const float4*)&xr[t * 8 + 4];
    float mx = fmaxf(fmaxf(fmaxf(fabsf(v0.x), fabsf(v0.y)), fmaxf(fabsf(v0.z), fabsf(v0.w))),
                     fmaxf(fmaxf(fabsf(v1.x), fabsf(v1.y)), fmaxf(fabsf(v1.z), fabsf(v1.w))));
    __shared__ float red[256];
    red[t] = mx;
    __syncthreads();
    for (int o = 128; o > 0; o >>= 1) {
        if (t < o) red[t] = fmaxf(red[t], red[t + o]);
        __syncthreads();
    }
    float s = __fdiv_rn(127.0f, fmaxf(red[0], 1e-5f));
    if (t == 0) rows[row] = s;
    int* xo = xq + (size_t)row * Kp + t * 2;
    {
        int b0 = (int)fminf(fmaxf(rintf(v0.x * s), -128.f), 127.f);
        int b1 = (int)fminf(fmaxf(rintf(v0.y * s), -128.f), 127.f);
        int b2 = (int)fminf(fmaxf(rintf(v0.z * s), -128.f), 127.f);
        int b3 = (int)fminf(fmaxf(rintf(v0.w * s), -128.f), 127.f);
        xo[0] = (b0 & 255) | ((b1 & 255) << 8) | ((b2 & 255) << 16) | ((b3 & 255) << 24);
        b0 = (int)fminf(fmaxf(rintf(v1.x * s), -128.f), 127.f);
        b1 = (int)fminf(fmaxf(rintf(v1.y * s), -128.f), 127.f);
        b2 = (int)fminf(fmaxf(rintf(v1.z * s), -128.f), 127.f);
        b3 = (int)fminf(fmaxf(rintf(v1.w * s), -128.f), 127.f);
        xo[1] = (b0 & 255) | ((b1 & 255) << 8) | ((b2 & 255) << 16) | ((b3 & 255) << 24);
    }
}

// ---------------- int8 dp4a GEMM (exact): C = (A8 . B8^T) * ws / s_row ----------------
__global__ __launch_bounds__(256, 2) void sgemm_i8(
    const int* __restrict__ A, const int* __restrict__ B,
    float* __restrict__ C, const float* __restrict__ rowscale,
    const float* __restrict__ wsp,
    int N, int rbi, int rbo, int roff) {
    __shared__ int As[2][8][128];
    __shared__ int Bs[2][8][128];
    int t = threadIdx.x;
    int bx = blockIdx.x, by = blockIdx.y;
    const int* Ab = A + (size_t)by * 128 * Kp;
    const int* Bb = B + (size_t)bx * 128 * Kp;
    int lr = t >> 1;
    int lk = (t & 1) * 4;

    int4 av = *(const int4*)&Ab[(size_t)lr * Kp + lk];
    int4 bv = *(const int4*)&Bb[(size_t)lr * Kp + lk];
    As[0][lk + 0][lr] = av.x; As[0][lk + 1][lr] = av.y;
    As[0][lk + 2][lr] = av.z; As[0][lk + 3][lr] = av.w;
    Bs[0][lk + 0][lr] = bv.x; Bs[0][lk + 1][lr] = bv.y;
    Bs[0][lk + 2][lr] = bv.z; Bs[0][lk + 3][lr] = bv.w;
    __syncthreads();

    int acc[8][8];
#pragma unroll
    for (int i = 0; i < 8; i++)
#pragma unroll
        for (int j = 0; j < 8; j++) acc[i][j] = 0;

    int tr = (t >> 4) * 8;
    int tc = (t & 15) * 8;
    const int nk = Kp / 8;  // 64

    for (int kt = 0; kt < nk; ++kt) {
        int buf = kt & 1;
        int nbuf = buf ^ 1;
        if (kt + 1 < nk) {
            int k0 = (kt + 1) * 8;
            av = *(const int4*)&Ab[(size_t)lr * Kp + k0 + lk];
            bv = *(const int4*)&Bb[(size_t)lr * Kp + k0 + lk];
        }
#pragma unroll
        for (int k = 0; k < 8; k++) {
            int a[8], b[8];
            *(int4*)&a[0] = *(const int4*)&As[buf][k][tr];
            *(int4*)&a[4] = *(const int4*)&As[buf][k][tr + 4];
            *(int4*)&b[0] = *(const int4*)&Bs[buf][k][tc];
            *(int4*)&b[4] = *(const int4*)&Bs[buf][k][tc + 4];
#pragma unroll
            for (int i = 0; i < 8; i++)
#pragma unroll
                for (int j = 0; j < 8; j++) acc[i][j] = __dp4a(a[i], b[j], acc[i][j]);
        }
        if (kt + 1 < nk) {
            As[nbuf][lk + 0][lr] = av.x; As[nbuf][lk + 1][lr] = av.y;
            As[nbuf][lk + 2][lr] = av.z; As[nbuf][lk + 3][lr] = av.w;
            Bs[nbuf][lk + 0][lr] = bv.x; Bs[nbuf][lk + 1][lr] = bv.y;
            Bs[nbuf][lk + 2][lr] = bv.z; Bs[nbuf][lk + 3][lr] = bv.w;
        }
        __syncthreads();
    }

    float ws = *wsp;
#pragma unroll
    for (int i = 0; i < 8; i++) {
        int m = by * 128 + tr + i;
        float f = ws / rowscale[m];
        int orow = (m / rbi) * rbo + roff + (m % rbi);
        float* cr = C + (size_t)orow * N + bx * 128 + tc;
        float4 v0, v1;
        v0.x = (float)acc[i][0] * f; v0.y = (float)acc[i][1] * f;
        v0.z = (float)acc[i][2] * f; v0.w = (float)acc[i][3] * f;
        v1.x = (float)acc[i][4] * f; v1.y = (float)acc[i][5] * f;
        v1.z = (float)acc[i][6] * f; v1.w = (float)acc[i][7] * f;
        *(float4*)&cr[0] = v0;
        *(float4*)&cr[4] = v1;
    }
}

// ---------------- fp32 SGEMM with packed f32x2 FMA ----------------
// C[m,n] = A[m,:] . B[n,:] (+bias), out row = (m/rbi)*rbo + roff + (m%rbi)
__global__ __launch_bounds__(256, 2) void sgemm128(
    const float* __restrict__ A, const float* __restrict__ B,
    float* __restrict__ C, const float* __restrict__ bias,
    int N, int K, int rbi, int rbo, int roff) {
    __shared__ float As[2][8][128];
    __shared__ float Bs[2][8][128];
    int t = threadIdx.x;
    int bx = blockIdx.x, by = blockIdx.y;
    const float* Ab = A + (size_t)by * 128 * K;
    const float* Bb = B + (size_t)bx * 128 * K;
    int lr = t >> 1;
    int lk = (t & 1) * 4;

    float4 av = *(const float4*)&Ab[(size_t)lr * K + lk];
    float4 bv = *(const float4*)&Bb[(size_t)lr * K + lk];
    As[0][lk + 0][lr] = av.x; As[0][lk + 1][lr] = av.y;
    As[0][lk + 2][lr] = av.z; As[0][lk + 3][lr] = av.w;
    Bs[0][lk + 0][lr] = bv.x; Bs[0][lk + 1][lr] = bv.y;
    Bs[0][lk + 2][lr] = bv.z; Bs[0][lk + 3][lr] = bv.w;
    __syncthreads();

    ull acc2[8][4];  // pairs over output columns
#pragma unroll
    for (int i = 0; i < 8; i++)
#pragma unroll
        for (int j = 0; j < 4; j++) acc2[i][j] = 0ULL;

    int tr = (t >> 4) * 8;
    int tc = (t & 15) * 8;
    int nk = K / 8;

    for (int kt = 0; kt < nk; ++kt) {
        int buf = kt & 1;
        int nbuf = buf ^ 1;
        if (kt + 1 < nk) {
            int k0 = (kt + 1) * 8;
            av = *(const float4*)&Ab[(size_t)lr * K + k0 + lk];
            bv = *(const float4*)&Bb[(size_t)lr * K + k0 + lk];
        }
#pragma unroll
        for (int k = 0; k < 8; k++) {
            float a[8];
            *(float4*)&a[0] = *(const float4*)&As[buf][k][tr];
            *(float4*)&a[4] = *(const float4*)&As[buf][k][tr + 4];
            ull b2[4];
            {
                ulonglong2 bl = *(const ulonglong2*)&Bs[buf][k][tc];
                ulonglong2 bh = *(const ulonglong2*)&Bs[buf][k][tc + 4];
                b2[0] = bl.x; b2[1] = bl.y; b2[2] = bh.x; b2[3] = bh.y;
            }
#pragma unroll
            for (int i = 0; i < 8; i++) {
                ull aa = pack2(a[i], a[i]);
#pragma unroll
                for (int j = 0; j < 4; j++) ffma2(acc2[i][j], aa, b2[j]);
            }
        }
        if (kt + 1 < nk) {
            As[nbuf][lk + 0][lr] = av.x; As[nbuf][lk + 1][lr] = av.y;
            As[nbuf][lk + 2][lr] = av.z; As[nbuf][lk + 3][lr] = av.w;
            Bs[nbuf][lk + 0][lr] = bv.x; Bs[nbuf][lk + 1][lr] = bv.y;
            Bs[nbuf][lk + 2][lr] = bv.z; Bs[nbuf][lk + 3][lr] = bv.w;
        }
        __syncthreads();
    }

    float bvals[8];
#pragma unroll
    for (int j = 0; j < 8; j++) bvals[j] = bias ? bias[bx * 128 + tc + j] : 0.f;

#pragma unroll
    for (int i = 0; i < 8; i++) {
        int m = by * 128 + tr + i;
        int orow = (m / rbi) * rbo + roff + (m % rbi);
        float* cr = C + (size_t)orow * N + bx * 128 + tc;
        float2 p0 = unpack2(acc2[i][0]);
        float2 p1 = unpack2(acc2[i][1]);
        float2 p2 = unpack2(acc2[i][2]);
        float2 p3 = unpack2(acc2[i][3]);
        float4 v0, v1;
        v0.x = p0.x + bvals[0]; v0.y = p0.y + bvals[1];
        v0.z = p1.x + bvals[2]; v0.w = p1.y + bvals[3];
        v1.x = p2.x + bvals[4]; v1.y = p2.y + bvals[5];
        v1.z = p3.x + bvals[6]; v1.w = p3.y + bvals[7];
        *(float4*)&cr[0] = v0;
        *(float4*)&cr[4] = v1;
    }
}

// ---------------- flash attention (fp32 exact, f32x2 packed FMA) ----------------
#define DST 132
#define SST 65
#define SMEM_ATTN (119808)

__global__ __launch_bounds__(256, 1) void attn_kernel(
    const float* __restrict__ Qp, const float* __restrict__ Kp_,
    const float* __restrict__ Vp, float* __restrict__ Op) {
    extern __shared__ float sm[];
    float* Qs = sm;                   // 64*132
    float* Ks = Qs + 64 * DST;        // 64*132
    float* Vs = Ks + 64 * DST;        // 64*132
    float* Ss = Vs + 64 * DST;        // 64*65
    float* Sp = Ss + 64 * SST;        // 64*4 partial sums
    float* rm = Sp + 256;             // 64 row max
    float* ra = rm + 64;              // 64 row alpha
    float* rl = ra + 64;              // 64 row l

    int t = threadIdx.x;
    int qb = blockIdx.x * 64;
    int h = blockIdx.y;
    int b = blockIdx.z;

    const float* Qbase = Qp + ((size_t)(b * Sq + qb)) * Eq + h * Dq;
    for (int i = t; i < 64 * 32; i += 256) {
        int r = i >> 5, d4 = (i & 31) << 2;
        *(float4*)&Qs[r * DST + d4] = *(const float4*)&Qbase[(size_t)r * Eq + d4];
    }
    if (t < 64) { rm[t] = -1e30f; rl[t] = 0.f; }

    ull acc2o[16];  // 32 output channels as 16 f32x2 pairs
#pragma unroll
    for (int i = 0; i < 16; i++) acc2o[i] = 0ULL;

    const int orow = (t >> 5) * 8 + ((t & 31) >> 2);
    const int oc0 = (t & 3) * 32;
    const int str = t >> 4, stc = t & 15;
    const int er = t >> 2, ec0 = (t & 3) * 16;
    const float SCALE = 0.08838834764831845f;  // 1/sqrt(128)

    __syncthreads();

    for (int kt = 0; kt < Lq / 64; ++kt) {
        const float* Kbase = Kp_ + ((size_t)(b * Lq + kt * 64)) * Eq + h * Dq;
        const float* Vbase = Vp + ((size_t)(b * Lq + kt * 64)) * Eq + h * Dq;
        for (int i = t; i < 64 * 32; i += 256) {
            int r = i >> 5, d4 = (i & 31) << 2;
            *(float4*)&Ks[r * DST + d4] = *(const float4*)&Kbase[(size_t)r * Eq + d4];
            *(float4*)&Vs[r * DST + d4] = *(const float4*)&Vbase[(size_t)r * Eq + d4];
        }
        __syncthreads();

        // scores: 4x4 micro-tile per thread, f32x2 pairs over k
        ull sacc2[4][4];
#pragma unroll
        for (int i = 0; i < 4; i++)
#pragma unroll
            for (int j = 0; j < 4; j++) sacc2[i][j] = 0ULL;

#pragma unroll 4
        for (int k4 = 0; k4 < Dq; k4 += 4) {
            ulonglong2 qv[4], kv[4];
#pragma unroll
            for (int i = 0; i < 4; i++)
                qv[i] = *(const ulonglong2*)&Qs[(str * 4 + i) * DST + k4];
#pragma unroll
            for (int j = 0; j < 4; j++)
                kv[j] = *(const ulonglong2*)&Ks[(stc * 4 + j) * DST + k4];
#pragma unroll
            for (int i = 0; i < 4; i++)
#pragma unroll
                for (int j = 0; j < 4; j++) {
                    ffma2(sacc2[i][j], qv[i].x, kv[j].x);
                    ffma2(sacc2[i][j], qv[i].y, kv[j].y);
                }
        }
#pragma unroll
        for (int i = 0; i < 4; i++)
#pragma unroll
            for (int j = 0; j < 4; j++) {
                float2 p = unpack2(sacc2[i][j]);
                Ss[(str * 4 + i) * SST + stc * 4 + j] = (p.x + p.y) * SCALE;
            }
        __syncthreads();

        // row max + alpha
        if (t < 64) {
            float mo = rm[t], mn = mo;
#pragma unroll 8
            for (int j = 0; j < 64; j++) mn = fmaxf(mn, Ss[t * SST + j]);
            rm[t] = mn;
            ra[t] = __expf(mo - mn);
        }
        __syncthreads();

        // exponentiate + partial row sums
        {
            float m = rm[er];
            float ps = 0.f;
#pragma unroll
            for (int j = 0; j < 16; j++) {
                float e = __expf(Ss[er * SST + ec0 + j] - m);
                Ss[er * SST + ec0 + j] = e;
                ps += e;
            }
            Sp[er * 4 + (t & 3)] = ps;
        }
        __syncthreads();

        if (t < 64) {
            float s = Sp[t * 4] + Sp[t * 4 + 1] + Sp[t * 4 + 2] + Sp[t * 4 + 3];
            rl[t] = rl[t] * ra[t] + s;
        }

        // O = O*alpha + P @ V  (f32x2 pairs over channels)
        {
            float al = ra[orow];
            ull al2 = pack2(al, al);
#pragma unroll
            for (int i = 0; i < 16; i++) acc2o[i] = fmul2(acc2o[i], al2);
#pragma unroll 4
            for (int j = 0; j < 64; j++) {
                float p = Ss[orow * SST + j];
                ull pp = pack2(p, p);
                const float* vr = &Vs[j * DST + oc0];
#pragma unroll
                for (int c2 = 0; c2 < 8; c2++) {
                    ulonglong2 v = *(const ulonglong2*)&vr[c2 * 4];
                    ffma2(acc2o[c2 * 2 + 0], pp, v.x);
                    ffma2(acc2o[c2 * 2 + 1], pp, v.y);
                }
            }
        }
        __syncthreads();
    }

    float invl = 1.0f / rl[orow];
    float* Ob = Op + ((size_t)(b * Sq + qb + orow)) * Eq + h * Dq + oc0;
#pragma unroll
    for (int c4 = 0; c4 < 8; c4++) {
        float2 f0 = unpack2(acc2o[c4 * 2 + 0]);
        float2 f1 = unpack2(acc2o[c4 * 2 + 1]);
        float4 v;
        v.x = f0.x * invl; v.y = f0.y * invl;
        v.z = f1.x * invl; v.w = f1.y * invl;
        *(float4*)&Ob[c4 * 4] = v;
    }
}

// ---------------- host launcher ----------------
extern "C" void kernel_launch(void* const* d_in, const int* in_sizes, int n_in,
                              void* d_out, int out_size) {
    const float* x  = (const float*)d_in[0];
    const float* rt = (const float*)d_in[1];
    const float* qw = (const float*)d_in[2];
    const float* kw = (const float*)d_in[3];
    const float* vw = (const float*)d_in[4];
    const float* ow = (const float*)d_in[5];
    const float* ob = (const float*)d_in[6];
    float* out = (float*)d_out;

    int *w8, *x8;
    float *rows, *qb, *kb, *vb, *obuf, *part, *scale;
    cudaGetSymbolAddress((void**)&w8, g_w8);
    cudaGetSymbolAddress((void**)&x8, g_x8);
    cudaGetSymbolAddress((void**)&rows, g_rows);
    cudaGetSymbolAddress((void**)&qb, g_qb);
    cudaGetSymbolAddress((void**)&kb, g_kb);
    cudaGetSymbolAddress((void**)&vb, g_vb);
    cudaGetSymbolAddress((void**)&obuf, g_ob);
    cudaGetSymbolAddress((void**)&part, g_part);
    cudaGetSymbolAddress((void**)&scale, g_scale);

    cudaFuncSetAttribute(attn_kernel, cudaFuncAttributeMaxDynamicSharedMemorySize,
                         SMEM_ATTN);

    // 1) weight scales (mean |w|), deterministic two-stage
    reduce_abs_kernel<<<dim3(1024, 3), 256>>>(qw, kw, vw, part);
    finalize_scale_kernel<<<3, 256>>>(part, scale);
    // 2) quantize weights + activations to packed int8
    quant_weight_i8<<<dim3(Eq * Eq / (256 * 16), 3), 256>>>(qw, kw, vw, w8, scale);
    quant_act_i8<<<Bq * Sq, 256>>>(x, x8, rows);
    // 3) quantized projections: exact int8 GEMM + dequant epilogue
    size_t EK = (size_t)Eq * Kp;
    sgemm_i8<<<dim3(Eq / 128, (Bq * Sq) / 128), 256>>>(x8, w8 + 0 * EK, qb, rows,
                                                       scale + 0, Eq, Sq, Sq, 0);
    sgemm_i8<<<dim3(Eq / 128, (Bq * Sq) / 128), 256>>>(x8, w8 + 1 * EK, kb, rows,
                                                       scale + 1, Eq, Sq, Lq, 0);
    sgemm_i8<<<dim3(Eq / 128, (Bq * Sq) / 128), 256>>>(x8, w8 + 2 * EK, vb, rows,
                                                       scale + 2, Eq, Sq, Lq, 0);
    // reasoning tokens: unquantized fp32 projections, appended after S self rows
    sgemm128<<<dim3(Eq / 128, (Bq * Rq) / 128), 256>>>(rt, kw, kb, nullptr,
                                                       Eq, Eq, Rq, Lq, Sq);
    sgemm128<<<dim3(Eq / 128, (Bq * Rq) / 128), 256>>>(rt, vw, vb, nullptr,
                                                       Eq, Eq, Rq, Lq, Sq);
    // 4) attention
    attn_kernel<<<dim3(Sq / 64, Hq, Bq), 256, SMEM_ATTN>>>(qb, kb, vb, obuf);
    // 5) output projection + bias
    sgemm128<<<dim3(Eq / 128, (Bq * Sq) / 128), 256>>>(obuf, ow, out, ob,
                                                       Eq, Eq, Bq * Sq, Bq * Sq, 0);
}

// round 4
// speedup vs baseline: 1.2454x; 1.0940x over previous
#include <cuda_runtime.h>
#include <cuda_bf16.h>
#include <cstdint>

#define Bq 2
#define Sq 2048
#define Rq 128
#define Eq 2048
#define Hq 16
#define Dq 128
#define Lq (Sq + Rq)   // 2176

// ---------------- scratch (device globals, no allocations) ----------------
__device__ __nv_bfloat16 g_xbf[(size_t)Bq * Sq * Eq];      // quantized acts as bf16 ints
__device__ __nv_bfloat16 g_wbf[3][(size_t)Eq * Eq];        // ternary weights as bf16
__device__ __nv_bfloat16 g_rt3[(size_t)Bq * Rq * 3 * Eq];  // reasoning tokens split [hi|hi|lo]
__device__ __nv_bfloat16 g_kw3[(size_t)Eq * 3 * Eq];       // k_w split [hi|lo|hi]
__device__ __nv_bfloat16 g_vw3[(size_t)Eq * 3 * Eq];       // v_w split
__device__ __nv_bfloat16 g_ow3[(size_t)Eq * 3 * Eq];       // out_w split
__device__ __nv_bfloat16 g_ao3[(size_t)Bq * Sq * 3 * Eq];  // attn out split [hi|hi|lo]
__device__ float g_rows[(size_t)Bq * Sq];                  // per-row act scale s
__device__ float g_qb[(size_t)Bq * Sq * Eq];               // Q
__device__ float g_kb[(size_t)Bq * Lq * Eq];               // K (self + reasoning)
__device__ float g_vb[(size_t)Bq * Lq * Eq];               // V
__device__ float g_ob[(size_t)Bq * Sq * Eq];               // attention output
__device__ float g_part[3 * 1024];
__device__ float g_scale[3];

// ---------------- small PTX helpers ----------------
typedef unsigned long long ull;
__device__ __forceinline__ ull pack2(float x, float y) {
    ull r; asm("mov.b64 %0, {%1, %2};" : "=l"(r) : "f"(x), "f"(y)); return r;
}
__device__ __forceinline__ float2 unpack2(ull v) {
    float2 f; asm("mov.b64 {%0, %1}, %2;" : "=f"(f.x), "=f"(f.y) : "l"(v)); return f;
}
__device__ __forceinline__ void ffma2(ull& d, ull a, ull b) {
    asm("fma.rn.f32x2 %0, %1, %2, %0;" : "+l"(d) : "l"(a), "l"(b));
}
__device__ __forceinline__ ull fmul2(ull a, ull b) {
    ull d; asm("mul.rn.f32x2 %0, %1, %2;" : "=l"(d) : "l"(a), "l"(b)); return d;
}
__device__ __forceinline__ uint32_t smem_u32(const void* p) {
    uint32_t a;
    asm("{ .reg .u64 t; cvta.to.shared.u64 t, %1; cvt.u32.u64 %0, t; }" : "=r"(a) : "l"(p));
    return a;
}
__device__ __forceinline__ void ldmx4(uint32_t* r, uint32_t addr) {
    asm volatile("ldmatrix.sync.aligned.m8n8.x4.shared.b16 {%0,%1,%2,%3}, [%4];"
                 : "=r"(r[0]), "=r"(r[1]), "=r"(r[2]), "=r"(r[3]) : "r"(addr));
}
__device__ __forceinline__ void ldmx2(uint32_t* r, uint32_t addr) {
    asm volatile("ldmatrix.sync.aligned.m8n8.x2.shared.b16 {%0,%1}, [%2];"
                 : "=r"(r[0]), "=r"(r[1]) : "r"(addr));
}
__device__ __forceinline__ void mma16816(float* c, const uint32_t* a, const uint32_t* b) {
    asm volatile("mma.sync.aligned.m16n8k16.row.col.f32.bf16.bf16.f32 "
                 "{%0,%1,%2,%3}, {%4,%5,%6,%7}, {%8,%9}, {%0,%1,%2,%3};"
                 : "+f"(c[0]), "+f"(c[1]), "+f"(c[2]), "+f"(c[3])
                 : "r"(a[0]), "r"(a[1]), "r"(a[2]), "r"(a[3]), "r"(b[0]), "r"(b[1]));
}

// ---------------- weight mean(|w|) : stage 1 ----------------
__global__ void reduce_abs_kernel(const float* __restrict__ w0, const float* __restrict__ w1,
                                  const float* __restrict__ w2, float* __restrict__ part) {
    const float* w = (blockIdx.y == 0) ? w0 : ((blockIdx.y == 1) ? w1 : w2);
    int t = threadIdx.x;
    size_t base = (size_t)blockIdx.x * 4096;
    float s = 0.f;
#pragma unroll
    for (int i = 0; i < 16; i++) s += fabsf(w[base + t + i * 256]);
    __shared__ float red[256];
    red[t] = s;
    __syncthreads();
    for (int o = 128; o > 0; o >>= 1) {
        if (t < o) red[t] += red[t + o];
        __syncthreads();
    }
    if (t == 0) part[blockIdx.y * 1024 + blockIdx.x] = red[0];
}

__global__ void finalize_scale_kernel(const float* __restrict__ part, float* __restrict__ scale) {
    int w = blockIdx.x;
    int t = threadIdx.x;
    float s = part[w * 1024 + t] + part[w * 1024 + t + 256] +
              part[w * 1024 + t + 512] + part[w * 1024 + t + 768];
    __shared__ float red[256];
    red[t] = s;
    __syncthreads();
    for (int o = 128; o > 0; o >>= 1) {
        if (t < o) red[t] += red[t + o];
        __syncthreads();
    }
    if (t == 0) {
        float mean = red[0] * (1.0f / ((float)Eq * (float)Eq));
        scale[w] = fmaxf(mean, 1e-5f);
    }
}

// ---------------- ternary weight quantization -> bf16 {-1,0,1} ----------------
__global__ void quant_weight_bf16(const float* __restrict__ w0, const float* __restrict__ w1,
                                  const float* __restrict__ w2, __nv_bfloat16* __restrict__ wq,
                                  const float* __restrict__ scale) {
    int wi = blockIdx.y;
    const float* w = (wi == 0) ? w0 : ((wi == 1) ? w1 : w2);
    float inv = __frcp_rn(scale[wi]);
    size_t e0 = ((size_t)blockIdx.x * 256 + threadIdx.x) * 8;
    __nv_bfloat16* wo = wq + (size_t)wi * Eq * Eq + e0;
#pragma unroll
    for (int i = 0; i < 8; i += 4) {
        float4 v = *(const float4*)&w[e0 + i];
        wo[i + 0] = __float2bfloat16(fminf(fmaxf(rintf(v.x * inv), -1.f), 1.f));
        wo[i + 1] = __float2bfloat16(fminf(fmaxf(rintf(v.y * inv), -1.f), 1.f));
        wo[i + 2] = __float2bfloat16(fminf(fmaxf(rintf(v.z * inv), -1.f), 1.f));
        wo[i + 3] = __float2bfloat16(fminf(fmaxf(rintf(v.w * inv), -1.f), 1.f));
    }
}

// ---------------- per-token absmax quantization -> bf16 integers + row scale ----------------
__global__ void quant_act_bf16(const float* __restrict__ x, __nv_bfloat16* __restrict__ xq,
                               float* __restrict__ rows) {
    int row = blockIdx.x;
    int t = threadIdx.x;
    const float* xr = x + (size_t)row * Eq;
    float4 v0 = *(const float4*)&xr[t * 8];
    float4 v1 = *(const float4*)&xr[t * 8 + 4];
    float mx = fmaxf(fmaxf(fmaxf(fabsf(v0.x), fabsf(v0.y)), fmaxf(fabsf(v0.z), fabsf(v0.w))),
                     fmaxf(fmaxf(fabsf(v1.x), fabsf(v1.y)), fmaxf(fabsf(v1.z), fabsf(v1.w))));
    __shared__ float red[256];
    red[t] = mx;
    __syncthreads();
    for (int o = 128; o > 0; o >>= 1) {
        if (t < o) red[t] = fmaxf(red[t], red[t + o]);
        __syncthreads();
    }
    float s = __fdiv_rn(127.0f, fmaxf(red[0], 1e-5f));
    if (t == 0) rows[row] = s;
    __nv_bfloat16* xo = xq + (size_t)row * Eq + t * 8;
    xo[0] = __float2bfloat16(fminf(fmaxf(rintf(v0.x * s), -128.f), 127.f));
    xo[1] = __float2bfloat16(fminf(fmaxf(rintf(v0.y * s), -128.f), 127.f));
    xo[2] = __float2bfloat16(fminf(fmaxf(rintf(v0.z * s), -128.f), 127.f));
    xo[3] = __float2bfloat16(fminf(fmaxf(rintf(v0.w * s), -128.f), 127.f));
    xo[4] = __float2bfloat16(fminf(fmaxf(rintf(v1.x * s), -128.f), 127.f));
    xo[5] = __float2bfloat16(fminf(fmaxf(rintf(v1.y * s), -128.f), 127.f));
    xo[6] = __float2bfloat16(fminf(fmaxf(rintf(v1.z * s), -128.f), 127.f));
    xo[7] = __float2bfloat16(fminf(fmaxf(rintf(v1.w * s), -128.f), 127.f));
}

// ---------------- fp32 -> split-bf16 K-tripling ----------------
// mode 0 (A side): [hi | hi | lo]    mode 1 (B side): [hi | lo | hi]
__global__ void split3(const float* __restrict__ X, __nv_bfloat16* __restrict__ Y, int mode) {
    size_t i = (size_t)blockIdx.x * 256 + threadIdx.x;
    size_t row = i >> 11, col = i & 2047;
    float x = X[i];
    __nv_bfloat16 hi = __float2bfloat16(x);
    __nv_bfloat16 lo = __float2bfloat16(x - __bfloat162float(hi));
    __nv_bfloat16* yr = Y + row * (size_t)(3 * Eq);
    yr[col] = hi;
    yr[Eq + col] = mode ? lo : hi;
    yr[2 * Eq + col] = mode ? hi : lo;
}

// ---------------- HMMA bf16 GEMM: C[m,n] = A[m,:K].B[n,:K] ----------------
// A: [M,K] bf16 row-major, B: [N,K] bf16 row-major.
// Epilogue: C = D * (ws/rows[m]) (+bias), out row = (m/rbi)*rbo + roff + (m%rbi)
// Tile 128x128xBK32, 8 warps (2 M x 4 N), each warp 64x32 via 4x4 m16n8k16 frags.
// smem row = 32 bf16 = 64B; swizzle: 16B-group g stored at g ^ ((row>>1)&3).
__device__ __forceinline__ uint32_t swoff(int r, int g) {
    return (uint32_t)(r * 64 + ((g ^ ((r >> 1) & 3)) << 4));
}

__global__ __launch_bounds__(256) void hmma_gemm(
    const __nv_bfloat16* __restrict__ A, const __nv_bfloat16* __restrict__ B,
    float* __restrict__ C, const float* __restrict__ rowscale,
    const float* __restrict__ wsp, const float* __restrict__ bias,
    int K, int Nout, int rbi, int rbo, int roff) {
    __shared__ __align__(128) uint8_t sA[2][8192];
    __shared__ __align__(128) uint8_t sB[2][8192];
    int t = threadIdx.x;
    int lane = t & 31, wid = t >> 5;
    int m0 = blockIdx.y * 128, n0 = blockIdx.x * 128;
    int warp_m = wid & 1, warp_n = wid >> 1;

    // gmem load mapping: chunk c in [0,512): r=c>>2, g=c&3 (16B each); thread does c=t and c=t+256
    int r0 = t >> 2, g0 = t & 3;
    int r1 = 64 + r0;
    const uint4* Ag0 = (const uint4*)(A + (size_t)(m0 + r0) * K) + g0;
    const uint4* Ag1 = (const uint4*)(A + (size_t)(m0 + r1) * K) + g0;
    const uint4* Bg0 = (const uint4*)(B + (size_t)(n0 + r0) * K) + g0;
    const uint4* Bg1 = (const uint4*)(B + (size_t)(n0 + r1) * K) + g0;
    uint32_t st0 = swoff(r0, g0), st1 = swoff(r1, g0);

    uint32_t sAu = smem_u32(sA), sBu = smem_u32(sB);

    // ldmatrix base addresses (ks=0); ks=1 address = base ^ 32
    uint32_t aaddr[4], baddr[4];
#pragma unroll
    for (int mi = 0; mi < 4; mi++) {
        int r = warp_m * 64 + mi * 16 + (lane & 15);
        int g = lane >> 4;
        aaddr[mi] = sAu + swoff(r, g);
    }
#pragma unroll
    for (int ni = 0; ni < 4; ni++) {
        int r = warp_n * 32 + ni * 8 + (lane & 7);
        int g = (lane >> 3) & 1;
        baddr[ni] = sBu + swoff(r, g);
    }

    // preload tile 0
    uint4 pa0 = Ag0[0], pa1 = Ag1[0], pb0 = Bg0[0], pb1 = Bg1[0];
    *(uint4*)(sA[0] + st0) = pa0;
    *(uint4*)(sA[0] + st1) = pa1;
    *(uint4*)(sB[0] + st0) = pb0;
    *(uint4*)(sB[0] + st1) = pb1;
    __syncthreads();

    float c[4][4][4];
#pragma unroll
    for (int mi = 0; mi < 4; mi++)
#pragma unroll
        for (int ni = 0; ni < 4; ni++)
#pragma unroll
            for (int k = 0; k < 4; k++) c[mi][ni][k] = 0.f;

    const int NK = K >> 5;
    for (int kt = 0; kt < NK; ++kt) {
        int buf = kt & 1;
        if (kt + 1 < NK) {
            pa0 = Ag0[(kt + 1) * 4];
            pa1 = Ag1[(kt + 1) * 4];
            pb0 = Bg0[(kt + 1) * 4];
            pb1 = Bg1[(kt + 1) * 4];
        }
        uint32_t bofs = buf * 8192;
#pragma unroll
        for (int ks = 0; ks < 2; ks++) {
            uint32_t kx = ks * 32;
            uint32_t a[4][4], b[4][2];
#pragma unroll
            for (int mi = 0; mi < 4; mi++) ldmx4(a[mi], (aaddr[mi] + bofs) ^ kx);
#pragma unroll
            for (int ni = 0; ni < 4; ni++) ldmx2(b[ni], (baddr[ni] + bofs) ^ kx);
#pragma unroll
            for (int mi = 0; mi < 4; mi++)
#pragma unroll
                for (int ni = 0; ni < 4; ni++) mma16816(c[mi][ni], a[mi], b[ni]);
        }
        if (kt + 1 < NK) {
            int nb = buf ^ 1;
            *(uint4*)(sA[nb] + st0) = pa0;
            *(uint4*)(sA[nb] + st1) = pa1;
            *(uint4*)(sB[nb] + st0) = pb0;
            *(uint4*)(sB[nb] + st1) = pb1;
        }
        __syncthreads();
    }

    // epilogue
    float ws = wsp ? *wsp : 1.0f;
    int g = lane >> 2, tg = lane & 3;
#pragma unroll
    for (int mi = 0; mi < 4; mi++) {
        int mA = m0 + warp_m * 64 + mi * 16 + g;
        int mB = mA + 8;
        float fA = rowscale ? (ws / rowscale[mA]) : 1.0f;
        float fB = rowscale ? (ws / rowscale[mB]) : 1.0f;
        int oA = (mA / rbi) * rbo + roff + (mA % rbi);
        int oB = (mB / rbi) * rbo + roff + (mB % rbi);
        float* crA = C + (size_t)oA * Nout;
        float* crB = C + (size_t)oB * Nout;
#pragma unroll
        for (int ni = 0; ni < 4; ni++) {
            int col = n0 + warp_n * 32 + ni * 8 + tg * 2;
            float b0 = 0.f, b1 = 0.f;
            if (bias) { b0 = bias[col]; b1 = bias[col + 1]; }
            float2 vA, vB;
            vA.x = c[mi][ni][0] * fA + b0;
            vA.y = c[mi][ni][1] * fA + b1;
            vB.x = c[mi][ni][2] * fB + b0;
            vB.y = c[mi][ni][3] * fB + b1;
            *(float2*)&crA[col] = vA;
            *(float2*)&crB[col] = vB;
        }
    }
}

// ---------------- flash attention (fp32 exact, f32x2 packed FMA) ----------------
#define DST 132
#define SST 65
#define SMEM_ATTN (119808)

__global__ __launch_bounds__(256, 1) void attn_kernel(
    const float* __restrict__ Qp, const float* __restrict__ Kp_,
    const float* __restrict__ Vp, float* __restrict__ Op) {
    extern __shared__ char smg[];
    float* sm = (float*)smg;
    float* Qs = sm;
    float* Ks = Qs + 64 * DST;
    float* Vs = Ks + 64 * DST;
    float* Ss = Vs + 64 * DST;
    float* Sp = Ss + 64 * SST;
    float* rm = Sp + 256;
    float* ra = rm + 64;
    float* rl = ra + 64;

    int t = threadIdx.x;
    int qb = blockIdx.x * 64;
    int h = blockIdx.y;
    int b = blockIdx.z;

    const float* Qbase = Qp + ((size_t)(b * Sq + qb)) * Eq + h * Dq;
    for (int i = t; i < 64 * 32; i += 256) {
        int r = i >> 5, d4 = (i & 31) << 2;
        *(float4*)&Qs[r * DST + d4] = *(const float4*)&Qbase[(size_t)r * Eq + d4];
    }
    if (t < 64) { rm[t] = -1e30f; rl[t] = 0.f; }

    ull acc2o[16];
#pragma unroll
    for (int i = 0; i < 16; i++) acc2o[i] = 0ULL;

    const int orow = (t >> 5) * 8 + ((t & 31) >> 2);
    const int oc0 = (t & 3) * 32;
    const int str = t >> 4, stc = t & 15;
    const int er = t >> 2, ec0 = (t & 3) * 16;
    const float SCALE = 0.08838834764831845f;

    __syncthreads();

    for (int kt = 0; kt < Lq / 64; ++kt) {
        const float* Kbase = Kp_ + ((size_t)(b * Lq + kt * 64)) * Eq + h * Dq;
        const float* Vbase = Vp + ((size_t)(b * Lq + kt * 64)) * Eq + h * Dq;
        for (int i = t; i < 64 * 32; i += 256) {
            int r = i >> 5, d4 = (i & 31) << 2;
            *(float4*)&Ks[r * DST + d4] = *(const float4*)&Kbase[(size_t)r * Eq + d4];
            *(float4*)&Vs[r * DST + d4] = *(const float4*)&Vbase[(size_t)r * Eq + d4];
        }
        __syncthreads();

        ull sacc2[4][4];
#pragma unroll
        for (int i = 0; i < 4; i++)
#pragma unroll
            for (int j = 0; j < 4; j++) sacc2[i][j] = 0ULL;

#pragma unroll 4
        for (int k4 = 0; k4 < Dq; k4 += 4) {
            ulonglong2 qv[4], kv[4];
#pragma unroll
            for (int i = 0; i < 4; i++)
                qv[i] = *(const ulonglong2*)&Qs[(str * 4 + i) * DST + k4];
#pragma unroll
            for (int j = 0; j < 4; j++)
                kv[j] = *(const ulonglong2*)&Ks[(stc * 4 + j) * DST + k4];
#pragma unroll
            for (int i = 0; i < 4; i++)
#pragma unroll
                for (int j = 0; j < 4; j++) {
                    ffma2(sacc2[i][j], qv[i].x, kv[j].x);
                    ffma2(sacc2[i][j], qv[i].y, kv[j].y);
                }
        }
#pragma unroll
        for (int i = 0; i < 4; i++)
#pragma unroll
            for (int j = 0; j < 4; j++) {
                float2 p = unpack2(sacc2[i][j]);
                Ss[(str * 4 + i) * SST + stc * 4 + j] = (p.x + p.y) * SCALE;
            }
        __syncthreads();

        if (t < 64) {
            float mo = rm[t], mn = mo;
#pragma unroll 8
            for (int j = 0; j < 64; j++) mn = fmaxf(mn, Ss[t * SST + j]);
            rm[t] = mn;
            ra[t] = __expf(mo - mn);
        }
        __syncthreads();

        {
            float m = rm[er];
            float ps = 0.f;
#pragma unroll
            for (int j = 0; j < 16; j++) {
                float e = __expf(Ss[er * SST + ec0 + j] - m);
                Ss[er * SST + ec0 + j] = e;
                ps += e;
            }
            Sp[er * 4 + (t & 3)] = ps;
        }
        __syncthreads();

        if (t < 64) {
            float s = Sp[t * 4] + Sp[t * 4 + 1] + Sp[t * 4 + 2] + Sp[t * 4 + 3];
            rl[t] = rl[t] * ra[t] + s;
        }

        {
            float al = ra[orow];
            ull al2 = pack2(al, al);
#pragma unroll
            for (int i = 0; i < 16; i++) acc2o[i] = fmul2(acc2o[i], al2);
#pragma unroll 4
            for (int j = 0; j < 64; j++) {
                float p = Ss[orow * SST + j];
                ull pp = pack2(p, p);
                const float* vr = &Vs[j * DST + oc0];
#pragma unroll
                for (int c2 = 0; c2 < 8; c2++) {
                    ulonglong2 v = *(const ulonglong2*)&vr[c2 * 4];
                    ffma2(acc2o[c2 * 2 + 0], pp, v.x);
                    ffma2(acc2o[c2 * 2 + 1], pp, v.y);
                }
            }
        }
        __syncthreads();
    }

    float invl = 1.0f / rl[orow];
    float* Ob = Op + ((size_t)(b * Sq + qb + orow)) * Eq + h * Dq + oc0;
#pragma unroll
    for (int c4 = 0; c4 < 8; c4++) {
        float2 f0 = unpack2(acc2o[c4 * 2 + 0]);
        float2 f1 = unpack2(acc2o[c4 * 2 + 1]);
        float4 v;
        v.x = f0.x * invl; v.y = f0.y * invl;
        v.z = f1.x * invl; v.w = f1.y * invl;
        *(float4*)&Ob[c4 * 4] = v;
    }
}

// ---------------- host launcher ----------------
extern "C" void kernel_launch(void* const* d_in, const int* in_sizes, int n_in,
                              void* d_out, int out_size) {
    const float* x  = (const float*)d_in[0];
    const float* rt = (const float*)d_in[1];
    const float* qw = (const float*)d_in[2];
    const float* kw = (const float*)d_in[3];
    const float* vw = (const float*)d_in[4];
    const float* ow = (const float*)d_in[5];
    const float* ob = (const float*)d_in[6];
    float* out = (float*)d_out;

    __nv_bfloat16 *xbf, *wbf, *rt3, *kw3, *vw3, *ow3, *ao3;
    float *rows, *qb, *kb, *vb, *obuf, *part, *scale;
    cudaGetSymbolAddress((void**)&xbf, g_xbf);
    cudaGetSymbolAddress((void**)&wbf, g_wbf);
    cudaGetSymbolAddress((void**)&rt3, g_rt3);
    cudaGetSymbolAddress((void**)&kw3, g_kw3);
    cudaGetSymbolAddress((void**)&vw3, g_vw3);
    cudaGetSymbolAddress((void**)&ow3, g_ow3);
    cudaGetSymbolAddress((void**)&ao3, g_ao3);
    cudaGetSymbolAddress((void**)&rows, g_rows);
    cudaGetSymbolAddress((void**)&qb, g_qb);
    cudaGetSymbolAddress((void**)&kb, g_kb);
    cudaGetSymbolAddress((void**)&vb, g_vb);
    cudaGetSymbolAddress((void**)&obuf, g_ob);
    cudaGetSymbolAddress((void**)&part, g_part);
    cudaGetSymbolAddress((void**)&scale, g_scale);

    cudaFuncSetAttribute(attn_kernel, cudaFuncAttributeMaxDynamicSharedMemorySize, SMEM_ATTN);

    // 1) weight scales
    reduce_abs_kernel<<<dim3(1024, 3), 256>>>(qw, kw, vw, part);
    finalize_scale_kernel<<<3, 256>>>(part, scale);
    // 2) quantize to bf16 (exact integer/ternary values)
    quant_weight_bf16<<<dim3(2048, 3), 256>>>(qw, kw, vw, wbf, scale);
    quant_act_bf16<<<Bq * Sq, 256>>>(x, xbf, rows);
    // 3) split unquantized operands (K-tripled bf16)
    split3<<<(Eq * Eq) / 256, 256>>>(kw, kw3, 1);
    split3<<<(Eq * Eq) / 256, 256>>>(vw, vw3, 1);
    split3<<<(Eq * Eq) / 256, 256>>>(ow, ow3, 1);
    split3<<<(Bq * Rq * Eq) / 256, 256>>>(rt, rt3, 0);
    // 4) quantized projections: exact bf16-int HMMA GEMM + dequant epilogue
    size_t EE = (size_t)Eq * Eq;
    hmma_gemm<<<dim3(16, 32), 256>>>(xbf, wbf + 0 * EE, qb, rows, scale + 0, nullptr,
                                     Eq, Eq, Sq, Sq, 0);
    hmma_gemm<<<dim3(16, 32), 256>>>(xbf, wbf + 1 * EE, kb, rows, scale + 1, nullptr,
                                     Eq, Eq, Sq, Lq, 0);
    hmma_gemm<<<dim3(16, 32), 256>>>(xbf, wbf + 2 * EE, vb, rows, scale + 2, nullptr,
                                     Eq, Eq, Sq, Lq, 0);
    // 5) reasoning projections: split-bf16 (K=6144), appended after S self rows
    hmma_gemm<<<dim3(16, 2), 256>>>(rt3, kw3, kb, nullptr, nullptr, nullptr,
                                    3 * Eq, Eq, Rq, Lq, Sq);
    hmma_gemm<<<dim3(16, 2), 256>>>(rt3, vw3, vb, nullptr, nullptr, nullptr,
                                    3 * Eq, Eq, Rq, Lq, Sq);
    // 6) attention
    attn_kernel<<<dim3(Sq / 64, Hq, Bq), 256, SMEM_ATTN>>>(qb, kb, vb, obuf);
    // 7) output projection: split attn output, split-bf16 GEMM + bias
    split3<<<(Bq * Sq * Eq) / 256, 256>>>(obuf, ao3, 0);
    hmma_gemm<<<dim3(16, 32), 256>>>(ao3, ow3, out, nullptr, nullptr, ob,
                                     3 * Eq, Eq, Bq * Sq, Bq * Sq, 0);
}

// round 5
// speedup vs baseline: 6.2437x; 5.0133x over previous
#include <cuda_runtime.h>
#include <cuda_bf16.h>
#include <cstdint>

#define Bq 2
#define Sq 2048
#define Rq 128
#define Eq 2048
#define Hq 16
#define Dq 128
#define Lq (Sq + Rq)   // 2176

// ---------------- scratch (device globals, no allocations) ----------------
__device__ __nv_bfloat16 g_xbf[(size_t)Bq * Sq * Eq];      // quantized acts as bf16 ints
__device__ __nv_bfloat16 g_wbf[3][(size_t)Eq * Eq];        // ternary weights as bf16
__device__ __nv_bfloat16 g_rt3[(size_t)Bq * Rq * 3 * Eq];  // reasoning tokens split [hi|hi|lo]
__device__ __nv_bfloat16 g_kw3[(size_t)Eq * 3 * Eq];       // k_w split [hi|lo|hi]
__device__ __nv_bfloat16 g_vw3[(size_t)Eq * 3 * Eq];       // v_w split
__device__ __nv_bfloat16 g_ow3[(size_t)Eq * 3 * Eq];       // out_w split
__device__ __nv_bfloat16 g_ao3[(size_t)Bq * Sq * 3 * Eq];  // attn out split [hi|hi|lo]
__device__ __nv_bfloat16 g_qh[(size_t)Bq * Sq * Eq];       // Q hi
__device__ __nv_bfloat16 g_ql[(size_t)Bq * Sq * Eq];       // Q lo
__device__ __nv_bfloat16 g_kh[(size_t)Bq * Lq * Eq];       // K hi
__device__ __nv_bfloat16 g_kl[(size_t)Bq * Lq * Eq];       // K lo
__device__ __nv_bfloat16 g_vth[(size_t)Bq * Hq * Dq * Lq]; // V^T hi [B,H,D,L]
__device__ __nv_bfloat16 g_vtl[(size_t)Bq * Hq * Dq * Lq]; // V^T lo
__device__ float g_rows[(size_t)Bq * Sq];                  // per-row act scale s
__device__ float g_qb[(size_t)Bq * Sq * Eq];               // Q fp32
__device__ float g_kb[(size_t)Bq * Lq * Eq];               // K fp32 (self + reasoning)
__device__ float g_vb[(size_t)Bq * Lq * Eq];               // V fp32
__device__ float g_part[3 * 1024];
__device__ float g_scale[3];

// ---------------- PTX helpers ----------------
typedef unsigned long long ull;
__device__ __forceinline__ uint32_t smem_u32(const void* p) {
    uint32_t a;
    asm("{ .reg .u64 t; cvta.to.shared.u64 t, %1; cvt.u32.u64 %0, t; }" : "=r"(a) : "l"(p));
    return a;
}
__device__ __forceinline__ void ldmx4(uint32_t* r, uint32_t addr) {
    asm volatile("ldmatrix.sync.aligned.m8n8.x4.shared.b16 {%0,%1,%2,%3}, [%4];"
                 : "=r"(r[0]), "=r"(r[1]), "=r"(r[2]), "=r"(r[3]) : "r"(addr));
}
__device__ __forceinline__ void ldmx2(uint32_t* r, uint32_t addr) {
    asm volatile("ldmatrix.sync.aligned.m8n8.x2.shared.b16 {%0,%1}, [%2];"
                 : "=r"(r[0]), "=r"(r[1]) : "r"(addr));
}
__device__ __forceinline__ void mma16816(float* c, const uint32_t* a, const uint32_t* b) {
    asm volatile("mma.sync.aligned.m16n8k16.row.col.f32.bf16.bf16.f32 "
                 "{%0,%1,%2,%3}, {%4,%5,%6,%7}, {%8,%9}, {%0,%1,%2,%3};"
                 : "+f"(c[0]), "+f"(c[1]), "+f"(c[2]), "+f"(c[3])
                 : "r"(a[0]), "r"(a[1]), "r"(a[2]), "r"(a[3]), "r"(b[0]), "r"(b[1]));
}
// smem rows of 32 bf16 (64B); 16B group g stored at g ^ ((row>>1)&3)
__device__ __forceinline__ uint32_t swoff(int r, int g) {
    return (uint32_t)(r * 64 + ((g ^ ((r >> 1) & 3)) << 4));
}

// ---------------- weight mean(|w|) : stage 1 ----------------
__global__ void reduce_abs_kernel(const float* __restrict__ w0, const float* __restrict__ w1,
                                  const float* __restrict__ w2, float* __restrict__ part) {
    const float* w = (blockIdx.y == 0) ? w0 : ((blockIdx.y == 1) ? w1 : w2);
    int t = threadIdx.x;
    size_t base = (size_t)blockIdx.x * 4096;
    float s = 0.f;
#pragma unroll
    for (int i = 0; i < 16; i++) s += fabsf(w[base + t + i * 256]);
    __shared__ float red[256];
    red[t] = s;
    __syncthreads();
    for (int o = 128; o > 0; o >>= 1) {
        if (t < o) red[t] += red[t + o];
        __syncthreads();
    }
    if (t == 0) part[blockIdx.y * 1024 + blockIdx.x] = red[0];
}

__global__ void finalize_scale_kernel(const float* __restrict__ part, float* __restrict__ scale) {
    int w = blockIdx.x;
    int t = threadIdx.x;
    float s = part[w * 1024 + t] + part[w * 1024 + t + 256] +
              part[w * 1024 + t + 512] + part[w * 1024 + t + 768];
    __shared__ float red[256];
    red[t] = s;
    __syncthreads();
    for (int o = 128; o > 0; o >>= 1) {
        if (t < o) red[t] += red[t + o];
        __syncthreads();
    }
    if (t == 0) {
        float mean = red[0] * (1.0f / ((float)Eq * (float)Eq));
        scale[w] = fmaxf(mean, 1e-5f);
    }
}

// ---------------- ternary weight quantization -> bf16 {-1,0,1} ----------------
__global__ void quant_weight_bf16(const float* __restrict__ w0, const float* __restrict__ w1,
                                  const float* __restrict__ w2, __nv_bfloat16* __restrict__ wq,
                                  const float* __restrict__ scale) {
    int wi = blockIdx.y;
    const float* w = (wi == 0) ? w0 : ((wi == 1) ? w1 : w2);
    float inv = __frcp_rn(scale[wi]);
    size_t e0 = ((size_t)blockIdx.x * 256 + threadIdx.x) * 8;
    __nv_bfloat16* wo = wq + (size_t)wi * Eq * Eq + e0;
#pragma unroll
    for (int i = 0; i < 8; i += 4) {
        float4 v = *(const float4*)&w[e0 + i];
        wo[i + 0] = __float2bfloat16(fminf(fmaxf(rintf(v.x * inv), -1.f), 1.f));
        wo[i + 1] = __float2bfloat16(fminf(fmaxf(rintf(v.y * inv), -1.f), 1.f));
        wo[i + 2] = __float2bfloat16(fminf(fmaxf(rintf(v.z * inv), -1.f), 1.f));
        wo[i + 3] = __float2bfloat16(fminf(fmaxf(rintf(v.w * inv), -1.f), 1.f));
    }
}

// ---------------- per-token absmax quantization -> bf16 integers + row scale ----------------
__global__ void quant_act_bf16(const float* __restrict__ x, __nv_bfloat16* __restrict__ xq,
                               float* __restrict__ rows) {
    int row = blockIdx.x;
    int t = threadIdx.x;
    const float* xr = x + (size_t)row * Eq;
    float4 v0 = *(const float4*)&xr[t * 8];
    float4 v1 = *(const float4*)&xr[t * 8 + 4];
    float mx = fmaxf(fmaxf(fmaxf(fabsf(v0.x), fabsf(v0.y)), fmaxf(fabsf(v0.z), fabsf(v0.w))),
                     fmaxf(fmaxf(fabsf(v1.x), fabsf(v1.y)), fmaxf(fabsf(v1.z), fabsf(v1.w))));
    __shared__ float red[256];
    red[t] = mx;
    __syncthreads();
    for (int o = 128; o > 0; o >>= 1) {
        if (t < o) red[t] = fmaxf(red[t], red[t + o]);
        __syncthreads();
    }
    float s = __fdiv_rn(127.0f, fmaxf(red[0], 1e-5f));
    if (t == 0) rows[row] = s;
    __nv_bfloat16* xo = xq + (size_t)row * Eq + t * 8;
    xo[0] = __float2bfloat16(fminf(fmaxf(rintf(v0.x * s), -128.f), 127.f));
    xo[1] = __float2bfloat16(fminf(fmaxf(rintf(v0.y * s), -128.f), 127.f));
    xo[2] = __float2bfloat16(fminf(fmaxf(rintf(v0.z * s), -128.f), 127.f));
    xo[3] = __float2bfloat16(fminf(fmaxf(rintf(v0.w * s), -128.f), 127.f));
    xo[4] = __float2bfloat16(fminf(fmaxf(rintf(v1.x * s), -128.f), 127.f));
    xo[5] = __float2bfloat16(fminf(fmaxf(rintf(v1.y * s), -128.f), 127.f));
    xo[6] = __float2bfloat16(fminf(fmaxf(rintf(v1.z * s), -128.f), 127.f));
    xo[7] = __float2bfloat16(fminf(fmaxf(rintf(v1.w * s), -128.f), 127.f));
}

// ---------------- fp32 -> split-bf16 K-tripling (row length 2048) ----------------
// mode 0 (A side): [hi | hi | lo]    mode 1 (B side): [hi | lo | hi]
__global__ void split3(const float* __restrict__ X, __nv_bfloat16* __restrict__ Y, int mode) {
    size_t i = (size_t)blockIdx.x * 256 + threadIdx.x;
    size_t row = i >> 11, col = i & 2047;
    float x = X[i];
    __nv_bfloat16 hi = __float2bfloat16(x);
    __nv_bfloat16 lo = __float2bfloat16(x - __bfloat162float(hi));
    __nv_bfloat16* yr = Y + row * (size_t)(3 * Eq);
    yr[col] = hi;
    yr[Eq + col] = mode ? lo : hi;
    yr[2 * Eq + col] = mode ? hi : lo;
}

// ---------------- fp32 -> separate hi/lo bf16 buffers ----------------
__global__ void split_hl(const float* __restrict__ X, __nv_bfloat16* __restrict__ H,
                         __nv_bfloat16* __restrict__ L) {
    size_t i = ((size_t)blockIdx.x * 256 + threadIdx.x) * 4;
    float4 v = *(const float4*)&X[i];
    __nv_bfloat16 h0 = __float2bfloat16(v.x), h1 = __float2bfloat16(v.y);
    __nv_bfloat16 h2 = __float2bfloat16(v.z), h3 = __float2bfloat16(v.w);
    __nv_bfloat162* Hp = (__nv_bfloat162*)&H[i];
    __nv_bfloat162* Lp = (__nv_bfloat162*)&L[i];
    __nv_bfloat162 a, b, c, d;
    a.x = h0; a.y = h1; b.x = h2; b.y = h3;
    c.x = __float2bfloat16(v.x - __bfloat162float(h0));
    c.y = __float2bfloat16(v.y - __bfloat162float(h1));
    d.x = __float2bfloat16(v.z - __bfloat162float(h2));
    d.y = __float2bfloat16(v.w - __bfloat162float(h3));
    Hp[0] = a; Hp[1] = b;
    Lp[0] = c; Lp[1] = d;
}

// ---------------- V fp32 [B,L,E] -> V^T hi/lo [B,H,D,L] ----------------
__global__ void transpose_v(const float* __restrict__ V, __nv_bfloat16* __restrict__ Th,
                            __nv_bfloat16* __restrict__ Tl) {
    __shared__ float s[32][33];
    int l0 = blockIdx.x * 32;
    int e0 = blockIdx.y * 32;
    int b = blockIdx.z;
    int t = threadIdx.x;
    int h = e0 >> 7, d0 = e0 & 127;
#pragma unroll
    for (int i = 0; i < 4; i++) {
        int idx = t + i * 256;
        int lr = idx >> 5, lc = idx & 31;
        s[lr][lc] = V[((size_t)(b * Lq + l0 + lr)) * Eq + e0 + lc];
    }
    __syncthreads();
#pragma unroll
    for (int i = 0; i < 4; i++) {
        int idx = t + i * 256;
        int dr = idx >> 5, dc = idx & 31;
        float f = s[dc][dr];
        __nv_bfloat16 hi = __float2bfloat16(f);
        __nv_bfloat16 lo = __float2bfloat16(f - __bfloat162float(hi));
        size_t o = ((size_t)((b * Hq + h) * Dq + d0 + dr)) * Lq + l0 + dc;
        Th[o] = hi;
        Tl[o] = lo;
    }
}

// ---------------- HMMA bf16 GEMM (unchanged, proven in round 4) ----------------
__global__ __launch_bounds__(256) void hmma_gemm(
    const __nv_bfloat16* __restrict__ A, const __nv_bfloat16* __restrict__ B,
    float* __restrict__ C, const float* __restrict__ rowscale,
    const float* __restrict__ wsp, const float* __restrict__ bias,
    int K, int Nout, int rbi, int rbo, int roff) {
    __shared__ __align__(128) uint8_t sA[2][8192];
    __shared__ __align__(128) uint8_t sB[2][8192];
    int t = threadIdx.x;
    int lane = t & 31, wid = t >> 5;
    int m0 = blockIdx.y * 128, n0 = blockIdx.x * 128;
    int warp_m = wid & 1, warp_n = wid >> 1;

    int r0 = t >> 2, g0 = t & 3;
    int r1 = 64 + r0;
    const uint4* Ag0 = (const uint4*)(A + (size_t)(m0 + r0) * K) + g0;
    const uint4* Ag1 = (const uint4*)(A + (size_t)(m0 + r1) * K) + g0;
    const uint4* Bg0 = (const uint4*)(B + (size_t)(n0 + r0) * K) + g0;
    const uint4* Bg1 = (const uint4*)(B + (size_t)(n0 + r1) * K) + g0;
    uint32_t st0 = swoff(r0, g0), st1 = swoff(r1, g0);

    uint32_t sAu = smem_u32(sA), sBu = smem_u32(sB);

    uint32_t aaddr[4], baddr[4];
#pragma unroll
    for (int mi = 0; mi < 4; mi++) {
        int r = warp_m * 64 + mi * 16 + (lane & 15);
        int g = lane >> 4;
        aaddr[mi] = sAu + swoff(r, g);
    }
#pragma unroll
    for (int ni = 0; ni < 4; ni++) {
        int r = warp_n * 32 + ni * 8 + (lane & 7);
        int g = (lane >> 3) & 1;
        baddr[ni] = sBu + swoff(r, g);
    }

    uint4 pa0 = Ag0[0], pa1 = Ag1[0], pb0 = Bg0[0], pb1 = Bg1[0];
    *(uint4*)(sA[0] + st0) = pa0;
    *(uint4*)(sA[0] + st1) = pa1;
    *(uint4*)(sB[0] + st0) = pb0;
    *(uint4*)(sB[0] + st1) = pb1;
    __syncthreads();

    float c[4][4][4];
#pragma unroll
    for (int mi = 0; mi < 4; mi++)
#pragma unroll
        for (int ni = 0; ni < 4; ni++)
#pragma unroll
            for (int k = 0; k < 4; k++) c[mi][ni][k] = 0.f;

    const int NK = K >> 5;
    for (int kt = 0; kt < NK; ++kt) {
        int buf = kt & 1;
        if (kt + 1 < NK) {
            pa0 = Ag0[(kt + 1) * 4];
            pa1 = Ag1[(kt + 1) * 4];
            pb0 = Bg0[(kt + 1) * 4];
            pb1 = Bg1[(kt + 1) * 4];
        }
        uint32_t bofs = buf * 8192;
#pragma unroll
        for (int ks = 0; ks < 2; ks++) {
            uint32_t kx = ks * 32;
            uint32_t a[4][4], b[4][2];
#pragma unroll
            for (int mi = 0; mi < 4; mi++) ldmx4(a[mi], (aaddr[mi] + bofs) ^ kx);
#pragma unroll
            for (int ni = 0; ni < 4; ni++) ldmx2(b[ni], (baddr[ni] + bofs) ^ kx);
#pragma unroll
            for (int mi = 0; mi < 4; mi++)
#pragma unroll
                for (int ni = 0; ni < 4; ni++) mma16816(c[mi][ni], a[mi], b[ni]);
        }
        if (kt + 1 < NK) {
            int nb = buf ^ 1;
            *(uint4*)(sA[nb] + st0) = pa0;
            *(uint4*)(sA[nb] + st1) = pa1;
            *(uint4*)(sB[nb] + st0) = pb0;
            *(uint4*)(sB[nb] + st1) = pb1;
        }
        __syncthreads();
    }

    float ws = wsp ? *wsp : 1.0f;
    int g = lane >> 2, tg = lane & 3;
#pragma unroll
    for (int mi = 0; mi < 4; mi++) {
        int mA = m0 + warp_m * 64 + mi * 16 + g;
        int mB = mA + 8;
        float fA = rowscale ? (ws / rowscale[mA]) : 1.0f;
        float fB = rowscale ? (ws / rowscale[mB]) : 1.0f;
        int oA = (mA / rbi) * rbo + roff + (mA % rbi);
        int oB = (mB / rbi) * rbo + roff + (mB % rbi);
        float* crA = C + (size_t)oA * Nout;
        float* crB = C + (size_t)oB * Nout;
#pragma unroll
        for (int ni = 0; ni < 4; ni++) {
            int col = n0 + warp_n * 32 + ni * 8 + tg * 2;
            float b0 = 0.f, b1 = 0.f;
            if (bias) { b0 = bias[col]; b1 = bias[col + 1]; }
            float2 vA, vB;
            vA.x = c[mi][ni][0] * fA + b0;
            vA.y = c[mi][ni][1] * fA + b1;
            vB.x = c[mi][ni][2] * fB + b0;
            vB.y = c[mi][ni][3] * fB + b1;
            *(float2*)&crA[col] = vA;
            *(float2*)&crB[col] = vB;
        }
    }
}

// ---------------- HMMA flash attention (split-bf16 exact) ----------------
// smem layout (bytes):
#define OFF_QH 0
#define OFF_QL 16384
#define OFF_KH 32768
#define OFF_KL 49152
#define OFF_VH 32768
#define OFF_VL 49152
#define OFF_PH 65536
#define OFF_PL 73728
#define OFF_SS 81920            // float [64][66]
#define OFF_RED (OFF_SS + 64 * 66 * 4)   // Sp[256]f, rm[64]f, ra[64]f, rl[64]f
#define SMEM_ATTN2 (OFF_RED + 1792)

__global__ __launch_bounds__(256, 2) void attn_mma(
    const __nv_bfloat16* __restrict__ Qh, const __nv_bfloat16* __restrict__ Ql,
    const __nv_bfloat16* __restrict__ Kh, const __nv_bfloat16* __restrict__ Kl,
    const __nv_bfloat16* __restrict__ Vth, const __nv_bfloat16* __restrict__ Vtl,
    __nv_bfloat16* __restrict__ O3) {
    extern __shared__ char smg[];
    uint32_t sb = smem_u32(smg);
    float* Ss = (float*)(smg + OFF_SS);
    float* Sp = (float*)(smg + OFF_RED);
    float* rm = Sp + 256;
    float* ra = rm + 64;
    float* rl = ra + 64;

    int t = threadIdx.x;
    int lane = t & 31, wid = t >> 5;
    int qb = blockIdx.x * 64;
    int h = blockIdx.y;
    int b = blockIdx.z;

    // load Q hi/lo: 64 rows x 128 cols, 16 uint4-groups per row
    {
        const __nv_bfloat16* Qhg = Qh + ((size_t)(b * Sq + qb)) * Eq + h * Dq;
        const __nv_bfloat16* Qlg = Ql + ((size_t)(b * Sq + qb)) * Eq + h * Dq;
#pragma unroll
        for (int i = 0; i < 4; i++) {
            int idx = t + i * 256;
            int r = idx >> 4, g = idx & 15;
            int chunk = g >> 2, gc = g & 3;
            uint32_t dst = chunk * 4096 + swoff(r, gc);
            *(uint4*)(smg + OFF_QH + dst) = *(const uint4*)(Qhg + (size_t)r * Eq + g * 8);
            *(uint4*)(smg + OFF_QL + dst) = *(const uint4*)(Qlg + (size_t)r * Eq + g * 8);
        }
    }
    if (t < 64) { rm[t] = -1e30f; rl[t] = 0.f; }

    // warp tiling: QK: wm (16 q) x wn (32 k); PV: wm (16 q) x wn (64 ch)
    int wm = wid & 3, wn = wid >> 2;
    uint32_t a_off = swoff(wm * 16 + (lane & 15), lane >> 4);
    uint32_t bk_off[4], bv_off[8];
#pragma unroll
    for (int ni = 0; ni < 4; ni++)
        bk_off[ni] = swoff(wn * 32 + ni * 8 + (lane & 7), (lane >> 3) & 1);
#pragma unroll
    for (int ni = 0; ni < 8; ni++)
        bv_off[ni] = swoff(wn * 64 + ni * 8 + (lane & 7), (lane >> 3) & 1);

    int g4 = lane >> 2, tg = lane & 3;
    int row0 = wm * 16 + g4, row1 = row0 + 8;
    int sr = t >> 2, sq = t & 3;   // softmax mapping: row sr, col-quarter sq
    const float SCALE = 0.08838834764831845f;

    float co[8][4];
#pragma unroll
    for (int i = 0; i < 8; i++)
#pragma unroll
        for (int j = 0; j < 4; j++) co[i][j] = 0.f;

    __syncthreads();

    for (int kt = 0; kt < Lq / 64; ++kt) {
        // ---- load K tile (64 keys x 128) hi/lo ----
        {
            const __nv_bfloat16* Khg = Kh + ((size_t)(b * Lq + kt * 64)) * Eq + h * Dq;
            const __nv_bfloat16* Klg = Kl + ((size_t)(b * Lq + kt * 64)) * Eq + h * Dq;
#pragma unroll
            for (int i = 0; i < 4; i++) {
                int idx = t + i * 256;
                int r = idx >> 4, g = idx & 15;
                int chunk = g >> 2, gc = g & 3;
                uint32_t dst = chunk * 4096 + swoff(r, gc);
                *(uint4*)(smg + OFF_KH + dst) = *(const uint4*)(Khg + (size_t)r * Eq + g * 8);
                *(uint4*)(smg + OFF_KL + dst) = *(const uint4*)(Klg + (size_t)r * Eq + g * 8);
            }
        }
        __syncthreads();

        // ---- S = Qh.Kh + Qh.Kl + Ql.Kh ----
        float cs[4][4];
#pragma unroll
        for (int i = 0; i < 4; i++)
#pragma unroll
            for (int j = 0; j < 4; j++) cs[i][j] = 0.f;
        {
            const uint32_t Ab[3] = {sb + OFF_QH, sb + OFF_QH, sb + OFF_QL};
            const uint32_t Bb[3] = {sb + OFF_KH, sb + OFF_KL, sb + OFF_KH};
#pragma unroll
            for (int p = 0; p < 3; p++)
#pragma unroll
                for (int ch = 0; ch < 4; ch++)
#pragma unroll
                    for (int ks = 0; ks < 2; ks++) {
                        uint32_t a[4];
                        ldmx4(a, Ab[p] + ch * 4096 + (a_off ^ (ks * 32)));
#pragma unroll
                        for (int ni = 0; ni < 4; ni++) {
                            uint32_t bf[2];
                            ldmx2(bf, Bb[p] + ch * 4096 + (bk_off[ni] ^ (ks * 32)));
                            mma16816(cs[ni], a, bf);
                        }
                    }
        }
#pragma unroll
        for (int ni = 0; ni < 4; ni++) {
            int c = wn * 32 + ni * 8 + tg * 2;
            float2 v0, v1;
            v0.x = cs[ni][0] * SCALE; v0.y = cs[ni][1] * SCALE;
            v1.x = cs[ni][2] * SCALE; v1.y = cs[ni][3] * SCALE;
            *(float2*)&Ss[row0 * 66 + c] = v0;
            *(float2*)&Ss[row1 * 66 + c] = v1;
        }
        __syncthreads();

        // ---- softmax: partial max ----
        {
            float mx = -1e30f;
#pragma unroll
            for (int j = 0; j < 16; j++) mx = fmaxf(mx, Ss[sr * 66 + sq * 16 + j]);
            Sp[sr * 4 + sq] = mx;
        }
        __syncthreads();
        if (t < 64) {
            float mo = rm[t];
            float mn = fmaxf(fmaxf(fmaxf(Sp[t * 4], Sp[t * 4 + 1]),
                                   fmaxf(Sp[t * 4 + 2], Sp[t * 4 + 3])), mo);
            rm[t] = mn;
            ra[t] = __expf(mo - mn);
        }
        __syncthreads();

        // ---- exp + write P hi/lo + partial sums ----
        {
            float m = rm[sr];
            float ps = 0.f;
#pragma unroll
            for (int j = 0; j < 16; j++) {
                int col = sq * 16 + j;
                float e = __expf(Ss[sr * 66 + col] - m);
                ps += e;
                __nv_bfloat16 eh = __float2bfloat16(e);
                __nv_bfloat16 el = __float2bfloat16(e - __bfloat162float(eh));
                int chunk = col >> 5, wc = col & 31;
                uint32_t adr = chunk * 4096 + swoff(sr, wc >> 3) + (wc & 7) * 2;
                *(__nv_bfloat16*)(smg + OFF_PH + adr) = eh;
                *(__nv_bfloat16*)(smg + OFF_PL + adr) = el;
            }
            Sp[sr * 4 + sq] = ps;
        }
        __syncthreads();

        if (t < 64)
            rl[t] = rl[t] * ra[t] + (Sp[t * 4] + Sp[t * 4 + 1] + Sp[t * 4 + 2] + Sp[t * 4 + 3]);

        // ---- load V^T tile (128 ch x 64 keys) hi/lo into K buffer ----
        {
            const __nv_bfloat16* Vhg = Vth + ((size_t)((b * Hq + h) * Dq)) * Lq + kt * 64;
            const __nv_bfloat16* Vlg = Vtl + ((size_t)((b * Hq + h) * Dq)) * Lq + kt * 64;
#pragma unroll
            for (int i = 0; i < 4; i++) {
                int idx = t + i * 256;
                int r = idx >> 3, g = idx & 7;
                int chunk = g >> 2, gc = g & 3;
                uint32_t dst = chunk * 8192 + swoff(r, gc);
                *(uint4*)(smg + OFF_VH + dst) = *(const uint4*)(Vhg + (size_t)r * Lq + g * 8);
                *(uint4*)(smg + OFF_VL + dst) = *(const uint4*)(Vlg + (size_t)r * Lq + g * 8);
            }
        }
        __syncthreads();

        // ---- rescale O, then O += Ph.Vh + Ph.Vl + Pl.Vh ----
        {
            float al0 = ra[row0], al1 = ra[row1];
#pragma unroll
            for (int ni = 0; ni < 8; ni++) {
                co[ni][0] *= al0; co[ni][1] *= al0;
                co[ni][2] *= al1; co[ni][3] *= al1;
            }
            const uint32_t Ab[3] = {sb + OFF_PH, sb + OFF_PH, sb + OFF_PL};
            const uint32_t Bb[3] = {sb + OFF_VH, sb + OFF_VL, sb + OFF_VH};
#pragma unroll
            for (int p = 0; p < 3; p++)
#pragma unroll
                for (int ch = 0; ch < 2; ch++)
#pragma unroll
                    for (int ks = 0; ks < 2; ks++) {
                        uint32_t a[4];
                        ldmx4(a, Ab[p] + ch * 4096 + (a_off ^ (ks * 32)));
#pragma unroll
                        for (int ni = 0; ni < 8; ni++) {
                            uint32_t bf[2];
                            ldmx2(bf, Bb[p] + ch * 8192 + (bv_off[ni] ^ (ks * 32)));
                            mma16816(co[ni], a, bf);
                        }
                    }
        }
        __syncthreads();
    }

    // ---- epilogue: write O split [hi|hi|lo] into out-proj A buffer ----
    float il0 = 1.0f / rl[row0], il1 = 1.0f / rl[row1];
    __nv_bfloat16* O0 = O3 + ((size_t)(b * Sq + qb + row0)) * (3 * Eq) + h * Dq;
    __nv_bfloat16* O1 = O3 + ((size_t)(b * Sq + qb + row1)) * (3 * Eq) + h * Dq;
#pragma unroll
    for (int ni = 0; ni < 8; ni++) {
        int col = wn * 64 + ni * 8 + tg * 2;
        float x0 = co[ni][0] * il0, x1 = co[ni][1] * il0;
        float y0 = co[ni][2] * il1, y1 = co[ni][3] * il1;
        __nv_bfloat162 h0, l0, h1, l1;
        h0.x = __float2bfloat16(x0); h0.y = __float2bfloat16(x1);
        l0.x = __float2bfloat16(x0 - __bfloat162float(h0.x));
        l0.y = __float2bfloat16(x1 - __bfloat162float(h0.y));
        h1.x = __float2bfloat16(y0); h1.y = __float2bfloat16(y1);
        l1.x = __float2bfloat16(y0 - __bfloat162float(h1.x));
        l1.y = __float2bfloat16(y1 - __bfloat162float(h1.y));
        *(__nv_bfloat162*)(O0 + col) = h0;
        *(__nv_bfloat162*)(O0 + Eq + col) = h0;
        *(__nv_bfloat162*)(O0 + 2 * Eq + col) = l0;
        *(__nv_bfloat162*)(O1 + col) = h1;
        *(__nv_bfloat162*)(O1 + Eq + col) = h1;
        *(__nv_bfloat162*)(O1 + 2 * Eq + col) = l1;
    }
}

// ---------------- host launcher ----------------
extern "C" void kernel_launch(void* const* d_in, const int* in_sizes, int n_in,
                              void* d_out, int out_size) {
    const float* x  = (const float*)d_in[0];
    const float* rt = (const float*)d_in[1];
    const float* qw = (const float*)d_in[2];
    const float* kw = (const float*)d_in[3];
    const float* vw = (const float*)d_in[4];
    const float* ow = (const float*)d_in[5];
    const float* ob = (const float*)d_in[6];
    float* out = (float*)d_out;

    __nv_bfloat16 *xbf, *wbf, *rt3, *kw3, *vw3, *ow3, *ao3, *qh, *ql, *kh, *kl, *vth, *vtl;
    float *rows, *qb, *kb, *vb, *part, *scale;
    cudaGetSymbolAddress((void**)&xbf, g_xbf);
    cudaGetSymbolAddress((void**)&wbf, g_wbf);
    cudaGetSymbolAddress((void**)&rt3, g_rt3);
    cudaGetSymbolAddress((void**)&kw3, g_kw3);
    cudaGetSymbolAddress((void**)&vw3, g_vw3);
    cudaGetSymbolAddress((void**)&ow3, g_ow3);
    cudaGetSymbolAddress((void**)&ao3, g_ao3);
    cudaGetSymbolAddress((void**)&qh, g_qh);
    cudaGetSymbolAddress((void**)&ql, g_ql);
    cudaGetSymbolAddress((void**)&kh, g_kh);
    cudaGetSymbolAddress((void**)&kl, g_kl);
    cudaGetSymbolAddress((void**)&vth, g_vth);
    cudaGetSymbolAddress((void**)&vtl, g_vtl);
    cudaGetSymbolAddress((void**)&rows, g_rows);
    cudaGetSymbolAddress((void**)&qb, g_qb);
    cudaGetSymbolAddress((void**)&kb, g_kb);
    cudaGetSymbolAddress((void**)&vb, g_vb);
    cudaGetSymbolAddress((void**)&part, g_part);
    cudaGetSymbolAddress((void**)&scale, g_scale);

    cudaFuncSetAttribute(attn_mma, cudaFuncAttributeMaxDynamicSharedMemorySize, SMEM_ATTN2);

    // 1) weight scales
    reduce_abs_kernel<<<dim3(1024, 3), 256>>>(qw, kw, vw, part);
    finalize_scale_kernel<<<3, 256>>>(part, scale);
    // 2) quantize to bf16 (exact integer/ternary values)
    quant_weight_bf16<<<dim3(2048, 3), 256>>>(qw, kw, vw, wbf, scale);
    quant_act_bf16<<<Bq * Sq, 256>>>(x, xbf, rows);
    // 3) split unquantized operands (K-tripled bf16)
    split3<<<(Eq * Eq) / 256, 256>>>(kw, kw3, 1);
    split3<<<(Eq * Eq) / 256, 256>>>(vw, vw3, 1);
    split3<<<(Eq * Eq) / 256, 256>>>(ow, ow3, 1);
    split3<<<(Bq * Rq * Eq) / 256, 256>>>(rt, rt3, 0);
    // 4) quantized projections: exact bf16-int HMMA GEMM + dequant epilogue
    size_t EE = (size_t)Eq * Eq;
    hmma_gemm<<<dim3(16, 32), 256>>>(xbf, wbf + 0 * EE, qb, rows, scale + 0, nullptr,
                                     Eq, Eq, Sq, Sq, 0);
    hmma_gemm<<<dim3(16, 32), 256>>>(xbf, wbf + 1 * EE, kb, rows, scale + 1, nullptr,
                                     Eq, Eq, Sq, Lq, 0);
    hmma_gemm<<<dim3(16, 32), 256>>>(xbf, wbf + 2 * EE, vb, rows, scale + 2, nullptr,
                                     Eq, Eq, Sq, Lq, 0);
    // 5) reasoning projections: split-bf16 (K=6144), appended after S self rows
    hmma_gemm<<<dim3(16, 2), 256>>>(rt3, kw3, kb, nullptr, nullptr, nullptr,
                                    3 * Eq, Eq, Rq, Lq, Sq);
    hmma_gemm<<<dim3(16, 2), 256>>>(rt3, vw3, vb, nullptr, nullptr, nullptr,
                                    3 * Eq, Eq, Rq, Lq, Sq);
    // 6) split Q/K into hi/lo, transpose+split V
    split_hl<<<(Bq * Sq * Eq) / 1024, 256>>>(qb, qh, ql);
    split_hl<<<(Bq * Lq * Eq) / 1024, 256>>>(kb, kh, kl);
    transpose_v<<<dim3(Lq / 32, Eq / 32, Bq), 256>>>(vb, vth, vtl);
    // 7) attention (HMMA, split-bf16 exact) -> writes [hi|hi|lo] out-proj input
    attn_mma<<<dim3(Sq / 64, Hq, Bq), 256, SMEM_ATTN2>>>(qh, ql, kh, kl, vth, vtl, ao3);
    // 8) output projection + bias
    hmma_gemm<<<dim3(16, 32), 256>>>(ao3, ow3, out, nullptr, nullptr, ob,
                                     3 * Eq, Eq, Bq * Sq, Bq * Sq, 0);
}

// round 6
// speedup vs baseline: 7.6567x; 1.2263x over previous
#include <cuda_runtime.h>
#include <cuda_bf16.h>
#include <cstdint>

#define Bq 2
#define Sq 2048
#define Rq 128
#define Eq 2048
#define Hq 16
#define Dq 128
#define Lq (Sq + Rq)   // 2176

// ---------------- scratch (device globals, no allocations) ----------------
__device__ __nv_bfloat16 g_xbf[(size_t)Bq * Sq * Eq];      // quantized acts as bf16 ints
__device__ __nv_bfloat16 g_wbf[3][(size_t)Eq * Eq];        // ternary weights as bf16
__device__ __nv_bfloat16 g_rt3[(size_t)Bq * Rq * 3 * Eq];  // reasoning tokens split [hi|hi|lo]
__device__ __nv_bfloat16 g_kw3[(size_t)Eq * 3 * Eq];       // k_w split [hi|lo|hi]
__device__ __nv_bfloat16 g_vw3[(size_t)Eq * 3 * Eq];       // v_w split
__device__ __nv_bfloat16 g_ow3[(size_t)Eq * 3 * Eq];       // out_w split
__device__ __nv_bfloat16 g_ao3[(size_t)Bq * Sq * 3 * Eq];  // attn out split [hi|hi|lo]
__device__ __nv_bfloat16 g_qh[(size_t)Bq * Sq * Eq];       // Q hi
__device__ __nv_bfloat16 g_ql[(size_t)Bq * Sq * Eq];       // Q lo
__device__ __nv_bfloat16 g_kh[(size_t)Bq * Lq * Eq];       // K hi
__device__ __nv_bfloat16 g_kl[(size_t)Bq * Lq * Eq];       // K lo
__device__ __nv_bfloat16 g_vth[(size_t)Bq * Hq * Dq * Lq]; // V^T hi [B,H,D,L]
__device__ __nv_bfloat16 g_vtl[(size_t)Bq * Hq * Dq * Lq]; // V^T lo
__device__ float g_rows[(size_t)Bq * Sq];                  // per-row act scale s
__device__ float g_vb[(size_t)Bq * Lq * Eq];               // V fp32
__device__ float g_part[3 * 1024];
__device__ float g_scale[3];

// ---------------- PTX helpers ----------------
typedef unsigned long long ull;
__device__ __forceinline__ uint32_t smem_u32(const void* p) {
    uint32_t a;
    asm("{ .reg .u64 t; cvta.to.shared.u64 t, %1; cvt.u32.u64 %0, t; }" : "=r"(a) : "l"(p));
    return a;
}
__device__ __forceinline__ void ldmx4(uint32_t* r, uint32_t addr) {
    asm volatile("ldmatrix.sync.aligned.m8n8.x4.shared.b16 {%0,%1,%2,%3}, [%4];"
                 : "=r"(r[0]), "=r"(r[1]), "=r"(r[2]), "=r"(r[3]) : "r"(addr));
}
__device__ __forceinline__ void ldmx2(uint32_t* r, uint32_t addr) {
    asm volatile("ldmatrix.sync.aligned.m8n8.x2.shared.b16 {%0,%1}, [%2];"
                 : "=r"(r[0]), "=r"(r[1]) : "r"(addr));
}
__device__ __forceinline__ void mma16816(float* c, const uint32_t* a, const uint32_t* b) {
    asm volatile("mma.sync.aligned.m16n8k16.row.col.f32.bf16.bf16.f32 "
                 "{%0,%1,%2,%3}, {%4,%5,%6,%7}, {%8,%9}, {%0,%1,%2,%3};"
                 : "+f"(c[0]), "+f"(c[1]), "+f"(c[2]), "+f"(c[3])
                 : "r"(a[0]), "r"(a[1]), "r"(a[2]), "r"(a[3]), "r"(b[0]), "r"(b[1]));
}
// smem rows of 32 bf16 (64B); 16B group g stored at g ^ ((row>>1)&3)
__device__ __forceinline__ uint32_t swoff(int r, int g) {
    return (uint32_t)(r * 64 + ((g ^ ((r >> 1) & 3)) << 4));
}
// pack two fp32 into bf16x2 hi + residual lo
__device__ __forceinline__ void hl2(float x, float y, uint32_t& h, uint32_t& l) {
    __nv_bfloat162 hh, ll;
    hh.x = __float2bfloat16(x);
    hh.y = __float2bfloat16(y);
    ll.x = __float2bfloat16(x - __bfloat162float(hh.x));
    ll.y = __float2bfloat16(y - __bfloat162float(hh.y));
    h = *(uint32_t*)&hh;
    l = *(uint32_t*)&ll;
}

// ---------------- weight mean(|w|) : stage 1 ----------------
__global__ void reduce_abs_kernel(const float* __restrict__ w0, const float* __restrict__ w1,
                                  const float* __restrict__ w2, float* __restrict__ part) {
    const float* w = (blockIdx.y == 0) ? w0 : ((blockIdx.y == 1) ? w1 : w2);
    int t = threadIdx.x;
    size_t base = (size_t)blockIdx.x * 4096;
    float s = 0.f;
#pragma unroll
    for (int i = 0; i < 16; i++) s += fabsf(w[base + t + i * 256]);
    __shared__ float red[256];
    red[t] = s;
    __syncthreads();
    for (int o = 128; o > 0; o >>= 1) {
        if (t < o) red[t] += red[t + o];
        __syncthreads();
    }
    if (t == 0) part[blockIdx.y * 1024 + blockIdx.x] = red[0];
}

__global__ void finalize_scale_kernel(const float* __restrict__ part, float* __restrict__ scale) {
    int w = blockIdx.x;
    int t = threadIdx.x;
    float s = part[w * 1024 + t] + part[w * 1024 + t + 256] +
              part[w * 1024 + t + 512] + part[w * 1024 + t + 768];
    __shared__ float red[256];
    red[t] = s;
    __syncthreads();
    for (int o = 128; o > 0; o >>= 1) {
        if (t < o) red[t] += red[t + o];
        __syncthreads();
    }
    if (t == 0) {
        float mean = red[0] * (1.0f / ((float)Eq * (float)Eq));
        scale[w] = fmaxf(mean, 1e-5f);
    }
}

// ---------------- ternary weight quantization -> bf16 {-1,0,1} ----------------
__global__ void quant_weight_bf16(const float* __restrict__ w0, const float* __restrict__ w1,
                                  const float* __restrict__ w2, __nv_bfloat16* __restrict__ wq,
                                  const float* __restrict__ scale) {
    int wi = blockIdx.y;
    const float* w = (wi == 0) ? w0 : ((wi == 1) ? w1 : w2);
    float inv = __frcp_rn(scale[wi]);
    size_t e0 = ((size_t)blockIdx.x * 256 + threadIdx.x) * 8;
    __nv_bfloat16* wo = wq + (size_t)wi * Eq * Eq + e0;
#pragma unroll
    for (int i = 0; i < 8; i += 4) {
        float4 v = *(const float4*)&w[e0 + i];
        wo[i + 0] = __float2bfloat16(fminf(fmaxf(rintf(v.x * inv), -1.f), 1.f));
        wo[i + 1] = __float2bfloat16(fminf(fmaxf(rintf(v.y * inv), -1.f), 1.f));
        wo[i + 2] = __float2bfloat16(fminf(fmaxf(rintf(v.z * inv), -1.f), 1.f));
        wo[i + 3] = __float2bfloat16(fminf(fmaxf(rintf(v.w * inv), -1.f), 1.f));
    }
}

// ---------------- per-token absmax quantization -> bf16 integers + row scale ----------------
__global__ void quant_act_bf16(const float* __restrict__ x, __nv_bfloat16* __restrict__ xq,
                               float* __restrict__ rows) {
    int row = blockIdx.x;
    int t = threadIdx.x;
    const float* xr = x + (size_t)row * Eq;
    float4 v0 = *(const float4*)&xr[t * 8];
    float4 v1 = *(const float4*)&xr[t * 8 + 4];
    float mx = fmaxf(fmaxf(fmaxf(fabsf(v0.x), fabsf(v0.y)), fmaxf(fabsf(v0.z), fabsf(v0.w))),
                     fmaxf(fmaxf(fabsf(v1.x), fabsf(v1.y)), fmaxf(fabsf(v1.z), fabsf(v1.w))));
    __shared__ float red[256];
    red[t] = mx;
    __syncthreads();
    for (int o = 128; o > 0; o >>= 1) {
        if (t < o) red[t] = fmaxf(red[t], red[t + o]);
        __syncthreads();
    }
    float s = __fdiv_rn(127.0f, fmaxf(red[0], 1e-5f));
    if (t == 0) rows[row] = s;
    __nv_bfloat16* xo = xq + (size_t)row * Eq + t * 8;
    xo[0] = __float2bfloat16(fminf(fmaxf(rintf(v0.x * s), -128.f), 127.f));
    xo[1] = __float2bfloat16(fminf(fmaxf(rintf(v0.y * s), -128.f), 127.f));
    xo[2] = __float2bfloat16(fminf(fmaxf(rintf(v0.z * s), -128.f), 127.f));
    xo[3] = __float2bfloat16(fminf(fmaxf(rintf(v0.w * s), -128.f), 127.f));
    xo[4] = __float2bfloat16(fminf(fmaxf(rintf(v1.x * s), -128.f), 127.f));
    xo[5] = __float2bfloat16(fminf(fmaxf(rintf(v1.y * s), -128.f), 127.f));
    xo[6] = __float2bfloat16(fminf(fmaxf(rintf(v1.z * s), -128.f), 127.f));
    xo[7] = __float2bfloat16(fminf(fmaxf(rintf(v1.w * s), -128.f), 127.f));
}

// ---------------- fp32 -> split-bf16 K-tripling (row length 2048) ----------------
// mode 0 (A side): [hi | hi | lo]    mode 1 (B side): [hi | lo | hi]
__global__ void split3(const float* __restrict__ X, __nv_bfloat16* __restrict__ Y, int mode) {
    size_t i = (size_t)blockIdx.x * 256 + threadIdx.x;
    size_t row = i >> 11, col = i & 2047;
    float x = X[i];
    __nv_bfloat16 hi = __float2bfloat16(x);
    __nv_bfloat16 lo = __float2bfloat16(x - __bfloat162float(hi));
    __nv_bfloat16* yr = Y + row * (size_t)(3 * Eq);
    yr[col] = hi;
    yr[Eq + col] = mode ? lo : hi;
    yr[2 * Eq + col] = mode ? hi : lo;
}

// ---------------- V fp32 [B,L,E] -> V^T hi/lo [B,H,D,L] ----------------
__global__ void transpose_v(const float* __restrict__ V, __nv_bfloat16* __restrict__ Th,
                            __nv_bfloat16* __restrict__ Tl) {
    __shared__ float s[32][33];
    int l0 = blockIdx.x * 32;
    int e0 = blockIdx.y * 32;
    int b = blockIdx.z;
    int t = threadIdx.x;
    int h = e0 >> 7, d0 = e0 & 127;
#pragma unroll
    for (int i = 0; i < 4; i++) {
        int idx = t + i * 256;
        int lr = idx >> 5, lc = idx & 31;
        s[lr][lc] = V[((size_t)(b * Lq + l0 + lr)) * Eq + e0 + lc];
    }
    __syncthreads();
#pragma unroll
    for (int i = 0; i < 4; i++) {
        int idx = t + i * 256;
        int dr = idx >> 5, dc = idx & 31;
        float f = s[dc][dr];
        __nv_bfloat16 hi = __float2bfloat16(f);
        __nv_bfloat16 lo = __float2bfloat16(f - __bfloat162float(hi));
        size_t o = ((size_t)((b * Hq + h) * Dq + d0 + dr)) * Lq + l0 + dc;
        Th[o] = hi;
        Tl[o] = lo;
    }
}

// ---------------- HMMA bf16 GEMM with optional split-bf16 output ----------------
// C fp32 (if Hout==null) or Hout/Lout bf16 hi/lo (if Hout!=null).
__global__ __launch_bounds__(256) void hmma_gemm(
    const __nv_bfloat16* __restrict__ A, const __nv_bfloat16* __restrict__ B,
    float* __restrict__ C, const float* __restrict__ rowscale,
    const float* __restrict__ wsp, const float* __restrict__ bias,
    int K, int Nout, int rbi, int rbo, int roff,
    __nv_bfloat16* __restrict__ Hout, __nv_bfloat16* __restrict__ Lout) {
    __shared__ __align__(128) uint8_t sA[2][8192];
    __shared__ __align__(128) uint8_t sB[2][8192];
    int t = threadIdx.x;
    int lane = t & 31, wid = t >> 5;
    int m0 = blockIdx.y * 128, n0 = blockIdx.x * 128;
    int warp_m = wid & 1, warp_n = wid >> 1;

    int r0 = t >> 2, g0 = t & 3;
    int r1 = 64 + r0;
    const uint4* Ag0 = (const uint4*)(A + (size_t)(m0 + r0) * K) + g0;
    const uint4* Ag1 = (const uint4*)(A + (size_t)(m0 + r1) * K) + g0;
    const uint4* Bg0 = (const uint4*)(B + (size_t)(n0 + r0) * K) + g0;
    const uint4* Bg1 = (const uint4*)(B + (size_t)(n0 + r1) * K) + g0;
    uint32_t st0 = swoff(r0, g0), st1 = swoff(r1, g0);

    uint32_t sAu = smem_u32(sA), sBu = smem_u32(sB);

    uint32_t aaddr[4], baddr[4];
#pragma unroll
    for (int mi = 0; mi < 4; mi++) {
        int r = warp_m * 64 + mi * 16 + (lane & 15);
        int g = lane >> 4;
        aaddr[mi] = sAu + swoff(r, g);
    }
#pragma unroll
    for (int ni = 0; ni < 4; ni++) {
        int r = warp_n * 32 + ni * 8 + (lane & 7);
        int g = (lane >> 3) & 1;
        baddr[ni] = sBu + swoff(r, g);
    }

    uint4 pa0 = Ag0[0], pa1 = Ag1[0], pb0 = Bg0[0], pb1 = Bg1[0];
    *(uint4*)(sA[0] + st0) = pa0;
    *(uint4*)(sA[0] + st1) = pa1;
    *(uint4*)(sB[0] + st0) = pb0;
    *(uint4*)(sB[0] + st1) = pb1;
    __syncthreads();

    float c[4][4][4];
#pragma unroll
    for (int mi = 0; mi < 4; mi++)
#pragma unroll
        for (int ni = 0; ni < 4; ni++)
#pragma unroll
            for (int k = 0; k < 4; k++) c[mi][ni][k] = 0.f;

    const int NK = K >> 5;
    for (int kt = 0; kt < NK; ++kt) {
        int buf = kt & 1;
        if (kt + 1 < NK) {
            pa0 = Ag0[(kt + 1) * 4];
            pa1 = Ag1[(kt + 1) * 4];
            pb0 = Bg0[(kt + 1) * 4];
            pb1 = Bg1[(kt + 1) * 4];
        }
        uint32_t bofs = buf * 8192;
#pragma unroll
        for (int ks = 0; ks < 2; ks++) {
            uint32_t kx = ks * 32;
            uint32_t a[4][4], b[4][2];
#pragma unroll
            for (int mi = 0; mi < 4; mi++) ldmx4(a[mi], (aaddr[mi] + bofs) ^ kx);
#pragma unroll
            for (int ni = 0; ni < 4; ni++) ldmx2(b[ni], (baddr[ni] + bofs) ^ kx);
#pragma unroll
            for (int mi = 0; mi < 4; mi++)
#pragma unroll
                for (int ni = 0; ni < 4; ni++) mma16816(c[mi][ni], a[mi], b[ni]);
        }
        if (kt + 1 < NK) {
            int nb = buf ^ 1;
            *(uint4*)(sA[nb] + st0) = pa0;
            *(uint4*)(sA[nb] + st1) = pa1;
            *(uint4*)(sB[nb] + st0) = pb0;
            *(uint4*)(sB[nb] + st1) = pb1;
        }
        __syncthreads();
    }

    float ws = wsp ? *wsp : 1.0f;
    int g = lane >> 2, tg = lane & 3;
#pragma unroll
    for (int mi = 0; mi < 4; mi++) {
        int mA = m0 + warp_m * 64 + mi * 16 + g;
        int mB = mA + 8;
        float fA = rowscale ? (ws / rowscale[mA]) : 1.0f;
        float fB = rowscale ? (ws / rowscale[mB]) : 1.0f;
        int oA = (mA / rbi) * rbo + roff + (mA % rbi);
        int oB = (mB / rbi) * rbo + roff + (mB % rbi);
        if (Hout) {
            __nv_bfloat16* hA = Hout + (size_t)oA * Nout;
            __nv_bfloat16* hB = Hout + (size_t)oB * Nout;
            __nv_bfloat16* lA = Lout + (size_t)oA * Nout;
            __nv_bfloat16* lB = Lout + (size_t)oB * Nout;
#pragma unroll
            for (int ni = 0; ni < 4; ni++) {
                int col = n0 + warp_n * 32 + ni * 8 + tg * 2;
                uint32_t h0, l0v, h1, l1v;
                hl2(c[mi][ni][0] * fA, c[mi][ni][1] * fA, h0, l0v);
                hl2(c[mi][ni][2] * fB, c[mi][ni][3] * fB, h1, l1v);
                *(uint32_t*)&hA[col] = h0;
                *(uint32_t*)&lA[col] = l0v;
                *(uint32_t*)&hB[col] = h1;
                *(uint32_t*)&lB[col] = l1v;
            }
        } else {
            float* crA = C + (size_t)oA * Nout;
            float* crB = C + (size_t)oB * Nout;
#pragma unroll
            for (int ni = 0; ni < 4; ni++) {
                int col = n0 + warp_n * 32 + ni * 8 + tg * 2;
                float b0 = 0.f, b1 = 0.f;
                if (bias) { b0 = bias[col]; b1 = bias[col + 1]; }
                float2 vA, vB;
                vA.x = c[mi][ni][0] * fA + b0;
                vA.y = c[mi][ni][1] * fA + b1;
                vB.x = c[mi][ni][2] * fB + b0;
                vB.y = c[mi][ni][3] * fB + b1;
                *(float2*)&crA[col] = vA;
                *(float2*)&crB[col] = vB;
            }
        }
    }
}

// ---------------- FA2-style HMMA flash attention (split-bf16 exact) ----------------
// 128 q per CTA, 8 warps x 16 q-rows. K-tile = 64 keys. P register-resident.
#define AOFF_QH 0
#define AOFF_QL 32768
#define AOFF_KH 65536   // shared with V^T hi
#define AOFF_KL 81920   // shared with V^T lo
#define SMEM_ATTN3 98304

__global__ __launch_bounds__(256, 1) void attn_mma2(
    const __nv_bfloat16* __restrict__ Qh, const __nv_bfloat16* __restrict__ Ql,
    const __nv_bfloat16* __restrict__ Kh, const __nv_bfloat16* __restrict__ Kl,
    const __nv_bfloat16* __restrict__ Vth, const __nv_bfloat16* __restrict__ Vtl,
    __nv_bfloat16* __restrict__ O3) {
    extern __shared__ char smg[];
    uint32_t sb = smem_u32(smg);
    int t = threadIdx.x;
    int lane = t & 31, wid = t >> 5;
    int qb = blockIdx.x * 128;
    int h = blockIdx.y;
    int b = blockIdx.z;

    // ---- load Q hi/lo: 128 rows x 128 cols ----
    {
        const __nv_bfloat16* Qhg = Qh + ((size_t)(b * Sq + qb)) * Eq + h * Dq;
        const __nv_bfloat16* Qlg = Ql + ((size_t)(b * Sq + qb)) * Eq + h * Dq;
#pragma unroll
        for (int i = 0; i < 8; i++) {
            int idx = t + i * 256;
            int r = idx >> 4, g = idx & 15;
            uint32_t dst = (g >> 2) * 8192 + swoff(r, g & 3);
            *(uint4*)(smg + AOFF_QH + dst) = *(const uint4*)(Qhg + (size_t)r * Eq + g * 8);
            *(uint4*)(smg + AOFF_QL + dst) = *(const uint4*)(Qlg + (size_t)r * Eq + g * 8);
        }
    }

    const int wm = wid;                       // warp owns q rows [wm*16, wm*16+16)
    const uint32_t a_off = swoff(wm * 16 + (lane & 15), lane >> 4);
    const uint32_t bo = swoff(lane & 7, (lane >> 3) & 1);   // + ni*512 for frag ni
    const int g4 = lane >> 2, tg = lane & 3;
    const float SCALE = 0.08838834764831845f;  // 1/sqrt(128)

    float m0 = -1e30f, m1 = -1e30f, l0 = 0.f, l1 = 0.f;
    float co[16][4];
#pragma unroll
    for (int i = 0; i < 16; i++)
#pragma unroll
        for (int j = 0; j < 4; j++) co[i][j] = 0.f;

    __syncthreads();

    for (int kt = 0; kt < Lq / 64; ++kt) {
        // ---- load K tile (64 keys x 128 d) hi/lo ----
        {
            const __nv_bfloat16* Khg = Kh + ((size_t)(b * Lq + kt * 64)) * Eq + h * Dq;
            const __nv_bfloat16* Klg = Kl + ((size_t)(b * Lq + kt * 64)) * Eq + h * Dq;
#pragma unroll
            for (int i = 0; i < 4; i++) {
                int idx = t + i * 256;
                int r = idx >> 4, g = idx & 15;
                uint32_t dst = (g >> 2) * 4096 + swoff(r, g & 3);
                *(uint4*)(smg + AOFF_KH + dst) = *(const uint4*)(Khg + (size_t)r * Eq + g * 8);
                *(uint4*)(smg + AOFF_KL + dst) = *(const uint4*)(Klg + (size_t)r * Eq + g * 8);
            }
        }
        __syncthreads();

        // ---- S = Qh.Kh + Qh.Kl + Ql.Kh : 16q x 64k per warp ----
        float cs[8][4];
#pragma unroll
        for (int i = 0; i < 8; i++)
#pragma unroll
            for (int j = 0; j < 4; j++) cs[i][j] = 0.f;
#pragma unroll
        for (int ch = 0; ch < 4; ch++)
#pragma unroll
            for (int ks = 0; ks < 2; ks++) {
                uint32_t kx = ks * 32;
                uint32_t ah[4], al[4];
                ldmx4(ah, sb + AOFF_QH + ch * 8192 + (a_off ^ kx));
                ldmx4(al, sb + AOFF_QL + ch * 8192 + (a_off ^ kx));
#pragma unroll
                for (int ni = 0; ni < 8; ni++) {
                    uint32_t bh[2], bl[2];
                    uint32_t ba = ch * 4096 + ((bo + ni * 512) ^ kx);
                    ldmx2(bh, sb + AOFF_KH + ba);
                    ldmx2(bl, sb + AOFF_KL + ba);
                    mma16816(cs[ni], ah, bh);
                    mma16816(cs[ni], ah, bl);
                    mma16816(cs[ni], al, bh);
                }
            }

        // ---- in-register softmax (row groups of 4 lanes) ----
        float tm0 = -1e30f, tm1 = -1e30f;
#pragma unroll
        for (int ni = 0; ni < 8; ni++) {
            cs[ni][0] *= SCALE; cs[ni][1] *= SCALE;
            cs[ni][2] *= SCALE; cs[ni][3] *= SCALE;
            tm0 = fmaxf(tm0, fmaxf(cs[ni][0], cs[ni][1]));
            tm1 = fmaxf(tm1, fmaxf(cs[ni][2], cs[ni][3]));
        }
        tm0 = fmaxf(tm0, __shfl_xor_sync(0xffffffffu, tm0, 1));
        tm0 = fmaxf(tm0, __shfl_xor_sync(0xffffffffu, tm0, 2));
        tm1 = fmaxf(tm1, __shfl_xor_sync(0xffffffffu, tm1, 1));
        tm1 = fmaxf(tm1, __shfl_xor_sync(0xffffffffu, tm1, 2));
        float nm0 = fmaxf(m0, tm0), nm1 = fmaxf(m1, tm1);
        float al0 = __expf(m0 - nm0), al1 = __expf(m1 - nm1);
        m0 = nm0; m1 = nm1;

        float rs0 = 0.f, rs1 = 0.f;
#pragma unroll
        for (int ni = 0; ni < 8; ni++) {
            cs[ni][0] = __expf(cs[ni][0] - m0); rs0 += cs[ni][0];
            cs[ni][1] = __expf(cs[ni][1] - m0); rs0 += cs[ni][1];
            cs[ni][2] = __expf(cs[ni][2] - m1); rs1 += cs[ni][2];
            cs[ni][3] = __expf(cs[ni][3] - m1); rs1 += cs[ni][3];
        }
        rs0 += __shfl_xor_sync(0xffffffffu, rs0, 1);
        rs0 += __shfl_xor_sync(0xffffffffu, rs0, 2);
        rs1 += __shfl_xor_sync(0xffffffffu, rs1, 1);
        rs1 += __shfl_xor_sync(0xffffffffu, rs1, 2);
        l0 = l0 * al0 + rs0;
        l1 = l1 * al1 + rs1;

        // ---- P hi/lo A-fragments, in registers ----
        uint32_t phf[4][4], plf[4][4];
#pragma unroll
        for (int ck = 0; ck < 4; ck++) {
            hl2(cs[2 * ck][0], cs[2 * ck][1], phf[ck][0], plf[ck][0]);
            hl2(cs[2 * ck][2], cs[2 * ck][3], phf[ck][1], plf[ck][1]);
            hl2(cs[2 * ck + 1][0], cs[2 * ck + 1][1], phf[ck][2], plf[ck][2]);
            hl2(cs[2 * ck + 1][2], cs[2 * ck + 1][3], phf[ck][3], plf[ck][3]);
        }

        // ---- rescale O ----
#pragma unroll
        for (int ni = 0; ni < 16; ni++) {
            co[ni][0] *= al0; co[ni][1] *= al0;
            co[ni][2] *= al1; co[ni][3] *= al1;
        }

        __syncthreads();   // all warps done reading K smem

        // ---- load V^T tile (128 ch x 64 keys) hi/lo into same buffer ----
        {
            const __nv_bfloat16* Vhg = Vth + ((size_t)((b * Hq + h) * Dq)) * Lq + kt * 64;
            const __nv_bfloat16* Vlg = Vtl + ((size_t)((b * Hq + h) * Dq)) * Lq + kt * 64;
#pragma unroll
            for (int i = 0; i < 4; i++) {
                int idx = t + i * 256;
                int r = idx >> 3, g = idx & 7;
                uint32_t dst = (g >> 2) * 8192 + swoff(r, g & 3);
                *(uint4*)(smg + AOFF_KH + dst) = *(const uint4*)(Vhg + (size_t)r * Lq + g * 8);
                *(uint4*)(smg + AOFF_KL + dst) = *(const uint4*)(Vlg + (size_t)r * Lq + g * 8);
            }
        }
        __syncthreads();

        // ---- O += Ph.Vh + Ph.Vl + Pl.Vh : 16q x 128ch per warp ----
#pragma unroll
        for (int ck = 0; ck < 4; ck++) {
#pragma unroll
            for (int ni = 0; ni < 16; ni++) {
                uint32_t bh[2], bl[2];
                uint32_t ba = (ck >> 1) * 8192 + ((bo + ni * 512) ^ ((ck & 1) * 32));
                ldmx2(bh, sb + AOFF_KH + ba);
                ldmx2(bl, sb + AOFF_KL + ba);
                mma16816(co[ni], phf[ck], bh);
                mma16816(co[ni], phf[ck], bl);
                mma16816(co[ni], plf[ck], bh);
            }
        }
        __syncthreads();   // all warps done reading V smem before next K load
    }

    // ---- epilogue: write O split [hi|hi|lo] into out-proj A buffer ----
    float il0 = 1.0f / l0, il1 = 1.0f / l1;
    int r0 = wm * 16 + g4, r1 = r0 + 8;
    __nv_bfloat16* O0 = O3 + ((size_t)(b * Sq + qb + r0)) * (3 * Eq) + h * Dq;
    __nv_bfloat16* O1 = O3 + ((size_t)(b * Sq + qb + r1)) * (3 * Eq) + h * Dq;
#pragma unroll
    for (int ni = 0; ni < 16; ni++) {
        int col = ni * 8 + tg * 2;
        uint32_t h0, lo0, h1, lo1;
        hl2(co[ni][0] * il0, co[ni][1] * il0, h0, lo0);
        hl2(co[ni][2] * il1, co[ni][3] * il1, h1, lo1);
        *(uint32_t*)(O0 + col) = h0;
        *(uint32_t*)(O0 + Eq + col) = h0;
        *(uint32_t*)(O0 + 2 * Eq + col) = lo0;
        *(uint32_t*)(O1 + col) = h1;
        *(uint32_t*)(O1 + Eq + col) = h1;
        *(uint32_t*)(O1 + 2 * Eq + col) = lo1;
    }
}

// ---------------- host launcher ----------------
extern "C" void kernel_launch(void* const* d_in, const int* in_sizes, int n_in,
                              void* d_out, int out_size) {
    const float* x  = (const float*)d_in[0];
    const float* rt = (const float*)d_in[1];
    const float* qw = (const float*)d_in[2];
    const float* kw = (const float*)d_in[3];
    const float* vw = (const float*)d_in[4];
    const float* ow = (const float*)d_in[5];
    const float* ob = (const float*)d_in[6];
    float* out = (float*)d_out;

    __nv_bfloat16 *xbf, *wbf, *rt3, *kw3, *vw3, *ow3, *ao3, *qh, *ql, *kh, *kl, *vth, *vtl;
    float *rows, *vb, *part, *scale;
    cudaGetSymbolAddress((void**)&xbf, g_xbf);
    cudaGetSymbolAddress((void**)&wbf, g_wbf);
    cudaGetSymbolAddress((void**)&rt3, g_rt3);
    cudaGetSymbolAddress((void**)&kw3, g_kw3);
    cudaGetSymbolAddress((void**)&vw3, g_vw3);
    cudaGetSymbolAddress((void**)&ow3, g_ow3);
    cudaGetSymbolAddress((void**)&ao3, g_ao3);
    cudaGetSymbolAddress((void**)&qh, g_qh);
    cudaGetSymbolAddress((void**)&ql, g_ql);
    cudaGetSymbolAddress((void**)&kh, g_kh);
    cudaGetSymbolAddress((void**)&kl, g_kl);
    cudaGetSymbolAddress((void**)&vth, g_vth);
    cudaGetSymbolAddress((void**)&vtl, g_vtl);
    cudaGetSymbolAddress((void**)&rows, g_rows);
    cudaGetSymbolAddress((void**)&vb, g_vb);
    cudaGetSymbolAddress((void**)&part, g_part);
    cudaGetSymbolAddress((void**)&scale, g_scale);

    cudaFuncSetAttribute(attn_mma2, cudaFuncAttributeMaxDynamicSharedMemorySize, SMEM_ATTN3);

    // 1) weight scales
    reduce_abs_kernel<<<dim3(1024, 3), 256>>>(qw, kw, vw, part);
    finalize_scale_kernel<<<3, 256>>>(part, scale);
    // 2) quantize to bf16 (exact integer/ternary values)
    quant_weight_bf16<<<dim3(2048, 3), 256>>>(qw, kw, vw, wbf, scale);
    quant_act_bf16<<<Bq * Sq, 256>>>(x, xbf, rows);
    // 3) split unquantized operands (K-tripled bf16)
    split3<<<(Eq * Eq) / 256, 256>>>(kw, kw3, 1);
    split3<<<(Eq * Eq) / 256, 256>>>(vw, vw3, 1);
    split3<<<(Eq * Eq) / 256, 256>>>(ow, ow3, 1);
    split3<<<(Bq * Rq * Eq) / 256, 256>>>(rt, rt3, 0);
    // 4) quantized projections (exact bf16-int HMMA); Q/K write hi/lo splits directly
    size_t EE = (size_t)Eq * Eq;
    hmma_gemm<<<dim3(16, 32), 256>>>(xbf, wbf + 0 * EE, nullptr, rows, scale + 0, nullptr,
                                     Eq, Eq, Sq, Sq, 0, qh, ql);
    hmma_gemm<<<dim3(16, 32), 256>>>(xbf, wbf + 1 * EE, nullptr, rows, scale + 1, nullptr,
                                     Eq, Eq, Sq, Lq, 0, kh, kl);
    hmma_gemm<<<dim3(16, 32), 256>>>(xbf, wbf + 2 * EE, vb, rows, scale + 2, nullptr,
                                     Eq, Eq, Sq, Lq, 0, nullptr, nullptr);
    // 5) reasoning projections: split-bf16 (K=6144), appended after S self rows
    hmma_gemm<<<dim3(16, 2), 256>>>(rt3, kw3, nullptr, nullptr, nullptr, nullptr,
                                    3 * Eq, Eq, Rq, Lq, Sq, kh, kl);
    hmma_gemm<<<dim3(16, 2), 256>>>(rt3, vw3, vb, nullptr, nullptr, nullptr,
                                    3 * Eq, Eq, Rq, Lq, Sq, nullptr, nullptr);
    // 6) transpose+split V
    transpose_v<<<dim3(Lq / 32, Eq / 32, Bq), 256>>>(vb, vth, vtl);
    // 7) attention (FA2-style HMMA, split-bf16 exact) -> writes [hi|hi|lo]
    attn_mma2<<<dim3(Sq / 128, Hq, Bq), 256, SMEM_ATTN3>>>(qh, ql, kh, kl, vth, vtl, ao3);
    // 8) output projection + bias
    hmma_gemm<<<dim3(16, 32), 256>>>(ao3, ow3, out, nullptr, nullptr, ob,
                                     3 * Eq, Eq, Bq * Sq, Bq * Sq, 0, nullptr, nullptr);
}

// round 7
// speedup vs baseline: 9.4083x; 1.2288x over previous
#include <cuda_runtime.h>
#include <cuda_bf16.h>
#include <cstdint>

#define Bq 2
#define Sq 2048
#define Rq 128
#define Eq 2048
#define Hq 16
#define Dq 128
#define Lq (Sq + Rq)   // 2176

// ---------------- scratch (device globals, no allocations) ----------------
__device__ __nv_bfloat16 g_xbf[(size_t)Bq * Sq * Eq];      // quantized acts as bf16 ints
__device__ __nv_bfloat16 g_wbf[3][(size_t)Eq * Eq];        // ternary weights as bf16
__device__ __nv_bfloat16 g_rt3[(size_t)Bq * Rq * 3 * Eq];  // reasoning tokens split [hi|hi|lo]
__device__ __nv_bfloat16 g_kw3[(size_t)Eq * 3 * Eq];       // k_w split [hi|lo|hi]
__device__ __nv_bfloat16 g_vw3[(size_t)Eq * 3 * Eq];       // v_w split
__device__ __nv_bfloat16 g_ow3[(size_t)Eq * 3 * Eq];       // out_w split
__device__ __nv_bfloat16 g_ao3[(size_t)Bq * Sq * 3 * Eq];  // attn out split [hi|hi|lo]
__device__ __nv_bfloat16 g_qh[(size_t)Bq * Sq * Eq];       // Q hi
__device__ __nv_bfloat16 g_ql[(size_t)Bq * Sq * Eq];       // Q lo
__device__ __nv_bfloat16 g_kh[(size_t)Bq * Lq * Eq];       // K hi
__device__ __nv_bfloat16 g_kl[(size_t)Bq * Lq * Eq];       // K lo
__device__ __nv_bfloat16 g_vth[(size_t)Bq * Hq * Dq * Lq]; // V^T hi [B,H,D,L]
__device__ __nv_bfloat16 g_vtl[(size_t)Bq * Hq * Dq * Lq]; // V^T lo
__device__ float g_rows[(size_t)Bq * Sq];                  // per-row act scale s
__device__ float g_vb[(size_t)Bq * Lq * Eq];               // V fp32
__device__ float g_part[3 * 1024];
__device__ float g_scale[3];

// ---------------- PTX helpers ----------------
typedef unsigned long long ull;
__device__ __forceinline__ uint32_t smem_u32(const void* p) {
    uint32_t a;
    asm("{ .reg .u64 t; cvta.to.shared.u64 t, %1; cvt.u32.u64 %0, t; }" : "=r"(a) : "l"(p));
    return a;
}
__device__ __forceinline__ void ldmx4(uint32_t* r, uint32_t addr) {
    asm volatile("ldmatrix.sync.aligned.m8n8.x4.shared.b16 {%0,%1,%2,%3}, [%4];"
                 : "=r"(r[0]), "=r"(r[1]), "=r"(r[2]), "=r"(r[3]) : "r"(addr));
}
__device__ __forceinline__ void mma16816(float* c, const uint32_t* a, const uint32_t* b) {
    asm volatile("mma.sync.aligned.m16n8k16.row.col.f32.bf16.bf16.f32 "
                 "{%0,%1,%2,%3}, {%4,%5,%6,%7}, {%8,%9}, {%0,%1,%2,%3};"
                 : "+f"(c[0]), "+f"(c[1]), "+f"(c[2]), "+f"(c[3])
                 : "r"(a[0]), "r"(a[1]), "r"(a[2]), "r"(a[3]), "r"(b[0]), "r"(b[1]));
}
__device__ __forceinline__ void cpa16(uint32_t dst, const void* src) {
    asm volatile("cp.async.cg.shared.global [%0], [%1], 16;" :: "r"(dst), "l"(src) : "memory");
}
__device__ __forceinline__ void cpa_commit() {
    asm volatile("cp.async.commit_group;" ::: "memory");
}
__device__ __forceinline__ void cpa_wait0() {
    asm volatile("cp.async.wait_group 0;" ::: "memory");
}
__device__ __forceinline__ void cpa_wait1() {
    asm volatile("cp.async.wait_group 1;" ::: "memory");
}
// smem rows of 32 bf16 (64B); 16B group g stored at g ^ ((row>>1)&3)
__device__ __forceinline__ uint32_t swoff(int r, int g) {
    return (uint32_t)(r * 64 + ((g ^ ((r >> 1) & 3)) << 4));
}
// per-lane address offset for B-side ldmatrix.x4 (2 consecutive n-frags of 8 rows)
__device__ __forceinline__ uint32_t boff4(int base_row, int lane) {
    int r = base_row + ((lane >> 4) << 3) + (lane & 7);
    int g = (lane >> 3) & 1;
    return swoff(r, g);
}
// pack two fp32 into bf16x2 hi + residual lo
__device__ __forceinline__ void hl2(float x, float y, uint32_t& h, uint32_t& l) {
    __nv_bfloat162 hh, ll;
    hh.x = __float2bfloat16(x);
    hh.y = __float2bfloat16(y);
    ll.x = __float2bfloat16(x - __bfloat162float(hh.x));
    ll.y = __float2bfloat16(y - __bfloat162float(hh.y));
    h = *(uint32_t*)&hh;
    l = *(uint32_t*)&ll;
}

// ---------------- weight mean(|w|) : stage 1 ----------------
__global__ void reduce_abs_kernel(const float* __restrict__ w0, const float* __restrict__ w1,
                                  const float* __restrict__ w2, float* __restrict__ part) {
    const float* w = (blockIdx.y == 0) ? w0 : ((blockIdx.y == 1) ? w1 : w2);
    int t = threadIdx.x;
    size_t base = (size_t)blockIdx.x * 4096;
    float s = 0.f;
#pragma unroll
    for (int i = 0; i < 16; i++) s += fabsf(w[base + t + i * 256]);
    __shared__ float red[256];
    red[t] = s;
    __syncthreads();
    for (int o = 128; o > 0; o >>= 1) {
        if (t < o) red[t] += red[t + o];
        __syncthreads();
    }
    if (t == 0) part[blockIdx.y * 1024 + blockIdx.x] = red[0];
}

__global__ void finalize_scale_kernel(const float* __restrict__ part, float* __restrict__ scale) {
    int w = blockIdx.x;
    int t = threadIdx.x;
    float s = part[w * 1024 + t] + part[w * 1024 + t + 256] +
              part[w * 1024 + t + 512] + part[w * 1024 + t + 768];
    __shared__ float red[256];
    red[t] = s;
    __syncthreads();
    for (int o = 128; o > 0; o >>= 1) {
        if (t < o) red[t] += red[t + o];
        __syncthreads();
    }
    if (t == 0) {
        float mean = red[0] * (1.0f / ((float)Eq * (float)Eq));
        scale[w] = fmaxf(mean, 1e-5f);
    }
}

// ---------------- ternary weight quantization -> bf16 {-1,0,1} ----------------
__global__ void quant_weight_bf16(const float* __restrict__ w0, const float* __restrict__ w1,
                                  const float* __restrict__ w2, __nv_bfloat16* __restrict__ wq,
                                  const float* __restrict__ scale) {
    int wi = blockIdx.y;
    const float* w = (wi == 0) ? w0 : ((wi == 1) ? w1 : w2);
    float inv = __frcp_rn(scale[wi]);
    size_t e0 = ((size_t)blockIdx.x * 256 + threadIdx.x) * 8;
    __nv_bfloat16* wo = wq + (size_t)wi * Eq * Eq + e0;
#pragma unroll
    for (int i = 0; i < 8; i += 4) {
        float4 v = *(const float4*)&w[e0 + i];
        wo[i + 0] = __float2bfloat16(fminf(fmaxf(rintf(v.x * inv), -1.f), 1.f));
        wo[i + 1] = __float2bfloat16(fminf(fmaxf(rintf(v.y * inv), -1.f), 1.f));
        wo[i + 2] = __float2bfloat16(fminf(fmaxf(rintf(v.z * inv), -1.f), 1.f));
        wo[i + 3] = __float2bfloat16(fminf(fmaxf(rintf(v.w * inv), -1.f), 1.f));
    }
}

// ---------------- per-token absmax quantization (warp per row, no syncs) ----------------
__global__ void quant_act_bf16(const float* __restrict__ x, __nv_bfloat16* __restrict__ xq,
                               float* __restrict__ rows) {
    int w = (blockIdx.x * blockDim.x + threadIdx.x) >> 5;  // one warp per row
    int lane = threadIdx.x & 31;
    const float* xr = x + (size_t)w * Eq;
    float4 v[16];
    float mx = 0.f;
#pragma unroll
    for (int i = 0; i < 16; i++) {
        v[i] = *(const float4*)&xr[i * 128 + lane * 4];
        mx = fmaxf(mx, fmaxf(fmaxf(fabsf(v[i].x), fabsf(v[i].y)),
                             fmaxf(fabsf(v[i].z), fabsf(v[i].w))));
    }
#pragma unroll
    for (int o = 16; o > 0; o >>= 1) mx = fmaxf(mx, __shfl_xor_sync(0xffffffffu, mx, o));
    float s = __fdiv_rn(127.0f, fmaxf(mx, 1e-5f));
    if (lane == 0) rows[w] = s;
    __nv_bfloat16* xo = xq + (size_t)w * Eq;
#pragma unroll
    for (int i = 0; i < 16; i++) {
        __nv_bfloat162 p0, p1;
        p0.x = __float2bfloat16(fminf(fmaxf(rintf(v[i].x * s), -128.f), 127.f));
        p0.y = __float2bfloat16(fminf(fmaxf(rintf(v[i].y * s), -128.f), 127.f));
        p1.x = __float2bfloat16(fminf(fmaxf(rintf(v[i].z * s), -128.f), 127.f));
        p1.y = __float2bfloat16(fminf(fmaxf(rintf(v[i].w * s), -128.f), 127.f));
        *(__nv_bfloat162*)&xo[i * 128 + lane * 4] = p0;
        *(__nv_bfloat162*)&xo[i * 128 + lane * 4 + 2] = p1;
    }
}

// ---------------- fp32 -> split-bf16 K-tripling (row length 2048) ----------------
// mode 0 (A side): [hi | hi | lo]    mode 1 (B side): [hi | lo | hi]
__global__ void split3(const float* __restrict__ X, __nv_bfloat16* __restrict__ Y, int mode) {
    size_t i = (size_t)blockIdx.x * 256 + threadIdx.x;
    size_t row = i >> 11, col = i & 2047;
    float x = X[i];
    __nv_bfloat16 hi = __float2bfloat16(x);
    __nv_bfloat16 lo = __float2bfloat16(x - __bfloat162float(hi));
    __nv_bfloat16* yr = Y + row * (size_t)(3 * Eq);
    yr[col] = hi;
    yr[Eq + col] = mode ? lo : hi;
    yr[2 * Eq + col] = mode ? hi : lo;
}

// ---------------- V fp32 [B,L,E] -> V^T hi/lo [B,H,D,L] ----------------
__global__ void transpose_v(const float* __restrict__ V, __nv_bfloat16* __restrict__ Th,
                            __nv_bfloat16* __restrict__ Tl) {
    __shared__ float s[32][33];
    int l0 = blockIdx.x * 32;
    int e0 = blockIdx.y * 32;
    int b = blockIdx.z;
    int t = threadIdx.x;
    int h = e0 >> 7, d0 = e0 & 127;
#pragma unroll
    for (int i = 0; i < 4; i++) {
        int idx = t + i * 256;
        int lr = idx >> 5, lc = idx & 31;
        s[lr][lc] = V[((size_t)(b * Lq + l0 + lr)) * Eq + e0 + lc];
    }
    __syncthreads();
#pragma unroll
    for (int i = 0; i < 4; i++) {
        int idx = t + i * 256;
        int dr = idx >> 5, dc = idx & 31;
        float f = s[dc][dr];
        __nv_bfloat16 hi = __float2bfloat16(f);
        __nv_bfloat16 lo = __float2bfloat16(f - __bfloat162float(hi));
        size_t o = ((size_t)((b * Hq + h) * Dq + d0 + dr)) * Lq + l0 + dc;
        Th[o] = hi;
        Tl[o] = lo;
    }
}

// ---------------- HMMA bf16 GEMM: cp.async 3-stage, 2 CTAs/SM ----------------
__global__ __launch_bounds__(256, 2) void hmma_gemm(
    const __nv_bfloat16* __restrict__ A, const __nv_bfloat16* __restrict__ B,
    float* __restrict__ C, const float* __restrict__ rowscale,
    const float* __restrict__ wsp, const float* __restrict__ bias,
    int K, int Nout, int rbi, int rbo, int roff,
    __nv_bfloat16* __restrict__ Hout, __nv_bfloat16* __restrict__ Lout) {
    __shared__ __align__(128) uint8_t sA[3][8192];
    __shared__ __align__(128) uint8_t sB[3][8192];
    int t = threadIdx.x;
    int lane = t & 31, wid = t >> 5;
    int m0 = blockIdx.y * 128, n0 = blockIdx.x * 128;
    int warp_m = wid & 1, warp_n = wid >> 1;

    int r0 = t >> 2, g0 = t & 3;
    int r1 = 64 + r0;
    const uint4* Ag0 = (const uint4*)(A + (size_t)(m0 + r0) * K) + g0;
    const uint4* Ag1 = (const uint4*)(A + (size_t)(m0 + r1) * K) + g0;
    const uint4* Bg0 = (const uint4*)(B + (size_t)(n0 + r0) * K) + g0;
    const uint4* Bg1 = (const uint4*)(B + (size_t)(n0 + r1) * K) + g0;
    uint32_t st0 = swoff(r0, g0), st1 = swoff(r1, g0);

    uint32_t sAu = smem_u32(sA), sBu = smem_u32(sB);

    uint32_t aaddr[4], baddr4[2];
#pragma unroll
    for (int mi = 0; mi < 4; mi++)
        aaddr[mi] = sAu + swoff(warp_m * 64 + mi * 16 + (lane & 15), lane >> 4);
#pragma unroll
    for (int ni2 = 0; ni2 < 2; ni2++)
        baddr4[ni2] = sBu + boff4(warp_n * 32 + ni2 * 16, lane);

    // 3-stage cp.async pipeline, 1 sync per k-tile
    const int NK = K >> 5;
    {
        // preload tile 0 -> stage 0
        cpa16(sAu + st0, Ag0);
        cpa16(sAu + st1, Ag1);
        cpa16(sBu + st0, Bg0);
        cpa16(sBu + st1, Bg1);
        cpa_commit();
    }

    float c[4][4][4];
#pragma unroll
    for (int mi = 0; mi < 4; mi++)
#pragma unroll
        for (int ni = 0; ni < 4; ni++)
#pragma unroll
            for (int k = 0; k < 4; k++) c[mi][ni][k] = 0.f;

    int s = 0;
    for (int kt = 0; kt < NK; ++kt) {
        if (kt + 1 < NK) {
            int sn = (s + 1 == 3) ? 0 : s + 1;
            uint32_t ao = sn * 8192, bo = sn * 8192;
            cpa16(sAu + ao + st0, Ag0 + (kt + 1) * 4);
            cpa16(sAu + ao + st1, Ag1 + (kt + 1) * 4);
            cpa16(sBu + bo + st0, Bg0 + (kt + 1) * 4);
            cpa16(sBu + bo + st1, Bg1 + (kt + 1) * 4);
            cpa_commit();
            cpa_wait1();
        } else {
            cpa_wait0();
        }
        __syncthreads();

        uint32_t bofs = s * 8192;
#pragma unroll
        for (int ks = 0; ks < 2; ks++) {
            uint32_t kx = ks * 32;
            uint32_t a[4][4], b[2][4];
#pragma unroll
            for (int mi = 0; mi < 4; mi++) ldmx4(a[mi], (aaddr[mi] + bofs) ^ kx);
#pragma unroll
            for (int ni2 = 0; ni2 < 2; ni2++) ldmx4(b[ni2], (baddr4[ni2] + bofs) ^ kx);
#pragma unroll
            for (int mi = 0; mi < 4; mi++)
#pragma unroll
                for (int ni = 0; ni < 4; ni++)
                    mma16816(c[mi][ni], a[mi], &b[ni >> 1][(ni & 1) * 2]);
        }
        s = (s + 1 == 3) ? 0 : s + 1;
    }

    float ws = wsp ? *wsp : 1.0f;
    int g = lane >> 2, tg = lane & 3;
#pragma unroll
    for (int mi = 0; mi < 4; mi++) {
        int mA = m0 + warp_m * 64 + mi * 16 + g;
        int mB = mA + 8;
        float fA = rowscale ? (ws / rowscale[mA]) : 1.0f;
        float fB = rowscale ? (ws / rowscale[mB]) : 1.0f;
        int oA = (mA / rbi) * rbo + roff + (mA % rbi);
        int oB = (mB / rbi) * rbo + roff + (mB % rbi);
        if (Hout) {
            __nv_bfloat16* hA = Hout + (size_t)oA * Nout;
            __nv_bfloat16* hB = Hout + (size_t)oB * Nout;
            __nv_bfloat16* lA = Lout + (size_t)oA * Nout;
            __nv_bfloat16* lB = Lout + (size_t)oB * Nout;
#pragma unroll
            for (int ni = 0; ni < 4; ni++) {
                int col = n0 + warp_n * 32 + ni * 8 + tg * 2;
                uint32_t h0, l0v, h1, l1v;
                hl2(c[mi][ni][0] * fA, c[mi][ni][1] * fA, h0, l0v);
                hl2(c[mi][ni][2] * fB, c[mi][ni][3] * fB, h1, l1v);
                *(uint32_t*)&hA[col] = h0;
                *(uint32_t*)&lA[col] = l0v;
                *(uint32_t*)&hB[col] = h1;
                *(uint32_t*)&lB[col] = l1v;
            }
        } else {
            float* crA = C + (size_t)oA * Nout;
            float* crB = C + (size_t)oB * Nout;
#pragma unroll
            for (int ni = 0; ni < 4; ni++) {
                int col = n0 + warp_n * 32 + ni * 8 + tg * 2;
                float b0 = 0.f, b1 = 0.f;
                if (bias) { b0 = bias[col]; b1 = bias[col + 1]; }
                float2 vA, vB;
                vA.x = c[mi][ni][0] * fA + b0;
                vA.y = c[mi][ni][1] * fA + b1;
                vB.x = c[mi][ni][2] * fB + b0;
                vB.y = c[mi][ni][3] * fB + b1;
                *(float2*)&crA[col] = vA;
                *(float2*)&crB[col] = vB;
            }
        }
    }
}

// ---------------- FA2-style HMMA flash attention, cp.async double-buffered K/V ----------------
// smem: QH 32K | QL 32K | 2 stages x (KH 16K | KL 16K | VH 16K | VL 16K)
#define ATT_QH 0
#define ATT_QL 32768
#define ATT_KV 65536
#define SMEM_ATTN3 (65536 + 2 * 65536)   // 196608

__global__ __launch_bounds__(256, 1) void attn_mma2(
    const __nv_bfloat16* __restrict__ Qh, const __nv_bfloat16* __restrict__ Ql,
    const __nv_bfloat16* __restrict__ Kh, const __nv_bfloat16* __restrict__ Kl,
    const __nv_bfloat16* __restrict__ Vth, const __nv_bfloat16* __restrict__ Vtl,
    __nv_bfloat16* __restrict__ O3) {
    extern __shared__ char smg[];
    uint32_t sb = smem_u32(smg);
    int t = threadIdx.x;
    int lane = t & 31, wid = t >> 5;
    int qb = blockIdx.x * 128;
    int h = blockIdx.y;
    int b = blockIdx.z;

    // ---- issue Q loads (joins tile-0 commit group) ----
    {
        const __nv_bfloat16* Qhg = Qh + ((size_t)(b * Sq + qb)) * Eq + h * Dq;
        const __nv_bfloat16* Qlg = Ql + ((size_t)(b * Sq + qb)) * Eq + h * Dq;
#pragma unroll
        for (int i = 0; i < 8; i++) {
            int idx = t + i * 256;
            int r = idx >> 4, g = idx & 15;
            uint32_t dst = (g >> 2) * 8192 + swoff(r, g & 3);
            cpa16(sb + ATT_QH + dst, Qhg + (size_t)r * Eq + g * 8);
            cpa16(sb + ATT_QL + dst, Qlg + (size_t)r * Eq + g * 8);
        }
    }

    const __nv_bfloat16* Khb = Kh + ((size_t)(b * Lq)) * Eq + h * Dq;
    const __nv_bfloat16* Klb = Kl + ((size_t)(b * Lq)) * Eq + h * Dq;
    const __nv_bfloat16* Vhb = Vth + ((size_t)((b * Hq + h) * Dq)) * Lq;
    const __nv_bfloat16* Vlb = Vtl + ((size_t)((b * Hq + h) * Dq)) * Lq;

    auto issueKV = [&](int kt, int st) {
        uint32_t base = sb + ATT_KV + st * 65536;
        const __nv_bfloat16* KhT = Khb + (size_t)(kt * 64) * Eq;
        const __nv_bfloat16* KlT = Klb + (size_t)(kt * 64) * Eq;
#pragma unroll
        for (int i = 0; i < 4; i++) {
            int idx = t + i * 256;
            int r = idx >> 4, g = idx & 15;
            uint32_t dst = (g >> 2) * 4096 + swoff(r, g & 3);
            cpa16(base + dst, KhT + (size_t)r * Eq + g * 8);
            cpa16(base + 16384 + dst, KlT + (size_t)r * Eq + g * 8);
        }
        const __nv_bfloat16* VhT = Vhb + kt * 64;
        const __nv_bfloat16* VlT = Vlb + kt * 64;
#pragma unroll
        for (int i = 0; i < 4; i++) {
            int idx = t + i * 256;
            int r = idx >> 3, g = idx & 7;
            uint32_t dst = (g >> 2) * 8192 + swoff(r, g & 3);
            cpa16(base + 32768 + dst, VhT + (size_t)r * Lq + g * 8);
            cpa16(base + 49152 + dst, VlT + (size_t)r * Lq + g * 8);
        }
        cpa_commit();
    };
    issueKV(0, 0);   // commit covers Q + tile 0

    const int wm = wid;
    const uint32_t a_off = swoff(wm * 16 + (lane & 15), lane >> 4);
    uint32_t k4[4], v4[8];
#pragma unroll
    for (int ni2 = 0; ni2 < 4; ni2++) k4[ni2] = boff4(ni2 * 16, lane);
#pragma unroll
    for (int ni2 = 0; ni2 < 8; ni2++) v4[ni2] = boff4(ni2 * 16, lane);
    const int g4 = lane >> 2, tg = lane & 3;
    const float SCALE = 0.08838834764831845f;

    float m0 = -1e30f, m1 = -1e30f, l0 = 0.f, l1 = 0.f;
    float co[16][4];
#pragma unroll
    for (int i = 0; i < 16; i++)
#pragma unroll
        for (int j = 0; j < 4; j++) co[i][j] = 0.f;

    const int NT = Lq / 64;  // 34? no: 2176/64 = 34 -> actually 34
    for (int kt = 0; kt < NT; ++kt) {
        int st = kt & 1;
        if (kt + 1 < NT) { issueKV(kt + 1, st ^ 1); cpa_wait1(); }
        else cpa_wait0();
        __syncthreads();
        uint32_t kvb = sb + ATT_KV + st * 65536;

        // ---- S = Qh.Kh + Qh.Kl + Ql.Kh ----
        float cs[8][4];
#pragma unroll
        for (int i = 0; i < 8; i++)
#pragma unroll
            for (int j = 0; j < 4; j++) cs[i][j] = 0.f;
#pragma unroll
        for (int ch = 0; ch < 4; ch++)
#pragma unroll
            for (int ks = 0; ks < 2; ks++) {
                uint32_t kx = ks * 32;
                uint32_t ah[4], al[4];
                ldmx4(ah, sb + ATT_QH + ch * 8192 + (a_off ^ kx));
                ldmx4(al, sb + ATT_QL + ch * 8192 + (a_off ^ kx));
#pragma unroll
                for (int ni2 = 0; ni2 < 4; ni2++) {
                    uint32_t bh[4], bl[4];
                    uint32_t ba = kvb + ch * 4096 + ((k4[ni2]) ^ kx);
                    ldmx4(bh, ba);
                    ldmx4(bl, ba + 16384);
                    mma16816(cs[2 * ni2], ah, bh);
                    mma16816(cs[2 * ni2], ah, bl);
                    mma16816(cs[2 * ni2], al, bh);
                    mma16816(cs[2 * ni2 + 1], ah, bh + 2);
                    mma16816(cs[2 * ni2 + 1], ah, bl + 2);
                    mma16816(cs[2 * ni2 + 1], al, bh + 2);
                }
            }

        // ---- in-register softmax ----
        float tm0 = -1e30f, tm1 = -1e30f;
#pragma unroll
        for (int ni = 0; ni < 8; ni++) {
            cs[ni][0] *= SCALE; cs[ni][1] *= SCALE;
            cs[ni][2] *= SCALE; cs[ni][3] *= SCALE;
            tm0 = fmaxf(tm0, fmaxf(cs[ni][0], cs[ni][1]));
            tm1 = fmaxf(tm1, fmaxf(cs[ni][2], cs[ni][3]));
        }
        tm0 = fmaxf(tm0, __shfl_xor_sync(0xffffffffu, tm0, 1));
        tm0 = fmaxf(tm0, __shfl_xor_sync(0xffffffffu, tm0, 2));
        tm1 = fmaxf(tm1, __shfl_xor_sync(0xffffffffu, tm1, 1));
        tm1 = fmaxf(tm1, __shfl_xor_sync(0xffffffffu, tm1, 2));
        float nm0 = fmaxf(m0, tm0), nm1 = fmaxf(m1, tm1);
        float al0 = __expf(m0 - nm0), al1 = __expf(m1 - nm1);
        m0 = nm0; m1 = nm1;

        float rs0 = 0.f, rs1 = 0.f;
#pragma unroll
        for (int ni = 0; ni < 8; ni++) {
            cs[ni][0] = __expf(cs[ni][0] - m0); rs0 += cs[ni][0];
            cs[ni][1] = __expf(cs[ni][1] - m0); rs0 += cs[ni][1];
            cs[ni][2] = __expf(cs[ni][2] - m1); rs1 += cs[ni][2];
            cs[ni][3] = __expf(cs[ni][3] - m1); rs1 += cs[ni][3];
        }
        rs0 += __shfl_xor_sync(0xffffffffu, rs0, 1);
        rs0 += __shfl_xor_sync(0xffffffffu, rs0, 2);
        rs1 += __shfl_xor_sync(0xffffffffu, rs1, 1);
        rs1 += __shfl_xor_sync(0xffffffffu, rs1, 2);
        l0 = l0 * al0 + rs0;
        l1 = l1 * al1 + rs1;

        // ---- P hi/lo A-fragments ----
        uint32_t phf[4][4], plf[4][4];
#pragma unroll
        for (int ck = 0; ck < 4; ck++) {
            hl2(cs[2 * ck][0], cs[2 * ck][1], phf[ck][0], plf[ck][0]);
            hl2(cs[2 * ck][2], cs[2 * ck][3], phf[ck][1], plf[ck][1]);
            hl2(cs[2 * ck + 1][0], cs[2 * ck + 1][1], phf[ck][2], plf[ck][2]);
            hl2(cs[2 * ck + 1][2], cs[2 * ck + 1][3], phf[ck][3], plf[ck][3]);
        }

        // ---- rescale O ----
#pragma unroll
        for (int ni = 0; ni < 16; ni++) {
            co[ni][0] *= al0; co[ni][1] *= al0;
            co[ni][2] *= al1; co[ni][3] *= al1;
        }

        // ---- O += Ph.Vh + Ph.Vl + Pl.Vh ----
#pragma unroll
        for (int ck = 0; ck < 4; ck++) {
#pragma unroll
            for (int ni2 = 0; ni2 < 8; ni2++) {
                uint32_t bh[4], bl[4];
                uint32_t ba = kvb + 32768 + (ck >> 1) * 8192 + ((v4[ni2]) ^ ((ck & 1) * 32));
                ldmx4(bh, ba);
                ldmx4(bl, ba + 16384);
                mma16816(co[2 * ni2], phf[ck], bh);
                mma16816(co[2 * ni2], phf[ck], bl);
                mma16816(co[2 * ni2], plf[ck], bh);
                mma16816(co[2 * ni2 + 1], phf[ck], bh + 2);
                mma16816(co[2 * ni2 + 1], phf[ck], bl + 2);
                mma16816(co[2 * ni2 + 1], plf[ck], bh + 2);
            }
        }
        __syncthreads();
    }

    // ---- epilogue: write O split [hi|hi|lo] ----
    float il0 = 1.0f / l0, il1 = 1.0f / l1;
    int r0 = wm * 16 + g4, r1 = r0 + 8;
    __nv_bfloat16* O0 = O3 + ((size_t)(b * Sq + qb + r0)) * (3 * Eq) + h * Dq;
    __nv_bfloat16* O1 = O3 + ((size_t)(b * Sq + qb + r1)) * (3 * Eq) + h * Dq;
#pragma unroll
    for (int ni = 0; ni < 16; ni++) {
        int col = ni * 8 + tg * 2;
        uint32_t h0, lo0, h1, lo1;
        hl2(co[ni][0] * il0, co[ni][1] * il0, h0, lo0);
        hl2(co[ni][2] * il1, co[ni][3] * il1, h1, lo1);
        *(uint32_t*)(O0 + col) = h0;
        *(uint32_t*)(O0 + Eq + col) = h0;
        *(uint32_t*)(O0 + 2 * Eq + col) = lo0;
        *(uint32_t*)(O1 + col) = h1;
        *(uint32_t*)(O1 + Eq + col) = h1;
        *(uint32_t*)(O1 + 2 * Eq + col) = lo1;
    }
}

// ---------------- host launcher ----------------
extern "C" void kernel_launch(void* const* d_in, const int* in_sizes, int n_in,
                              void* d_out, int out_size) {
    const float* x  = (const float*)d_in[0];
    const float* rt = (const float*)d_in[1];
    const float* qw = (const float*)d_in[2];
    const float* kw = (const float*)d_in[3];
    const float* vw = (const float*)d_in[4];
    const float* ow = (const float*)d_in[5];
    const float* ob = (const float*)d_in[6];
    float* out = (float*)d_out;

    __nv_bfloat16 *xbf, *wbf, *rt3, *kw3, *vw3, *ow3, *ao3, *qh, *ql, *kh, *kl, *vth, *vtl;
    float *rows, *vb, *part, *scale;
    cudaGetSymbolAddress((void**)&xbf, g_xbf);
    cudaGetSymbolAddress((void**)&wbf, g_wbf);
    cudaGetSymbolAddress((void**)&rt3, g_rt3);
    cudaGetSymbolAddress((void**)&kw3, g_kw3);
    cudaGetSymbolAddress((void**)&vw3, g_vw3);
    cudaGetSymbolAddress((void**)&ow3, g_ow3);
    cudaGetSymbolAddress((void**)&ao3, g_ao3);
    cudaGetSymbolAddress((void**)&qh, g_qh);
    cudaGetSymbolAddress((void**)&ql, g_ql);
    cudaGetSymbolAddress((void**)&kh, g_kh);
    cudaGetSymbolAddress((void**)&kl, g_kl);
    cudaGetSymbolAddress((void**)&vth, g_vth);
    cudaGetSymbolAddress((void**)&vtl, g_vtl);
    cudaGetSymbolAddress((void**)&rows, g_rows);
    cudaGetSymbolAddress((void**)&vb, g_vb);
    cudaGetSymbolAddress((void**)&part, g_part);
    cudaGetSymbolAddress((void**)&scale, g_scale);

    cudaFuncSetAttribute(attn_mma2, cudaFuncAttributeMaxDynamicSharedMemorySize, SMEM_ATTN3);

    // 1) weight scales
    reduce_abs_kernel<<<dim3(1024, 3), 256>>>(qw, kw, vw, part);
    finalize_scale_kernel<<<3, 256>>>(part, scale);
    // 2) quantize to bf16 (exact integer/ternary values)
    quant_weight_bf16<<<dim3(2048, 3), 256>>>(qw, kw, vw, wbf, scale);
    quant_act_bf16<<<(Bq * Sq) / 8, 256>>>(x, xbf, rows);
    // 3) split unquantized operands (K-tripled bf16)
    split3<<<(Eq * Eq) / 256, 256>>>(kw, kw3, 1);
    split3<<<(Eq * Eq) / 256, 256>>>(vw, vw3, 1);
    split3<<<(Eq * Eq) / 256, 256>>>(ow, ow3, 1);
    split3<<<(Bq * Rq * Eq) / 256, 256>>>(rt, rt3, 0);
    // 4) quantized projections (exact bf16-int HMMA); Q/K write hi/lo splits directly
    size_t EE = (size_t)Eq * Eq;
    hmma_gemm<<<dim3(16, 32), 256>>>(xbf, wbf + 0 * EE, nullptr, rows, scale + 0, nullptr,
                                     Eq, Eq, Sq, Sq, 0, qh, ql);
    hmma_gemm<<<dim3(16, 32), 256>>>(xbf, wbf + 1 * EE, nullptr, rows, scale + 1, nullptr,
                                     Eq, Eq, Sq, Lq, 0, kh, kl);
    hmma_gemm<<<dim3(16, 32), 256>>>(xbf, wbf + 2 * EE, vb, rows, scale + 2, nullptr,
                                     Eq, Eq, Sq, Lq, 0, nullptr, nullptr);
    // 5) reasoning projections: split-bf16 (K=6144), appended after S self rows
    hmma_gemm<<<dim3(16, 2), 256>>>(rt3, kw3, nullptr, nullptr, nullptr, nullptr,
                                    3 * Eq, Eq, Rq, Lq, Sq, kh, kl);
    hmma_gemm<<<dim3(16, 2), 256>>>(rt3, vw3, vb, nullptr, nullptr, nullptr,
                                    3 * Eq, Eq, Rq, Lq, Sq, nullptr, nullptr);
    // 6) transpose+split V
    transpose_v<<<dim3(Lq / 32, Eq / 32, Bq), 256>>>(vb, vth, vtl);
    // 7) attention (FA2-style HMMA, cp.async double-buffered) -> writes [hi|hi|lo]
    attn_mma2<<<dim3(Sq / 128, Hq, Bq), 256, SMEM_ATTN3>>>(qh, ql, kh, kl, vth, vtl, ao3);
    // 8) output projection + bias
    hmma_gemm<<<dim3(16, 32), 256>>>(ao3, ow3, out, nullptr, nullptr, ob,
                                     3 * Eq, Eq, Bq * Sq, Bq * Sq, 0, nullptr, nullptr);
}

// round 8
// speedup vs baseline: 10.4884x; 1.1148x over previous
#include <cuda_runtime.h>
#include <cuda_bf16.h>
#include <cstdint>

#define Bq 2
#define Sq 2048
#define Rq 128
#define Eq 2048
#define Hq 16
#define Dq 128
#define Lq (Sq + Rq)   // 2176

// ---------------- scratch (device globals, no allocations) ----------------
__device__ __nv_bfloat16 g_xbf[(size_t)Bq * Sq * Eq];      // quantized acts as bf16 ints
__device__ __nv_bfloat16 g_wbf[3][(size_t)Eq * Eq];        // ternary weights as bf16
__device__ __nv_bfloat16 g_rt3[(size_t)Bq * Rq * 3 * Eq];  // reasoning tokens split [hi|hi|lo]
__device__ __nv_bfloat16 g_kw3[(size_t)Eq * 3 * Eq];       // k_w split [hi|lo|hi]
__device__ __nv_bfloat16 g_vw3[(size_t)Eq * 3 * Eq];       // v_w split
__device__ __nv_bfloat16 g_ow3[(size_t)Eq * 3 * Eq];       // out_w split
__device__ __nv_bfloat16 g_ao3[(size_t)Bq * Sq * 3 * Eq];  // attn out split [hi|hi|lo]
__device__ __nv_bfloat16 g_qh[(size_t)Bq * Sq * Eq];       // Q hi
__device__ __nv_bfloat16 g_ql[(size_t)Bq * Sq * Eq];       // Q lo
__device__ __nv_bfloat16 g_kh[(size_t)Bq * Lq * Eq];       // K hi
__device__ __nv_bfloat16 g_kl[(size_t)Bq * Lq * Eq];       // K lo
__device__ __nv_bfloat16 g_vth[(size_t)Bq * Hq * Dq * Lq]; // V^T hi [B,H,D,L]
__device__ __nv_bfloat16 g_vtl[(size_t)Bq * Hq * Dq * Lq]; // V^T lo
__device__ float g_rows[(size_t)Bq * Sq];                  // per-row act scale s
__device__ float g_vb[(size_t)Bq * Lq * Eq];               // V fp32
__device__ float g_part[3 * 1024];
__device__ float g_scale[3];

// ---------------- PTX helpers ----------------
typedef unsigned long long ull;
__device__ __forceinline__ uint32_t smem_u32(const void* p) {
    uint32_t a;
    asm("{ .reg .u64 t; cvta.to.shared.u64 t, %1; cvt.u32.u64 %0, t; }" : "=r"(a) : "l"(p));
    return a;
}
__device__ __forceinline__ void ldmx4(uint32_t* r, uint32_t addr) {
    asm volatile("ldmatrix.sync.aligned.m8n8.x4.shared.b16 {%0,%1,%2,%3}, [%4];"
                 : "=r"(r[0]), "=r"(r[1]), "=r"(r[2]), "=r"(r[3]) : "r"(addr));
}
__device__ __forceinline__ void mma16816(float* c, const uint32_t* a, const uint32_t* b) {
    asm volatile("mma.sync.aligned.m16n8k16.row.col.f32.bf16.bf16.f32 "
                 "{%0,%1,%2,%3}, {%4,%5,%6,%7}, {%8,%9}, {%0,%1,%2,%3};"
                 : "+f"(c[0]), "+f"(c[1]), "+f"(c[2]), "+f"(c[3])
                 : "r"(a[0]), "r"(a[1]), "r"(a[2]), "r"(a[3]), "r"(b[0]), "r"(b[1]));
}
__device__ __forceinline__ void cpa16(uint32_t dst, const void* src) {
    asm volatile("cp.async.cg.shared.global [%0], [%1], 16;" :: "r"(dst), "l"(src) : "memory");
}
__device__ __forceinline__ void cpa_commit() {
    asm volatile("cp.async.commit_group;" ::: "memory");
}
__device__ __forceinline__ void cpa_wait0() {
    asm volatile("cp.async.wait_group 0;" ::: "memory");
}
__device__ __forceinline__ void cpa_wait1() {
    asm volatile("cp.async.wait_group 1;" ::: "memory");
}
// smem rows of 32 bf16 (64B); 16B group g stored at g ^ ((row>>1)&3)
__device__ __forceinline__ uint32_t swoff(int r, int g) {
    return (uint32_t)(r * 64 + ((g ^ ((r >> 1) & 3)) << 4));
}
// per-lane address offset for B-side ldmatrix.x4 (2 consecutive n-frags of 8 rows)
__device__ __forceinline__ uint32_t boff4(int base_row, int lane) {
    int r = base_row + ((lane >> 4) << 3) + (lane & 7);
    int g = (lane >> 3) & 1;
    return swoff(r, g);
}
// pack two fp32 into bf16x2 hi + residual lo
__device__ __forceinline__ void hl2(float x, float y, uint32_t& h, uint32_t& l) {
    __nv_bfloat162 hh, ll;
    hh.x = __float2bfloat16(x);
    hh.y = __float2bfloat16(y);
    ll.x = __float2bfloat16(x - __bfloat162float(hh.x));
    ll.y = __float2bfloat16(y - __bfloat162float(hh.y));
    h = *(uint32_t*)&hh;
    l = *(uint32_t*)&ll;
}

// ---------------- weight mean(|w|) : stage 1 ----------------
__global__ void reduce_abs_kernel(const float* __restrict__ w0, const float* __restrict__ w1,
                                  const float* __restrict__ w2, float* __restrict__ part) {
    const float* w = (blockIdx.y == 0) ? w0 : ((blockIdx.y == 1) ? w1 : w2);
    int t = threadIdx.x;
    size_t base = (size_t)blockIdx.x * 4096;
    float s = 0.f;
#pragma unroll
    for (int i = 0; i < 16; i++) s += fabsf(w[base + t + i * 256]);
    __shared__ float red[256];
    red[t] = s;
    __syncthreads();
    for (int o = 128; o > 0; o >>= 1) {
        if (t < o) red[t] += red[t + o];
        __syncthreads();
    }
    if (t == 0) part[blockIdx.y * 1024 + blockIdx.x] = red[0];
}

__global__ void finalize_scale_kernel(const float* __restrict__ part, float* __restrict__ scale) {
    int w = blockIdx.x;
    int t = threadIdx.x;
    float s = part[w * 1024 + t] + part[w * 1024 + t + 256] +
              part[w * 1024 + t + 512] + part[w * 1024 + t + 768];
    __shared__ float red[256];
    red[t] = s;
    __syncthreads();
    for (int o = 128; o > 0; o >>= 1) {
        if (t < o) red[t] += red[t + o];
        __syncthreads();
    }
    if (t == 0) {
        float mean = red[0] * (1.0f / ((float)Eq * (float)Eq));
        scale[w] = fmaxf(mean, 1e-5f);
    }
}

// ---------------- ternary weight quantization -> bf16 {-1,0,1} ----------------
__global__ void quant_weight_bf16(const float* __restrict__ w0, const float* __restrict__ w1,
                                  const float* __restrict__ w2, __nv_bfloat16* __restrict__ wq,
                                  const float* __restrict__ scale) {
    int wi = blockIdx.y;
    const float* w = (wi == 0) ? w0 : ((wi == 1) ? w1 : w2);
    float inv = __frcp_rn(scale[wi]);
    size_t e0 = ((size_t)blockIdx.x * 256 + threadIdx.x) * 8;
    __nv_bfloat16* wo = wq + (size_t)wi * Eq * Eq + e0;
#pragma unroll
    for (int i = 0; i < 8; i += 4) {
        float4 v = *(const float4*)&w[e0 + i];
        wo[i + 0] = __float2bfloat16(fminf(fmaxf(rintf(v.x * inv), -1.f), 1.f));
        wo[i + 1] = __float2bfloat16(fminf(fmaxf(rintf(v.y * inv), -1.f), 1.f));
        wo[i + 2] = __float2bfloat16(fminf(fmaxf(rintf(v.z * inv), -1.f), 1.f));
        wo[i + 3] = __float2bfloat16(fminf(fmaxf(rintf(v.w * inv), -1.f), 1.f));
    }
}

// ---------------- per-token absmax quantization (warp per row, no syncs) ----------------
__global__ void quant_act_bf16(const float* __restrict__ x, __nv_bfloat16* __restrict__ xq,
                               float* __restrict__ rows) {
    int w = (blockIdx.x * blockDim.x + threadIdx.x) >> 5;  // one warp per row
    int lane = threadIdx.x & 31;
    const float* xr = x + (size_t)w * Eq;
    float4 v[16];
    float mx = 0.f;
#pragma unroll
    for (int i = 0; i < 16; i++) {
        v[i] = *(const float4*)&xr[i * 128 + lane * 4];
        mx = fmaxf(mx, fmaxf(fmaxf(fabsf(v[i].x), fabsf(v[i].y)),
                             fmaxf(fabsf(v[i].z), fabsf(v[i].w))));
    }
#pragma unroll
    for (int o = 16; o > 0; o >>= 1) mx = fmaxf(mx, __shfl_xor_sync(0xffffffffu, mx, o));
    float s = __fdiv_rn(127.0f, fmaxf(mx, 1e-5f));
    if (lane == 0) rows[w] = s;
    __nv_bfloat16* xo = xq + (size_t)w * Eq;
#pragma unroll
    for (int i = 0; i < 16; i++) {
        __nv_bfloat162 p0, p1;
        p0.x = __float2bfloat16(fminf(fmaxf(rintf(v[i].x * s), -128.f), 127.f));
        p0.y = __float2bfloat16(fminf(fmaxf(rintf(v[i].y * s), -128.f), 127.f));
        p1.x = __float2bfloat16(fminf(fmaxf(rintf(v[i].z * s), -128.f), 127.f));
        p1.y = __float2bfloat16(fminf(fmaxf(rintf(v[i].w * s), -128.f), 127.f));
        *(__nv_bfloat162*)&xo[i * 128 + lane * 4] = p0;
        *(__nv_bfloat162*)&xo[i * 128 + lane * 4 + 2] = p1;
    }
}

// ---------------- fp32 -> split-bf16 K-tripling (row length 2048) ----------------
// mode 0 (A side): [hi | hi | lo]    mode 1 (B side): [hi | lo | hi]
__global__ void split3(const float* __restrict__ X, __nv_bfloat16* __restrict__ Y, int mode) {
    size_t i = (size_t)blockIdx.x * 256 + threadIdx.x;
    size_t row = i >> 11, col = i & 2047;
    float x = X[i];
    __nv_bfloat16 hi = __float2bfloat16(x);
    __nv_bfloat16 lo = __float2bfloat16(x - __bfloat162float(hi));
    __nv_bfloat16* yr = Y + row * (size_t)(3 * Eq);
    yr[col] = hi;
    yr[Eq + col] = mode ? lo : hi;
    yr[2 * Eq + col] = mode ? hi : lo;
}

// ---------------- V fp32 [B,L,E] -> V^T hi/lo [B,H,D,L] ----------------
__global__ void transpose_v(const float* __restrict__ V, __nv_bfloat16* __restrict__ Th,
                            __nv_bfloat16* __restrict__ Tl) {
    __shared__ float s[32][33];
    int l0 = blockIdx.x * 32;
    int e0 = blockIdx.y * 32;
    int b = blockIdx.z;
    int t = threadIdx.x;
    int h = e0 >> 7, d0 = e0 & 127;
#pragma unroll
    for (int i = 0; i < 4; i++) {
        int idx = t + i * 256;
        int lr = idx >> 5, lc = idx & 31;
        s[lr][lc] = V[((size_t)(b * Lq + l0 + lr)) * Eq + e0 + lc];
    }
    __syncthreads();
#pragma unroll
    for (int i = 0; i < 4; i++) {
        int idx = t + i * 256;
        int dr = idx >> 5, dc = idx & 31;
        float f = s[dc][dr];
        __nv_bfloat16 hi = __float2bfloat16(f);
        __nv_bfloat16 lo = __float2bfloat16(f - __bfloat162float(hi));
        size_t o = ((size_t)((b * Hq + h) * Dq + d0 + dr)) * Lq + l0 + dc;
        Th[o] = hi;
        Tl[o] = lo;
    }
}

// ---------------- HMMA bf16 GEMM: cp.async 3-stage, 2 CTAs/SM, z-batched ----------------
struct GArgs {
    const __nv_bfloat16* A;
    const __nv_bfloat16* B;
    float* C;
    const float* rowscale;
    const float* wsp;
    const float* bias;
    int K, Nout, rbi, rbo, roff;
    __nv_bfloat16* Hout;
    __nv_bfloat16* Lout;
};

__global__ __launch_bounds__(256, 2) void hmma_gemm3(GArgs ga0, GArgs ga1, GArgs ga2) {
    GArgs ga = (blockIdx.z == 0) ? ga0 : ((blockIdx.z == 1) ? ga1 : ga2);
    __shared__ __align__(128) uint8_t sA[3][8192];
    __shared__ __align__(128) uint8_t sB[3][8192];
    int t = threadIdx.x;
    int lane = t & 31, wid = t >> 5;
    int m0 = blockIdx.y * 128, n0 = blockIdx.x * 128;
    int warp_m = wid & 1, warp_n = wid >> 1;
    const int K = ga.K;

    int r0 = t >> 2, g0 = t & 3;
    int r1 = 64 + r0;
    const uint4* Ag0 = (const uint4*)(ga.A + (size_t)(m0 + r0) * K) + g0;
    const uint4* Ag1 = (const uint4*)(ga.A + (size_t)(m0 + r1) * K) + g0;
    const uint4* Bg0 = (const uint4*)(ga.B + (size_t)(n0 + r0) * K) + g0;
    const uint4* Bg1 = (const uint4*)(ga.B + (size_t)(n0 + r1) * K) + g0;
    uint32_t st0 = swoff(r0, g0), st1 = swoff(r1, g0);

    uint32_t sAu = smem_u32(sA), sBu = smem_u32(sB);

    uint32_t aaddr[4], baddr4[2];
#pragma unroll
    for (int mi = 0; mi < 4; mi++)
        aaddr[mi] = sAu + swoff(warp_m * 64 + mi * 16 + (lane & 15), lane >> 4);
#pragma unroll
    for (int ni2 = 0; ni2 < 2; ni2++)
        baddr4[ni2] = sBu + boff4(warp_n * 32 + ni2 * 16, lane);

    const int NK = K >> 5;
    {
        cpa16(sAu + st0, Ag0);
        cpa16(sAu + st1, Ag1);
        cpa16(sBu + st0, Bg0);
        cpa16(sBu + st1, Bg1);
        cpa_commit();
    }

    float c[4][4][4];
#pragma unroll
    for (int mi = 0; mi < 4; mi++)
#pragma unroll
        for (int ni = 0; ni < 4; ni++)
#pragma unroll
            for (int k = 0; k < 4; k++) c[mi][ni][k] = 0.f;

    int s = 0;
    for (int kt = 0; kt < NK; ++kt) {
        if (kt + 1 < NK) {
            int sn = (s + 1 == 3) ? 0 : s + 1;
            uint32_t ao = sn * 8192;
            cpa16(sAu + ao + st0, Ag0 + (kt + 1) * 4);
            cpa16(sAu + ao + st1, Ag1 + (kt + 1) * 4);
            cpa16(sBu + ao + st0, Bg0 + (kt + 1) * 4);
            cpa16(sBu + ao + st1, Bg1 + (kt + 1) * 4);
            cpa_commit();
            cpa_wait1();
        } else {
            cpa_wait0();
        }
        __syncthreads();

        uint32_t bofs = s * 8192;
#pragma unroll
        for (int ks = 0; ks < 2; ks++) {
            uint32_t kx = ks * 32;
            uint32_t a[4][4], b[2][4];
#pragma unroll
            for (int mi = 0; mi < 4; mi++) ldmx4(a[mi], (aaddr[mi] + bofs) ^ kx);
#pragma unroll
            for (int ni2 = 0; ni2 < 2; ni2++) ldmx4(b[ni2], (baddr4[ni2] + bofs) ^ kx);
#pragma unroll
            for (int mi = 0; mi < 4; mi++)
#pragma unroll
                for (int ni = 0; ni < 4; ni++)
                    mma16816(c[mi][ni], a[mi], &b[ni >> 1][(ni & 1) * 2]);
        }
        s = (s + 1 == 3) ? 0 : s + 1;
    }

    float ws = ga.wsp ? *ga.wsp : 1.0f;
    int g = lane >> 2, tg = lane & 3;
#pragma unroll
    for (int mi = 0; mi < 4; mi++) {
        int mA = m0 + warp_m * 64 + mi * 16 + g;
        int mB = mA + 8;
        float fA = ga.rowscale ? (ws / ga.rowscale[mA]) : 1.0f;
        float fB = ga.rowscale ? (ws / ga.rowscale[mB]) : 1.0f;
        int oA = (mA / ga.rbi) * ga.rbo + ga.roff + (mA % ga.rbi);
        int oB = (mB / ga.rbi) * ga.rbo + ga.roff + (mB % ga.rbi);
        if (ga.Hout) {
            __nv_bfloat16* hA = ga.Hout + (size_t)oA * ga.Nout;
            __nv_bfloat16* hB = ga.Hout + (size_t)oB * ga.Nout;
            __nv_bfloat16* lA = ga.Lout + (size_t)oA * ga.Nout;
            __nv_bfloat16* lB = ga.Lout + (size_t)oB * ga.Nout;
#pragma unroll
            for (int ni = 0; ni < 4; ni++) {
                int col = n0 + warp_n * 32 + ni * 8 + tg * 2;
                uint32_t h0, l0v, h1, l1v;
                hl2(c[mi][ni][0] * fA, c[mi][ni][1] * fA, h0, l0v);
                hl2(c[mi][ni][2] * fB, c[mi][ni][3] * fB, h1, l1v);
                *(uint32_t*)&hA[col] = h0;
                *(uint32_t*)&lA[col] = l0v;
                *(uint32_t*)&hB[col] = h1;
                *(uint32_t*)&lB[col] = l1v;
            }
        } else {
            float* crA = ga.C + (size_t)oA * ga.Nout;
            float* crB = ga.C + (size_t)oB * ga.Nout;
#pragma unroll
            for (int ni = 0; ni < 4; ni++) {
                int col = n0 + warp_n * 32 + ni * 8 + tg * 2;
                float b0 = 0.f, b1 = 0.f;
                if (ga.bias) { b0 = ga.bias[col]; b1 = ga.bias[col + 1]; }
                float2 vA, vB;
                vA.x = c[mi][ni][0] * fA + b0;
                vA.y = c[mi][ni][1] * fA + b1;
                vB.x = c[mi][ni][2] * fB + b0;
                vB.y = c[mi][ni][3] * fB + b1;
                *(float2*)&crA[col] = vA;
                *(float2*)&crB[col] = vB;
            }
        }
    }
}

// ---------------- FA2-style HMMA flash attention, 3-stage KV, Q in registers ----------------
// smem: 3 stages x 64K (KH 16K | KL 16K | VH 16K | VL 16K). Q preloaded via stage 2.
#define SMEM_ATTN4 (3 * 65536)   // 196608

__global__ __launch_bounds__(256, 1) void attn_mma3(
    const __nv_bfloat16* __restrict__ Qh, const __nv_bfloat16* __restrict__ Ql,
    const __nv_bfloat16* __restrict__ Kh, const __nv_bfloat16* __restrict__ Kl,
    const __nv_bfloat16* __restrict__ Vth, const __nv_bfloat16* __restrict__ Vtl,
    __nv_bfloat16* __restrict__ O3) {
    extern __shared__ char smg[];
    uint32_t sb = smem_u32(smg);
    int t = threadIdx.x;
    int lane = t & 31, wid = t >> 5;
    int qb = blockIdx.x * 128;
    int h = blockIdx.y;
    int b = blockIdx.z;

    const int wm = wid;
    const uint32_t a_off = swoff(wm * 16 + (lane & 15), lane >> 4);
    uint32_t k4[4], v4[8];
#pragma unroll
    for (int ni2 = 0; ni2 < 4; ni2++) k4[ni2] = boff4(ni2 * 16, lane);
#pragma unroll
    for (int ni2 = 0; ni2 < 8; ni2++) v4[ni2] = boff4(ni2 * 16, lane);
    const int g4 = lane >> 2, tg = lane & 3;
    const float SCALE = 0.08838834764831845f;

    // ---- issue Q into stage 2 (group 0) ----
    uint32_t qbase = sb + 2 * 65536;
    {
        const __nv_bfloat16* Qhg = Qh + ((size_t)(b * Sq + qb)) * Eq + h * Dq;
        const __nv_bfloat16* Qlg = Ql + ((size_t)(b * Sq + qb)) * Eq + h * Dq;
#pragma unroll
        for (int i = 0; i < 8; i++) {
            int idx = t + i * 256;
            int r = idx >> 4, g = idx & 15;
            uint32_t dst = (g >> 2) * 8192 + swoff(r, g & 3);
            cpa16(qbase + dst, Qhg + (size_t)r * Eq + g * 8);
            cpa16(qbase + 32768 + dst, Qlg + (size_t)r * Eq + g * 8);
        }
        cpa_commit();
    }

    const __nv_bfloat16* Khb = Kh + ((size_t)(b * Lq)) * Eq + h * Dq;
    const __nv_bfloat16* Klb = Kl + ((size_t)(b * Lq)) * Eq + h * Dq;
    const __nv_bfloat16* Vhb = Vth + ((size_t)((b * Hq + h) * Dq)) * Lq;
    const __nv_bfloat16* Vlb = Vtl + ((size_t)((b * Hq + h) * Dq)) * Lq;

    auto issueKV = [&](int kt) {
        uint32_t base = sb + (kt % 3) * 65536;
        const __nv_bfloat16* KhT = Khb + (size_t)(kt * 64) * Eq;
        const __nv_bfloat16* KlT = Klb + (size_t)(kt * 64) * Eq;
#pragma unroll
        for (int i = 0; i < 4; i++) {
            int idx = t + i * 256;
            int r = idx >> 4, g = idx & 15;
            uint32_t dst = (g >> 2) * 4096 + swoff(r, g & 3);
            cpa16(base + dst, KhT + (size_t)r * Eq + g * 8);
            cpa16(base + 16384 + dst, KlT + (size_t)r * Eq + g * 8);
        }
        const __nv_bfloat16* VhT = Vhb + kt * 64;
        const __nv_bfloat16* VlT = Vlb + kt * 64;
#pragma unroll
        for (int i = 0; i < 4; i++) {
            int idx = t + i * 256;
            int r = idx >> 3, g = idx & 7;
            uint32_t dst = (g >> 2) * 8192 + swoff(r, g & 3);
            cpa16(base + 32768 + dst, VhT + (size_t)r * Lq + g * 8);
            cpa16(base + 49152 + dst, VlT + (size_t)r * Lq + g * 8);
        }
        cpa_commit();
    };
    issueKV(0);          // group 1
    cpa_wait1();         // Q (group 0) complete
    __syncthreads();

    // ---- Q hi/lo fragments -> registers (freed stage 2 for KV tile 2) ----
    uint32_t qfh[4][2][4], qfl[4][2][4];
#pragma unroll
    for (int ch = 0; ch < 4; ch++)
#pragma unroll
        for (int ks = 0; ks < 2; ks++) {
            ldmx4(qfh[ch][ks], qbase + ch * 8192 + (a_off ^ (ks * 32)));
            ldmx4(qfl[ch][ks], qbase + 32768 + ch * 8192 + (a_off ^ (ks * 32)));
        }

    float m0 = -1e30f, m1 = -1e30f, l0 = 0.f, l1 = 0.f;
    float co[16][4];
#pragma unroll
    for (int i = 0; i < 16; i++)
#pragma unroll
        for (int j = 0; j < 4; j++) co[i][j] = 0.f;

    const int NT = Lq / 64;  // 34
    for (int kt = 0; kt < NT; ++kt) {
        // writes stage (kt+1)%3 == stage read at iter kt-2 (done before sync at kt-1) -> safe
        if (kt + 1 < NT) { issueKV(kt + 1); cpa_wait1(); }
        else cpa_wait0();
        __syncthreads();   // the ONLY sync per iteration
        uint32_t kvb = sb + (kt % 3) * 65536;

        // ---- S = Qh.Kh + Qh.Kl + Ql.Kh ----
        float cs[8][4];
#pragma unroll
        for (int i = 0; i < 8; i++)
#pragma unroll
            for (int j = 0; j < 4; j++) cs[i][j] = 0.f;
#pragma unroll
        for (int ch = 0; ch < 4; ch++)
#pragma unroll
            for (int ks = 0; ks < 2; ks++) {
                uint32_t kx = ks * 32;
#pragma unroll
                for (int ni2 = 0; ni2 < 4; ni2++) {
                    uint32_t bh[4], bl[4];
                    uint32_t ba = kvb + ch * 4096 + (k4[ni2] ^ kx);
                    ldmx4(bh, ba);
                    ldmx4(bl, ba + 16384);
                    mma16816(cs[2 * ni2], qfh[ch][ks], bh);
                    mma16816(cs[2 * ni2], qfh[ch][ks], bl);
                    mma16816(cs[2 * ni2], qfl[ch][ks], bh);
                    mma16816(cs[2 * ni2 + 1], qfh[ch][ks], bh + 2);
                    mma16816(cs[2 * ni2 + 1], qfh[ch][ks], bl + 2);
                    mma16816(cs[2 * ni2 + 1], qfl[ch][ks], bh + 2);
                }
            }

        // ---- in-register softmax ----
        float tm0 = -1e30f, tm1 = -1e30f;
#pragma unroll
        for (int ni = 0; ni < 8; ni++) {
            cs[ni][0] *= SCALE; cs[ni][1] *= SCALE;
            cs[ni][2] *= SCALE; cs[ni][3] *= SCALE;
            tm0 = fmaxf(tm0, fmaxf(cs[ni][0], cs[ni][1]));
            tm1 = fmaxf(tm1, fmaxf(cs[ni][2], cs[ni][3]));
        }
        tm0 = fmaxf(tm0, __shfl_xor_sync(0xffffffffu, tm0, 1));
        tm0 = fmaxf(tm0, __shfl_xor_sync(0xffffffffu, tm0, 2));
        tm1 = fmaxf(tm1, __shfl_xor_sync(0xffffffffu, tm1, 1));
        tm1 = fmaxf(tm1, __shfl_xor_sync(0xffffffffu, tm1, 2));
        float nm0 = fmaxf(m0, tm0), nm1 = fmaxf(m1, tm1);
        float al0 = __expf(m0 - nm0), al1 = __expf(m1 - nm1);
        m0 = nm0; m1 = nm1;

        float rs0 = 0.f, rs1 = 0.f;
#pragma unroll
        for (int ni = 0; ni < 8; ni++) {
            cs[ni][0] = __expf(cs[ni][0] - m0); rs0 += cs[ni][0];
            cs[ni][1] = __expf(cs[ni][1] - m0); rs0 += cs[ni][1];
            cs[ni][2] = __expf(cs[ni][2] - m1); rs1 += cs[ni][2];
            cs[ni][3] = __expf(cs[ni][3] - m1); rs1 += cs[ni][3];
        }
        rs0 += __shfl_xor_sync(0xffffffffu, rs0, 1);
        rs0 += __shfl_xor_sync(0xffffffffu, rs0, 2);
        rs1 += __shfl_xor_sync(0xffffffffu, rs1, 1);
        rs1 += __shfl_xor_sync(0xffffffffu, rs1, 2);
        l0 = l0 * al0 + rs0;
        l1 = l1 * al1 + rs1;

        // ---- P hi/lo A-fragments ----
        uint32_t phf[4][4], plf[4][4];
#pragma unroll
        for (int ck = 0; ck < 4; ck++) {
            hl2(cs[2 * ck][0], cs[2 * ck][1], phf[ck][0], plf[ck][0]);
            hl2(cs[2 * ck][2], cs[2 * ck][3], phf[ck][1], plf[ck][1]);
            hl2(cs[2 * ck + 1][0], cs[2 * ck + 1][1], phf[ck][2], plf[ck][2]);
            hl2(cs[2 * ck + 1][2], cs[2 * ck + 1][3], phf[ck][3], plf[ck][3]);
        }

        // ---- rescale O ----
#pragma unroll
        for (int ni = 0; ni < 16; ni++) {
            co[ni][0] *= al0; co[ni][1] *= al0;
            co[ni][2] *= al1; co[ni][3] *= al1;
        }

        // ---- O += Ph.Vh + Ph.Vl + Pl.Vh ----
#pragma unroll
        for (int ck = 0; ck < 4; ck++) {
#pragma unroll
            for (int ni2 = 0; ni2 < 8; ni2++) {
                uint32_t bh[4], bl[4];
                uint32_t ba = kvb + 32768 + (ck >> 1) * 8192 + (v4[ni2] ^ ((ck & 1) * 32));
                ldmx4(bh, ba);
                ldmx4(bl, ba + 16384);
                mma16816(co[2 * ni2], phf[ck], bh);
                mma16816(co[2 * ni2], phf[ck], bl);
                mma16816(co[2 * ni2], plf[ck], bh);
                mma16816(co[2 * ni2 + 1], phf[ck], bh + 2);
                mma16816(co[2 * ni2 + 1], phf[ck], bl + 2);
                mma16816(co[2 * ni2 + 1], plf[ck], bh + 2);
            }
        }
    }

    // ---- epilogue: write O split [hi|hi|lo] ----
    float il0 = 1.0f / l0, il1 = 1.0f / l1;
    int r0 = wm * 16 + g4, r1 = r0 + 8;
    __nv_bfloat16* O0 = O3 + ((size_t)(b * Sq + qb + r0)) * (3 * Eq) + h * Dq;
    __nv_bfloat16* O1 = O3 + ((size_t)(b * Sq + qb + r1)) * (3 * Eq) + h * Dq;
#pragma unroll
    for (int ni = 0; ni < 16; ni++) {
        int col = ni * 8 + tg * 2;
        uint32_t h0, lo0, h1, lo1;
        hl2(co[ni][0] * il0, co[ni][1] * il0, h0, lo0);
        hl2(co[ni][2] * il1, co[ni][3] * il1, h1, lo1);
        *(uint32_t*)(O0 + col) = h0;
        *(uint32_t*)(O0 + Eq + col) = h0;
        *(uint32_t*)(O0 + 2 * Eq + col) = lo0;
        *(uint32_t*)(O1 + col) = h1;
        *(uint32_t*)(O1 + Eq + col) = h1;
        *(uint32_t*)(O1 + 2 * Eq + col) = lo1;
    }
}

// ---------------- host launcher ----------------
extern "C" void kernel_launch(void* const* d_in, const int* in_sizes, int n_in,
                              void* d_out, int out_size) {
    const float* x  = (const float*)d_in[0];
    const float* rt = (const float*)d_in[1];
    const float* qw = (const float*)d_in[2];
    const float* kw = (const float*)d_in[3];
    const float* vw = (const float*)d_in[4];
    const float* ow = (const float*)d_in[5];
    const float* ob = (const float*)d_in[6];
    float* out = (float*)d_out;

    __nv_bfloat16 *xbf, *wbf, *rt3, *kw3, *vw3, *ow3, *ao3, *qh, *ql, *kh, *kl, *vth, *vtl;
    float *rows, *vb, *part, *scale;
    cudaGetSymbolAddress((void**)&xbf, g_xbf);
    cudaGetSymbolAddress((void**)&wbf, g_wbf);
    cudaGetSymbolAddress((void**)&rt3, g_rt3);
    cudaGetSymbolAddress((void**)&kw3, g_kw3);
    cudaGetSymbolAddress((void**)&vw3, g_vw3);
    cudaGetSymbolAddress((void**)&ow3, g_ow3);
    cudaGetSymbolAddress((void**)&ao3, g_ao3);
    cudaGetSymbolAddress((void**)&qh, g_qh);
    cudaGetSymbolAddress((void**)&ql, g_ql);
    cudaGetSymbolAddress((void**)&kh, g_kh);
    cudaGetSymbolAddress((void**)&kl, g_kl);
    cudaGetSymbolAddress((void**)&vth, g_vth);
    cudaGetSymbolAddress((void**)&vtl, g_vtl);
    cudaGetSymbolAddress((void**)&rows, g_rows);
    cudaGetSymbolAddress((void**)&vb, g_vb);
    cudaGetSymbolAddress((void**)&part, g_part);
    cudaGetSymbolAddress((void**)&scale, g_scale);

    cudaFuncSetAttribute(attn_mma3, cudaFuncAttributeMaxDynamicSharedMemorySize, SMEM_ATTN4);

    // 1) weight scales
    reduce_abs_kernel<<<dim3(1024, 3), 256>>>(qw, kw, vw, part);
    finalize_scale_kernel<<<3, 256>>>(part, scale);
    // 2) quantize to bf16 (exact integer/ternary values)
    quant_weight_bf16<<<dim3(2048, 3), 256>>>(qw, kw, vw, wbf, scale);
    quant_act_bf16<<<(Bq * Sq) / 8, 256>>>(x, xbf, rows);
    // 3) split unquantized operands (K-tripled bf16)
    split3<<<(Eq * Eq) / 256, 256>>>(kw, kw3, 1);
    split3<<<(Eq * Eq) / 256, 256>>>(vw, vw3, 1);
    split3<<<(Eq * Eq) / 256, 256>>>(ow, ow3, 1);
    split3<<<(Bq * Rq * Eq) / 256, 256>>>(rt, rt3, 0);
    // 4) Q/K/V projections in ONE launch (z = 0/1/2)
    size_t EE = (size_t)Eq * Eq;
    GArgs gQ = { xbf, wbf + 0 * EE, nullptr, rows, scale + 0, nullptr,
                 Eq, Eq, Sq, Sq, 0, qh, ql };
    GArgs gK = { xbf, wbf + 1 * EE, nullptr, rows, scale + 1, nullptr,
                 Eq, Eq, Sq, Lq, 0, kh, kl };
    GArgs gV = { xbf, wbf + 2 * EE, vb, rows, scale + 2, nullptr,
                 Eq, Eq, Sq, Lq, 0, nullptr, nullptr };
    hmma_gemm3<<<dim3(16, 32, 3), 256>>>(gQ, gK, gV);
    // 5) reasoning projections (K=6144) in one launch (z = 0/1)
    GArgs gRK = { rt3, kw3, nullptr, nullptr, nullptr, nullptr,
                  3 * Eq, Eq, Rq, Lq, Sq, kh, kl };
    GArgs gRV = { rt3, vw3, vb, nullptr, nullptr, nullptr,
                  3 * Eq, Eq, Rq, Lq, Sq, nullptr, nullptr };
    hmma_gemm3<<<dim3(16, 2, 2), 256>>>(gRK, gRV, gRV);
    // 6) transpose+split V
    transpose_v<<<dim3(Lq / 32, Eq / 32, Bq), 256>>>(vb, vth, vtl);
    // 7) attention (3-stage KV pipeline, Q in registers) -> writes [hi|hi|lo]
    attn_mma3<<<dim3(Sq / 128, Hq, Bq), 256, SMEM_ATTN4>>>(qh, ql, kh, kl, vth, vtl, ao3);
    // 8) output projection + bias
    GArgs gO = { ao3, ow3, out, nullptr, nullptr, ob,
                 3 * Eq, Eq, Bq * Sq, Bq * Sq, 0, nullptr, nullptr };
    hmma_gemm3<<<dim3(16, 32, 1), 256>>>(gO, gO, gO);
}

// round 9
// speedup vs baseline: 10.8979x; 1.0390x over previous
#include <cuda_runtime.h>
#include <cuda_bf16.h>
#include <cstdint>

#define Bq 2
#define Sq 2048
#define Rq 128
#define Eq 2048
#define Hq 16
#define Dq 128
#define Lq (Sq + Rq)   // 2176

// ---------------- scratch (device globals, no allocations) ----------------
__device__ __nv_bfloat16 g_xbf[(size_t)Bq * Sq * Eq];      // quantized acts as bf16 ints
__device__ __nv_bfloat16 g_wbf[3][(size_t)Eq * Eq];        // ternary weights as bf16
__device__ __nv_bfloat16 g_rt3[(size_t)Bq * Rq * 3 * Eq];  // reasoning tokens split [hi|hi|lo]
__device__ __nv_bfloat16 g_kw3[(size_t)Eq * 3 * Eq];       // k_w split [hi|lo|hi]
__device__ __nv_bfloat16 g_vw3[(size_t)Eq * 3 * Eq];       // v_w split
__device__ __nv_bfloat16 g_ow3[(size_t)Eq * 3 * Eq];       // out_w split
__device__ __nv_bfloat16 g_ao3[(size_t)Bq * Sq * 3 * Eq];  // attn out split [hi|hi|lo]
__device__ __nv_bfloat16 g_qh[(size_t)Bq * Sq * Eq];       // Q hi
__device__ __nv_bfloat16 g_ql[(size_t)Bq * Sq * Eq];       // Q lo
__device__ __nv_bfloat16 g_kh[(size_t)Bq * Lq * Eq];       // K hi
__device__ __nv_bfloat16 g_kl[(size_t)Bq * Lq * Eq];       // K lo
__device__ __nv_bfloat16 g_vth[(size_t)Bq * Hq * Dq * Lq]; // V^T hi [B,H,D,L]
__device__ __nv_bfloat16 g_vtl[(size_t)Bq * Hq * Dq * Lq]; // V^T lo
__device__ float g_rows[(size_t)Bq * Sq];                  // per-row act scale s
__device__ float g_vb[(size_t)Bq * Lq * Eq];               // V fp32
__device__ float g_part[3 * 1024];
__device__ float g_scale[3];

// ---------------- PTX helpers ----------------
typedef unsigned long long ull;
__device__ __forceinline__ uint32_t smem_u32(const void* p) {
    uint32_t a;
    asm("{ .reg .u64 t; cvta.to.shared.u64 t, %1; cvt.u32.u64 %0, t; }" : "=r"(a) : "l"(p));
    return a;
}
__device__ __forceinline__ void ldmx4(uint32_t* r, uint32_t addr) {
    asm volatile("ldmatrix.sync.aligned.m8n8.x4.shared.b16 {%0,%1,%2,%3}, [%4];"
                 : "=r"(r[0]), "=r"(r[1]), "=r"(r[2]), "=r"(r[3]) : "r"(addr));
}
__device__ __forceinline__ void mma16816(float* c, const uint32_t* a, const uint32_t* b) {
    asm volatile("mma.sync.aligned.m16n8k16.row.col.f32.bf16.bf16.f32 "
                 "{%0,%1,%2,%3}, {%4,%5,%6,%7}, {%8,%9}, {%0,%1,%2,%3};"
                 : "+f"(c[0]), "+f"(c[1]), "+f"(c[2]), "+f"(c[3])
                 : "r"(a[0]), "r"(a[1]), "r"(a[2]), "r"(a[3]), "r"(b[0]), "r"(b[1]));
}
__device__ __forceinline__ void cpa16(uint32_t dst, const void* src) {
    asm volatile("cp.async.cg.shared.global [%0], [%1], 16;" :: "r"(dst), "l"(src) : "memory");
}
__device__ __forceinline__ void cpa_commit() {
    asm volatile("cp.async.commit_group;" ::: "memory");
}
__device__ __forceinline__ void cpa_wait0() {
    asm volatile("cp.async.wait_group 0;" ::: "memory");
}
__device__ __forceinline__ void cpa_wait1() {
    asm volatile("cp.async.wait_group 1;" ::: "memory");
}
// smem rows of 32 bf16 (64B); 16B group g stored at g ^ ((row>>1)&3)
__device__ __forceinline__ uint32_t swoff(int r, int g) {
    return (uint32_t)(r * 64 + ((g ^ ((r >> 1) & 3)) << 4));
}
// per-lane address offset for B-side ldmatrix.x4 (2 consecutive n-frags of 8 rows)
__device__ __forceinline__ uint32_t boff4(int base_row, int lane) {
    int r = base_row + ((lane >> 4) << 3) + (lane & 7);
    int g = (lane >> 3) & 1;
    return swoff(r, g);
}
// pack two fp32 into bf16x2 hi + residual lo
__device__ __forceinline__ void hl2(float x, float y, uint32_t& h, uint32_t& l) {
    __nv_bfloat162 hh, ll;
    hh.x = __float2bfloat16(x);
    hh.y = __float2bfloat16(y);
    ll.x = __float2bfloat16(x - __bfloat162float(hh.x));
    ll.y = __float2bfloat16(y - __bfloat162float(hh.y));
    h = *(uint32_t*)&hh;
    l = *(uint32_t*)&ll;
}

// ---------------- weight mean(|w|) : stage 1 ----------------
__global__ void reduce_abs_kernel(const float* __restrict__ w0, const float* __restrict__ w1,
                                  const float* __restrict__ w2, float* __restrict__ part) {
    const float* w = (blockIdx.y == 0) ? w0 : ((blockIdx.y == 1) ? w1 : w2);
    int t = threadIdx.x;
    size_t base = (size_t)blockIdx.x * 4096;
    float s = 0.f;
#pragma unroll
    for (int i = 0; i < 16; i++) s += fabsf(w[base + t + i * 256]);
    __shared__ float red[256];
    red[t] = s;
    __syncthreads();
    for (int o = 128; o > 0; o >>= 1) {
        if (t < o) red[t] += red[t + o];
        __syncthreads();
    }
    if (t == 0) part[blockIdx.y * 1024 + blockIdx.x] = red[0];
}

__global__ void finalize_scale_kernel(const float* __restrict__ part, float* __restrict__ scale) {
    int w = blockIdx.x;
    int t = threadIdx.x;
    float s = part[w * 1024 + t] + part[w * 1024 + t + 256] +
              part[w * 1024 + t + 512] + part[w * 1024 + t + 768];
    __shared__ float red[256];
    red[t] = s;
    __syncthreads();
    for (int o = 128; o > 0; o >>= 1) {
        if (t < o) red[t] += red[t + o];
        __syncthreads();
    }
    if (t == 0) {
        float mean = red[0] * (1.0f / ((float)Eq * (float)Eq));
        scale[w] = fmaxf(mean, 1e-5f);
    }
}

// ---------------- merged weight prep: ternary (q/k/v) + split3 mode-1 (k/v/o) ----------------
__global__ void prep_weights(const float* __restrict__ qw, const float* __restrict__ kw,
                             const float* __restrict__ vw, const float* __restrict__ ow,
                             __nv_bfloat16* __restrict__ wq,
                             __nv_bfloat16* __restrict__ kw3, __nv_bfloat16* __restrict__ vw3,
                             __nv_bfloat16* __restrict__ ow3,
                             const float* __restrict__ scale) {
    int wi = blockIdx.y;
    const float* w = (wi == 0) ? qw : ((wi == 1) ? kw : ((wi == 2) ? vw : ow));
    float inv = (wi < 3) ? __frcp_rn(scale[wi]) : 0.f;
    size_t e0 = ((size_t)blockIdx.x * 256 + threadIdx.x) * 8;
    size_t row = e0 >> 11, col = e0 & 2047;
    __nv_bfloat16* wo = (wi < 3) ? (wq + (size_t)wi * Eq * Eq + e0) : nullptr;
    __nv_bfloat16* y = (wi == 1) ? kw3 : ((wi == 2) ? vw3 : ((wi == 3) ? ow3 : nullptr));
    __nv_bfloat16* yr = y ? (y + row * (size_t)(3 * Eq)) : nullptr;
#pragma unroll
    for (int i = 0; i < 8; i += 4) {
        float4 v = *(const float4*)&w[e0 + i];
        float f[4] = {v.x, v.y, v.z, v.w};
#pragma unroll
        for (int j = 0; j < 4; j++) {
            if (wo)
                wo[i + j] = __float2bfloat16(fminf(fmaxf(rintf(f[j] * inv), -1.f), 1.f));
            if (yr) {
                __nv_bfloat16 hi = __float2bfloat16(f[j]);
                __nv_bfloat16 lo = __float2bfloat16(f[j] - __bfloat162float(hi));
                yr[col + i + j] = hi;
                yr[Eq + col + i + j] = lo;
                yr[2 * Eq + col + i + j] = hi;
            }
        }
    }
}

// ---------------- per-token absmax quantization (warp per row, no syncs) ----------------
__global__ void quant_act_bf16(const float* __restrict__ x, __nv_bfloat16* __restrict__ xq,
                               float* __restrict__ rows) {
    int w = (blockIdx.x * blockDim.x + threadIdx.x) >> 5;  // one warp per row
    int lane = threadIdx.x & 31;
    const float* xr = x + (size_t)w * Eq;
    float4 v[16];
    float mx = 0.f;
#pragma unroll
    for (int i = 0; i < 16; i++) {
        v[i] = *(const float4*)&xr[i * 128 + lane * 4];
        mx = fmaxf(mx, fmaxf(fmaxf(fabsf(v[i].x), fabsf(v[i].y)),
                             fmaxf(fabsf(v[i].z), fabsf(v[i].w))));
    }
#pragma unroll
    for (int o = 16; o > 0; o >>= 1) mx = fmaxf(mx, __shfl_xor_sync(0xffffffffu, mx, o));
    float s = __fdiv_rn(127.0f, fmaxf(mx, 1e-5f));
    if (lane == 0) rows[w] = s;
    __nv_bfloat16* xo = xq + (size_t)w * Eq;
#pragma unroll
    for (int i = 0; i < 16; i++) {
        __nv_bfloat162 p0, p1;
        p0.x = __float2bfloat16(fminf(fmaxf(rintf(v[i].x * s), -128.f), 127.f));
        p0.y = __float2bfloat16(fminf(fmaxf(rintf(v[i].y * s), -128.f), 127.f));
        p1.x = __float2bfloat16(fminf(fmaxf(rintf(v[i].z * s), -128.f), 127.f));
        p1.y = __float2bfloat16(fminf(fmaxf(rintf(v[i].w * s), -128.f), 127.f));
        *(__nv_bfloat162*)&xo[i * 128 + lane * 4] = p0;
        *(__nv_bfloat162*)&xo[i * 128 + lane * 4 + 2] = p1;
    }
}

// ---------------- fp32 -> split-bf16 K-tripling, A side [hi|hi|lo] ----------------
__global__ void split3a(const float* __restrict__ X, __nv_bfloat16* __restrict__ Y) {
    size_t i = (size_t)blockIdx.x * 256 + threadIdx.x;
    size_t row = i >> 11, col = i & 2047;
    float x = X[i];
    __nv_bfloat16 hi = __float2bfloat16(x);
    __nv_bfloat16 lo = __float2bfloat16(x - __bfloat162float(hi));
    __nv_bfloat16* yr = Y + row * (size_t)(3 * Eq);
    yr[col] = hi;
    yr[Eq + col] = hi;
    yr[2 * Eq + col] = lo;
}

// ---------------- V fp32 [B,L,E] -> V^T hi/lo [B,H,D,L] ----------------
__global__ void transpose_v(const float* __restrict__ V, __nv_bfloat16* __restrict__ Th,
                            __nv_bfloat16* __restrict__ Tl) {
    __shared__ float s[32][33];
    int l0 = blockIdx.x * 32;
    int e0 = blockIdx.y * 32;
    int b = blockIdx.z;
    int t = threadIdx.x;
    int h = e0 >> 7, d0 = e0 & 127;
#pragma unroll
    for (int i = 0; i < 4; i++) {
        int idx = t + i * 256;
        int lr = idx >> 5, lc = idx & 31;
        s[lr][lc] = V[((size_t)(b * Lq + l0 + lr)) * Eq + e0 + lc];
    }
    __syncthreads();
#pragma unroll
    for (int i = 0; i < 4; i++) {
        int idx = t + i * 256;
        int dr = idx >> 5, dc = idx & 31;
        float f = s[dc][dr];
        __nv_bfloat16 hi = __float2bfloat16(f);
        __nv_bfloat16 lo = __float2bfloat16(f - __bfloat162float(hi));
        size_t o = ((size_t)((b * Hq + h) * Dq + d0 + dr)) * Lq + l0 + dc;
        Th[o] = hi;
        Tl[o] = lo;
    }
}

// ---------------- HMMA bf16 GEMM: cp.async 3-stage, BK=64, 2 CTAs/SM, z-batched ----------------
struct GArgs {
    const __nv_bfloat16* A;
    const __nv_bfloat16* B;
    float* C;
    const float* rowscale;
    const float* wsp;
    const float* bias;
    int K, Nout, rbi, rbo, roff, ylim;
    __nv_bfloat16* Hout;
    __nv_bfloat16* Lout;
};

// dynamic smem: 3 stages x (A 16K | B 16K) = 96 KB
#define SMEM_GEMM5 98304

__global__ __launch_bounds__(256, 2) void hmma_gemm5(GArgs ga0, GArgs ga1, GArgs ga2,
                                                     GArgs ga3, GArgs ga4) {
    int z = blockIdx.z;
    GArgs ga = (z == 0) ? ga0 : ((z == 1) ? ga1 : ((z == 2) ? ga2 : ((z == 3) ? ga3 : ga4)));
    if ((int)blockIdx.y >= ga.ylim) return;
    extern __shared__ __align__(128) uint8_t dsm[];
    uint32_t sb = smem_u32(dsm);
    int t = threadIdx.x;
    int lane = t & 31, wid = t >> 5;
    int m0 = blockIdx.y * 128, n0 = blockIdx.x * 128;
    int warp_m = wid & 1, warp_n = wid >> 1;
    const int K = ga.K;

    // cp.async mapping: tile 128 rows x 128 B (2 chunks of 64 B); 1024 groups of 16 B
    const uint8_t* asrc[4];
    const uint8_t* bsrc[4];
    uint32_t gdst[4];
#pragma unroll
    for (int i = 0; i < 4; i++) {
        int idx = t + i * 256;
        int r = idx >> 3, g = idx & 7;
        gdst[i] = (g >> 2) * 8192 + swoff(r, g & 3);
        asrc[i] = (const uint8_t*)(ga.A + (size_t)(m0 + r) * K) + g * 16;
        bsrc[i] = (const uint8_t*)(ga.B + (size_t)(n0 + r) * K) + g * 16;
    }

    uint32_t aaddr[4], baddr4[2];
#pragma unroll
    for (int mi = 0; mi < 4; mi++)
        aaddr[mi] = swoff(warp_m * 64 + mi * 16 + (lane & 15), lane >> 4);
#pragma unroll
    for (int ni2 = 0; ni2 < 2; ni2++)
        baddr4[ni2] = boff4(warp_n * 32 + ni2 * 16, lane);

    const int NK = K >> 6;
    {
#pragma unroll
        for (int i = 0; i < 4; i++) {
            cpa16(sb + gdst[i], asrc[i]);
            cpa16(sb + 16384 + gdst[i], bsrc[i]);
        }
        cpa_commit();
    }

    float c[4][4][4];
#pragma unroll
    for (int mi = 0; mi < 4; mi++)
#pragma unroll
        for (int ni = 0; ni < 4; ni++)
#pragma unroll
            for (int k = 0; k < 4; k++) c[mi][ni][k] = 0.f;

    int s = 0;
    for (int kt = 0; kt < NK; ++kt) {
        if (kt + 1 < NK) {
            int sn = (s + 1 == 3) ? 0 : s + 1;
            uint32_t base = sb + sn * 32768;
            size_t koff = (size_t)(kt + 1) * 128;
#pragma unroll
            for (int i = 0; i < 4; i++) {
                cpa16(base + gdst[i], asrc[i] + koff);
                cpa16(base + 16384 + gdst[i], bsrc[i] + koff);
            }
            cpa_commit();
            cpa_wait1();
        } else {
            cpa_wait0();
        }
        __syncthreads();

        uint32_t Ab = sb + s * 32768;
        uint32_t Bb = Ab + 16384;
#pragma unroll
        for (int ch = 0; ch < 2; ch++)
#pragma unroll
            for (int ks = 0; ks < 2; ks++) {
                uint32_t kx = ks * 32;
                uint32_t a[4][4], b[2][4];
#pragma unroll
                for (int mi = 0; mi < 4; mi++)
                    ldmx4(a[mi], Ab + ch * 8192 + (aaddr[mi] ^ kx));
#pragma unroll
                for (int ni2 = 0; ni2 < 2; ni2++)
                    ldmx4(b[ni2], Bb + ch * 8192 + (baddr4[ni2] ^ kx));
#pragma unroll
                for (int mi = 0; mi < 4; mi++)
#pragma unroll
                    for (int ni = 0; ni < 4; ni++)
                        mma16816(c[mi][ni], a[mi], &b[ni >> 1][(ni & 1) * 2]);
            }
        s = (s + 1 == 3) ? 0 : s + 1;
    }

    float ws = ga.wsp ? *ga.wsp : 1.0f;
    int g = lane >> 2, tg = lane & 3;
#pragma unroll
    for (int mi = 0; mi < 4; mi++) {
        int mA = m0 + warp_m * 64 + mi * 16 + g;
        int mB = mA + 8;
        float fA = ga.rowscale ? (ws / ga.rowscale[mA]) : 1.0f;
        float fB = ga.rowscale ? (ws / ga.rowscale[mB]) : 1.0f;
        int oA = (mA / ga.rbi) * ga.rbo + ga.roff + (mA % ga.rbi);
        int oB = (mB / ga.rbi) * ga.rbo + ga.roff + (mB % ga.rbi);
        if (ga.Hout) {
            __nv_bfloat16* hA = ga.Hout + (size_t)oA * ga.Nout;
            __nv_bfloat16* hB = ga.Hout + (size_t)oB * ga.Nout;
            __nv_bfloat16* lA = ga.Lout + (size_t)oA * ga.Nout;
            __nv_bfloat16* lB = ga.Lout + (size_t)oB * ga.Nout;
#pragma unroll
            for (int ni = 0; ni < 4; ni++) {
                int col = n0 + warp_n * 32 + ni * 8 + tg * 2;
                uint32_t h0, l0v, h1, l1v;
                hl2(c[mi][ni][0] * fA, c[mi][ni][1] * fA, h0, l0v);
                hl2(c[mi][ni][2] * fB, c[mi][ni][3] * fB, h1, l1v);
                *(uint32_t*)&hA[col] = h0;
                *(uint32_t*)&lA[col] = l0v;
                *(uint32_t*)&hB[col] = h1;
                *(uint32_t*)&lB[col] = l1v;
            }
        } else {
            float* crA = ga.C + (size_t)oA * ga.Nout;
            float* crB = ga.C + (size_t)oB * ga.Nout;
#pragma unroll
            for (int ni = 0; ni < 4; ni++) {
                int col = n0 + warp_n * 32 + ni * 8 + tg * 2;
                float b0 = 0.f, b1 = 0.f;
                if (ga.bias) { b0 = ga.bias[col]; b1 = ga.bias[col + 1]; }
                float2 vA, vB;
                vA.x = c[mi][ni][0] * fA + b0;
                vA.y = c[mi][ni][1] * fA + b1;
                vB.x = c[mi][ni][2] * fB + b0;
                vB.y = c[mi][ni][3] * fB + b1;
                *(float2*)&crA[col] = vA;
                *(float2*)&crB[col] = vB;
            }
        }
    }
}

// ---------------- FA2-style HMMA flash attention, 3-stage KV, Q in registers ----------------
// smem: 3 stages x 64K (KH 16K | KL 16K | VH 16K | VL 16K). Q preloaded via stage 2.
#define SMEM_ATTN4 (3 * 65536)   // 196608

__global__ __launch_bounds__(256, 1) void attn_mma3(
    const __nv_bfloat16* __restrict__ Qh, const __nv_bfloat16* __restrict__ Ql,
    const __nv_bfloat16* __restrict__ Kh, const __nv_bfloat16* __restrict__ Kl,
    const __nv_bfloat16* __restrict__ Vth, const __nv_bfloat16* __restrict__ Vtl,
    __nv_bfloat16* __restrict__ O3) {
    extern __shared__ char smg[];
    uint32_t sb = smem_u32(smg);
    int t = threadIdx.x;
    int lane = t & 31, wid = t >> 5;
    int qb = blockIdx.x * 128;
    int h = blockIdx.y;
    int b = blockIdx.z;

    const int wm = wid;
    const uint32_t a_off = swoff(wm * 16 + (lane & 15), lane >> 4);
    uint32_t k4[4], v4[8];
#pragma unroll
    for (int ni2 = 0; ni2 < 4; ni2++) k4[ni2] = boff4(ni2 * 16, lane);
#pragma unroll
    for (int ni2 = 0; ni2 < 8; ni2++) v4[ni2] = boff4(ni2 * 16, lane);
    const int g4 = lane >> 2, tg = lane & 3;
    const float SCALE = 0.08838834764831845f;

    // ---- issue Q into stage 2 (group 0) ----
    uint32_t qbase = sb + 2 * 65536;
    {
        const __nv_bfloat16* Qhg = Qh + ((size_t)(b * Sq + qb)) * Eq + h * Dq;
        const __nv_bfloat16* Qlg = Ql + ((size_t)(b * Sq + qb)) * Eq + h * Dq;
#pragma unroll
        for (int i = 0; i < 8; i++) {
            int idx = t + i * 256;
            int r = idx >> 4, g = idx & 15;
            uint32_t dst = (g >> 2) * 8192 + swoff(r, g & 3);
            cpa16(qbase + dst, Qhg + (size_t)r * Eq + g * 8);
            cpa16(qbase + 32768 + dst, Qlg + (size_t)r * Eq + g * 8);
        }
        cpa_commit();
    }

    const __nv_bfloat16* Khb = Kh + ((size_t)(b * Lq)) * Eq + h * Dq;
    const __nv_bfloat16* Klb = Kl + ((size_t)(b * Lq)) * Eq + h * Dq;
    const __nv_bfloat16* Vhb = Vth + ((size_t)((b * Hq + h) * Dq)) * Lq;
    const __nv_bfloat16* Vlb = Vtl + ((size_t)((b * Hq + h) * Dq)) * Lq;

    auto issueKV = [&](int kt) {
        uint32_t base = sb + (kt % 3) * 65536;
        const __nv_bfloat16* KhT = Khb + (size_t)(kt * 64) * Eq;
        const __nv_bfloat16* KlT = Klb + (size_t)(kt * 64) * Eq;
#pragma unroll
        for (int i = 0; i < 4; i++) {
            int idx = t + i * 256;
            int r = idx >> 4, g = idx & 15;
            uint32_t dst = (g >> 2) * 4096 + swoff(r, g & 3);
            cpa16(base + dst, KhT + (size_t)r * Eq + g * 8);
            cpa16(base + 16384 + dst, KlT + (size_t)r * Eq + g * 8);
        }
        const __nv_bfloat16* VhT = Vhb + kt * 64;
        const __nv_bfloat16* VlT = Vlb + kt * 64;
#pragma unroll
        for (int i = 0; i < 4; i++) {
            int idx = t + i * 256;
            int r = idx >> 3, g = idx & 7;
            uint32_t dst = (g >> 2) * 8192 + swoff(r, g & 3);
            cpa16(base + 32768 + dst, VhT + (size_t)r * Lq + g * 8);
            cpa16(base + 49152 + dst, VlT + (size_t)r * Lq + g * 8);
        }
        cpa_commit();
    };
    issueKV(0);          // group 1
    cpa_wait1();         // Q (group 0) complete
    __syncthreads();

    // ---- Q hi/lo fragments -> registers (freed stage 2 for KV tile 2) ----
    uint32_t qfh[4][2][4], qfl[4][2][4];
#pragma unroll
    for (int ch = 0; ch < 4; ch++)
#pragma unroll
        for (int ks = 0; ks < 2; ks++) {
            ldmx4(qfh[ch][ks], qbase + ch * 8192 + (a_off ^ (ks * 32)));
            ldmx4(qfl[ch][ks], qbase + 32768 + ch * 8192 + (a_off ^ (ks * 32)));
        }

    float m0 = -1e30f, m1 = -1e30f, l0 = 0.f, l1 = 0.f;
    float co[16][4];
#pragma unroll
    for (int i = 0; i < 16; i++)
#pragma unroll
        for (int j = 0; j < 4; j++) co[i][j] = 0.f;

    const int NT = Lq / 64;  // 34
    for (int kt = 0; kt < NT; ++kt) {
        if (kt + 1 < NT) { issueKV(kt + 1); cpa_wait1(); }
        else cpa_wait0();
        __syncthreads();   // the ONLY sync per iteration
        uint32_t kvb = sb + (kt % 3) * 65536;

        // ---- S = Qh.Kh + Qh.Kl + Ql.Kh ----
        float cs[8][4];
#pragma unroll
        for (int i = 0; i < 8; i++)
#pragma unroll
            for (int j = 0; j < 4; j++) cs[i][j] = 0.f;
#pragma unroll
        for (int ch = 0; ch < 4; ch++)
#pragma unroll
            for (int ks = 0; ks < 2; ks++) {
                uint32_t kx = ks * 32;
#pragma unroll
                for (int ni2 = 0; ni2 < 4; ni2++) {
                    uint32_t bh[4], bl[4];
                    uint32_t ba = kvb + ch * 4096 + (k4[ni2] ^ kx);
                    ldmx4(bh, ba);
                    ldmx4(bl, ba + 16384);
                    mma16816(cs[2 * ni2], qfh[ch][ks], bh);
                    mma16816(cs[2 * ni2], qfh[ch][ks], bl);
                    mma16816(cs[2 * ni2], qfl[ch][ks], bh);
                    mma16816(cs[2 * ni2 + 1], qfh[ch][ks], bh + 2);
                    mma16816(cs[2 * ni2 + 1], qfh[ch][ks], bl + 2);
                    mma16816(cs[2 * ni2 + 1], qfl[ch][ks], bh + 2);
                }
            }

        // ---- in-register softmax ----
        float tm0 = -1e30f, tm1 = -1e30f;
#pragma unroll
        for (int ni = 0; ni < 8; ni++) {
            cs[ni][0] *= SCALE; cs[ni][1] *= SCALE;
            cs[ni][2] *= SCALE; cs[ni][3] *= SCALE;
            tm0 = fmaxf(tm0, fmaxf(cs[ni][0], cs[ni][1]));
            tm1 = fmaxf(tm1, fmaxf(cs[ni][2], cs[ni][3]));
        }
        tm0 = fmaxf(tm0, __shfl_xor_sync(0xffffffffu, tm0, 1));
        tm0 = fmaxf(tm0, __shfl_xor_sync(0xffffffffu, tm0, 2));
        tm1 = fmaxf(tm1, __shfl_xor_sync(0xffffffffu, tm1, 1));
        tm1 = fmaxf(tm1, __shfl_xor_sync(0xffffffffu, tm1, 2));
        float nm0 = fmaxf(m0, tm0), nm1 = fmaxf(m1, tm1);
        float al0 = __expf(m0 - nm0), al1 = __expf(m1 - nm1);
        m0 = nm0; m1 = nm1;

        float rs0 = 0.f, rs1 = 0.f;
#pragma unroll
        for (int ni = 0; ni < 8; ni++) {
            cs[ni][0] = __expf(cs[ni][0] - m0); rs0 += cs[ni][0];
            cs[ni][1] = __expf(cs[ni][1] - m0); rs0 += cs[ni][1];
            cs[ni][2] = __expf(cs[ni][2] - m1); rs1 += cs[ni][2];
            cs[ni][3] = __expf(cs[ni][3] - m1); rs1 += cs[ni][3];
        }
        rs0 += __shfl_xor_sync(0xffffffffu, rs0, 1);
        rs0 += __shfl_xor_sync(0xffffffffu, rs0, 2);
        rs1 += __shfl_xor_sync(0xffffffffu, rs1, 1);
        rs1 += __shfl_xor_sync(0xffffffffu, rs1, 2);
        l0 = l0 * al0 + rs0;
        l1 = l1 * al1 + rs1;

        // ---- P hi/lo A-fragments ----
        uint32_t phf[4][4], plf[4][4];
#pragma unroll
        for (int ck = 0; ck < 4; ck++) {
            hl2(cs[2 * ck][0], cs[2 * ck][1], phf[ck][0], plf[ck][0]);
            hl2(cs[2 * ck][2], cs[2 * ck][3], phf[ck][1], plf[ck][1]);
            hl2(cs[2 * ck + 1][0], cs[2 * ck + 1][1], phf[ck][2], plf[ck][2]);
            hl2(cs[2 * ck + 1][2], cs[2 * ck + 1][3], phf[ck][3], plf[ck][3]);
        }

        // ---- rescale O ----
#pragma unroll
        for (int ni = 0; ni < 16; ni++) {
            co[ni][0] *= al0; co[ni][1] *= al0;
            co[ni][2] *= al1; co[ni][3] *= al1;
        }

        // ---- O += Ph.Vh + Ph.Vl + Pl.Vh ----
#pragma unroll
        for (int ck = 0; ck < 4; ck++) {
#pragma unroll
            for (int ni2 = 0; ni2 < 8; ni2++) {
                uint32_t bh[4], bl[4];
                uint32_t ba = kvb + 32768 + (ck >> 1) * 8192 + (v4[ni2] ^ ((ck & 1) * 32));
                ldmx4(bh, ba);
                ldmx4(bl, ba + 16384);
                mma16816(co[2 * ni2], phf[ck], bh);
                mma16816(co[2 * ni2], phf[ck], bl);
                mma16816(co[2 * ni2], plf[ck], bh);
                mma16816(co[2 * ni2 + 1], phf[ck], bh + 2);
                mma16816(co[2 * ni2 + 1], phf[ck], bl + 2);
                mma16816(co[2 * ni2 + 1], plf[ck], bh + 2);
            }
        }
    }

    // ---- epilogue: write O split [hi|hi|lo] ----
    float il0 = 1.0f / l0, il1 = 1.0f / l1;
    int r0 = wm * 16 + g4, r1 = r0 + 8;
    __nv_bfloat16* O0 = O3 + ((size_t)(b * Sq + qb + r0)) * (3 * Eq) + h * Dq;
    __nv_bfloat16* O1 = O3 + ((size_t)(b * Sq + qb + r1)) * (3 * Eq) + h * Dq;
#pragma unroll
    for (int ni = 0; ni < 16; ni++) {
        int col = ni * 8 + tg * 2;
        uint32_t h0, lo0, h1, lo1;
        hl2(co[ni][0] * il0, co[ni][1] * il0, h0, lo0);
        hl2(co[ni][2] * il1, co[ni][3] * il1, h1, lo1);
        *(uint32_t*)(O0 + col) = h0;
        *(uint32_t*)(O0 + Eq + col) = h0;
        *(uint32_t*)(O0 + 2 * Eq + col) = lo0;
        *(uint32_t*)(O1 + col) = h1;
        *(uint32_t*)(O1 + Eq + col) = h1;
        *(uint32_t*)(O1 + 2 * Eq + col) = lo1;
    }
}

// ---------------- host launcher ----------------
extern "C" void kernel_launch(void* const* d_in, const int* in_sizes, int n_in,
                              void* d_out, int out_size) {
    const float* x  = (const float*)d_in[0];
    const float* rt = (const float*)d_in[1];
    const float* qw = (const float*)d_in[2];
    const float* kw = (const float*)d_in[3];
    const float* vw = (const float*)d_in[4];
    const float* ow = (const float*)d_in[5];
    const float* ob = (const float*)d_in[6];
    float* out = (float*)d_out;

    __nv_bfloat16 *xbf, *wbf, *rt3, *kw3, *vw3, *ow3, *ao3, *qh, *ql, *kh, *kl, *vth, *vtl;
    float *rows, *vb, *part, *scale;
    cudaGetSymbolAddress((void**)&xbf, g_xbf);
    cudaGetSymbolAddress((void**)&wbf, g_wbf);
    cudaGetSymbolAddress((void**)&rt3, g_rt3);
    cudaGetSymbolAddress((void**)&kw3, g_kw3);
    cudaGetSymbolAddress((void**)&vw3, g_vw3);
    cudaGetSymbolAddress((void**)&ow3, g_ow3);
    cudaGetSymbolAddress((void**)&ao3, g_ao3);
    cudaGetSymbolAddress((void**)&qh, g_qh);
    cudaGetSymbolAddress((void**)&ql, g_ql);
    cudaGetSymbolAddress((void**)&kh, g_kh);
    cudaGetSymbolAddress((void**)&kl, g_kl);
    cudaGetSymbolAddress((void**)&vth, g_vth);
    cudaGetSymbolAddress((void**)&vtl, g_vtl);
    cudaGetSymbolAddress((void**)&rows, g_rows);
    cudaGetSymbolAddress((void**)&vb, g_vb);
    cudaGetSymbolAddress((void**)&part, g_part);
    cudaGetSymbolAddress((void**)&scale, g_scale);

    cudaFuncSetAttribute(attn_mma3, cudaFuncAttributeMaxDynamicSharedMemorySize, SMEM_ATTN4);
    cudaFuncSetAttribute(hmma_gemm5, cudaFuncAttributeMaxDynamicSharedMemorySize, SMEM_GEMM5);

    // 1) weight scales
    reduce_abs_kernel<<<dim3(1024, 3), 256>>>(qw, kw, vw, part);
    finalize_scale_kernel<<<3, 256>>>(part, scale);
    // 2) merged weight prep (ternary q/k/v + splits k/v/o) + act quant + rt split
    prep_weights<<<dim3(2048, 4), 256>>>(qw, kw, vw, ow, wbf, kw3, vw3, ow3, scale);
    quant_act_bf16<<<(Bq * Sq) / 8, 256>>>(x, xbf, rows);
    split3a<<<(Bq * Rq * Eq) / 256, 256>>>(rt, rt3);
    // 3) QKV + reasoning projections in ONE launch (z = 0..4)
    size_t EE = (size_t)Eq * Eq;
    GArgs gQ = { xbf, wbf + 0 * EE, nullptr, rows, scale + 0, nullptr,
                 Eq, Eq, Sq, Sq, 0, 32, qh, ql };
    GArgs gK = { xbf, wbf + 1 * EE, nullptr, rows, scale + 1, nullptr,
                 Eq, Eq, Sq, Lq, 0, 32, kh, kl };
    GArgs gV = { xbf, wbf + 2 * EE, vb, rows, scale + 2, nullptr,
                 Eq, Eq, Sq, Lq, 0, 32, nullptr, nullptr };
    GArgs gRK = { rt3, kw3, nullptr, nullptr, nullptr, nullptr,
                  3 * Eq, Eq, Rq, Lq, Sq, 2, kh, kl };
    GArgs gRV = { rt3, vw3, vb, nullptr, nullptr, nullptr,
                  3 * Eq, Eq, Rq, Lq, Sq, 2, nullptr, nullptr };
    hmma_gemm5<<<dim3(16, 32, 5), 256, SMEM_GEMM5>>>(gQ, gK, gV, gRK, gRV);
    // 4) transpose+split V
    transpose_v<<<dim3(Lq / 32, Eq / 32, Bq), 256>>>(vb, vth, vtl);
    // 5) attention (3-stage KV pipeline, Q in registers) -> writes [hi|hi|lo]
    attn_mma3<<<dim3(Sq / 128, Hq, Bq), 256, SMEM_ATTN4>>>(qh, ql, kh, kl, vth, vtl, ao3);
    // 6) output projection + bias
    GArgs gO = { ao3, ow3, out, nullptr, nullptr, ob,
                 3 * Eq, Eq, Bq * Sq, Bq * Sq, 0, 32, nullptr, nullptr };
    hmma_gemm5<<<dim3(16, 32, 1), 256, SMEM_GEMM5>>>(gO, gO, gO, gO, gO);
}